// round 7
// baseline (speedup 1.0000x reference)
#include <cuda_runtime.h>
#include <cuda_bf16.h>
#include <math.h>
#include <stdint.h>

// Problem constants
#define B_    64
#define S_    200
#define H_    16
#define DK_   64
#define DM_   1024
#define MROWS (B_ * S_)          // 12800
#define BH_   (B_ * H_)          // 1024
#define OUT_N  ((size_t)MROWS * DM_)       // 13107200
#define ATTN_N ((size_t)BH_ * S_ * S_)     // 40960000
#define XN    (MROWS * DM_)                // 13107200
#define WN    (DM_ * DM_)                  // 1048576

// Scratch (allocation-free rule: __device__ globals)
__device__ __nv_bfloat16 g_xhi[XN];
__device__ __nv_bfloat16 g_xlo[XN];
__device__ __nv_bfloat16 g_whi[4][WN];
__device__ __nv_bfloat16 g_wlo[4][WN];
__device__ __nv_bfloat16 g_Qhi[BH_ * S_ * DK_];
__device__ __nv_bfloat16 g_Qlo[BH_ * S_ * DK_];
__device__ __nv_bfloat16 g_Khi[BH_ * S_ * DK_];
__device__ __nv_bfloat16 g_Klo[BH_ * S_ * DK_];
__device__ __nv_bfloat16 g_Vhi[BH_ * S_ * DK_];
__device__ __nv_bfloat16 g_Vlo[BH_ * S_ * DK_];
__device__ __nv_bfloat16 g_ctxhi[MROWS * DM_];
__device__ __nv_bfloat16 g_ctxlo[MROWS * DM_];
__device__ float g_attn_fb[BH_ * S_ * S_];
__device__ float g_out_fb[MROWS * DM_];

// ===========================================================================
// Helpers
// ===========================================================================
__device__ __forceinline__ uint32_t smem_to_u32(const void* p) {
    uint32_t a;
    asm("{ .reg .u64 t; cvta.to.shared.u64 t, %1; cvt.u32.u64 %0, t; }"
        : "=r"(a) : "l"(p));
    return a;
}

__device__ __forceinline__ void ldsm_x4(uint32_t& r0, uint32_t& r1,
                                        uint32_t& r2, uint32_t& r3, uint32_t addr) {
    asm volatile("ldmatrix.sync.aligned.m8n8.x4.shared.b16 {%0,%1,%2,%3}, [%4];"
                 : "=r"(r0), "=r"(r1), "=r"(r2), "=r"(r3) : "r"(addr));
}
__device__ __forceinline__ void ldsm_x4_t(uint32_t& r0, uint32_t& r1,
                                          uint32_t& r2, uint32_t& r3, uint32_t addr) {
    asm volatile("ldmatrix.sync.aligned.m8n8.x4.trans.shared.b16 {%0,%1,%2,%3}, [%4];"
                 : "=r"(r0), "=r"(r1), "=r"(r2), "=r"(r3) : "r"(addr));
}

__device__ __forceinline__ void mma_bf16(float* d, const uint32_t* a, const uint32_t* b) {
    asm volatile(
        "mma.sync.aligned.m16n8k16.row.col.f32.bf16.bf16.f32 "
        "{%0,%1,%2,%3}, {%4,%5,%6,%7}, {%8,%9}, {%0,%1,%2,%3};"
        : "+f"(d[0]), "+f"(d[1]), "+f"(d[2]), "+f"(d[3])
        : "r"(a[0]), "r"(a[1]), "r"(a[2]), "r"(a[3]), "r"(b[0]), "r"(b[1]));
}

#define STS128(addr, r0, r1, r2, r3) \
    asm volatile("st.shared.v4.b32 [%0], {%1,%2,%3,%4};" \
        :: "r"(addr), "r"(r0), "r"(r1), "r"(r2), "r"(r3) : "memory")

#define CP_ASYNC16(sm, gp) \
    asm volatile("{ .reg .u64 g; cvta.to.global.u64 g, %1; " \
                 "cp.async.cg.shared.global [%0], [g], 16; }" \
                 :: "r"(sm), "l"(gp) : "memory")
#define CP_COMMIT() asm volatile("cp.async.commit_group;" ::: "memory")
#define CP_WAIT0()  asm volatile("cp.async.wait_group 0;" ::: "memory")

// hi/lo bf16 split of a float pair, packed as 2x uint32 (bf16x2)
__device__ __forceinline__ void split2(float x, float y, uint32_t& hi, uint32_t& lo) {
    __nv_bfloat162 h = __floats2bfloat162_rn(x, y);
    float rx = x - __bfloat162float(h.x);
    float ry = y - __bfloat162float(h.y);
    __nv_bfloat162 l = __floats2bfloat162_rn(rx, ry);
    hi = *(uint32_t*)&h;
    lo = *(uint32_t*)&l;
}

// 64B-row swizzle (gemm): 4 chunks of 16B; chunk ^= (row>>1)&3
__device__ __forceinline__ uint32_t swz(int row, int chunk) {
    return (uint32_t)(row * 64 + ((chunk ^ ((row >> 1) & 3)) << 4));
}
// 128B-row swizzle (attention): 8 chunks of 16B; chunk ^= row&7
__device__ __forceinline__ uint32_t swz128(int row, int chunk) {
    return (uint32_t)(row * 128 + ((chunk ^ (row & 7)) << 4));
}

// ===========================================================================
// Combined split kernel: x + 4 weight matrices in one launch
// ===========================================================================
__global__ void __launch_bounds__(256) split_all(
    const float* __restrict__ x,
    const float* __restrict__ wq, const float* __restrict__ wk,
    const float* __restrict__ wv, const float* __restrict__ wo)
{
    size_t i = ((size_t)blockIdx.x * 256 + threadIdx.x) * 8;
    const float* src;
    __nv_bfloat16 *hi, *lo;
    size_t off;
    if (i < (size_t)XN) {
        src = x; hi = g_xhi; lo = g_xlo; off = i;
    } else {
        size_t j = i - XN;
        int wsel = (int)(j >> 20);            // WN = 2^20
        off = j & (WN - 1);
        const float* ws[4] = {wq, wk, wv, wo};
        src = ws[wsel]; hi = g_whi[wsel]; lo = g_wlo[wsel];
    }
    float4 v0 = *(const float4*)(src + off);
    float4 v1 = *(const float4*)(src + off + 4);
    uint32_t h[4], l[4];
    split2(v0.x, v0.y, h[0], l[0]); split2(v0.z, v0.w, h[1], l[1]);
    split2(v1.x, v1.y, h[2], l[2]); split2(v1.z, v1.w, h[3], l[3]);
    *(uint4*)(hi + off) = make_uint4(h[0], h[1], h[2], h[3]);
    *(uint4*)(lo + off) = make_uint4(l[0], l[1], l[2], l[3]);
}

// ===========================================================================
// bf16 hi/lo GEMM via mma.sync on pre-split inputs.
// C = A[M,1024] @ W^T[1024,1024] + bias. CTA 128x256, 8 warps (2m x 4n of
// 64x64), K-chunk 32, cp.async double buffer.
// OUT_MODE 0: bf16 hi/lo scatter to [b,h,s,dk]. OUT_MODE 1: fp32 row-major.
// ===========================================================================
#define ST_AHI(s)  ((uint32_t)(s) * 49152u + 0u)
#define ST_ALO(s)  ((uint32_t)(s) * 49152u + 8192u)
#define ST_BHI(s)  ((uint32_t)(s) * 49152u + 16384u)
#define ST_BLO(s)  ((uint32_t)(s) * 49152u + 32768u)
#define GEMM_SMEM  98304

template <int OUT_MODE>
__global__ void __launch_bounds__(256, 1) gemm_mma(
    const __nv_bfloat16* __restrict__ Ahi, const __nv_bfloat16* __restrict__ Alo,
    const __nv_bfloat16* __restrict__ Whi, const __nv_bfloat16* __restrict__ Wlo,
    const float* __restrict__ bias,
    __nv_bfloat16* __restrict__ Chi, __nv_bfloat16* __restrict__ Clo,
    float* __restrict__ Cf)
{
    extern __shared__ char smem[];
    const uint32_t sb = smem_to_u32(smem);
    const int tid  = threadIdx.x;
    const int lane = tid & 31;
    const int wid  = tid >> 5;
    const int wm   = wid >> 2;     // 0..1  (64 m-rows each)
    const int wn   = wid & 3;      // 0..3  (64 n-cols each)
    const int m0   = blockIdx.y * 128;
    const int n0   = blockIdx.x * 256;

    float acc[4][8][4];
#pragma unroll
    for (int i = 0; i < 4; i++)
#pragma unroll
        for (int j = 0; j < 8; j++)
#pragma unroll
            for (int r = 0; r < 4; r++) acc[i][j][r] = 0.f;

    // A: 512 chunks (128 rows x 4); B: 1024 chunks (256 rows x 4)
    const int ar0 = tid >> 1;                 // need 2 chunks/thread for A
    const int ac0 = (tid & 1) << 1;           // chunks {0,1} or {2,3}
    const uint32_t aw0 = swz(ar0, ac0);
    const uint32_t aw1 = swz(ar0, ac0 + 1);
    const int br0 = tid >> 1;                 // B chunk pairs: 4 per thread
    const uint32_t bw0 = swz(br0, ac0);
    const uint32_t bw1 = swz(br0, ac0 + 1);
    const int br1 = br0 + 128;
    const uint32_t bw2 = swz(br1, ac0);
    const uint32_t bw3 = swz(br1, ac0 + 1);

#define ISSUE_STAGE(st, kt_) do { \
    size_t ka = (size_t)(kt_) * 32 + ac0 * 8; \
    const __nv_bfloat16* pa = Ahi + (size_t)(m0 + ar0) * DM_ + ka; \
    CP_ASYNC16(sb + ST_AHI(st) + aw0, pa); \
    CP_ASYNC16(sb + ST_AHI(st) + aw1, pa + 8); \
    pa = Alo + (size_t)(m0 + ar0) * DM_ + ka; \
    CP_ASYNC16(sb + ST_ALO(st) + aw0, pa); \
    CP_ASYNC16(sb + ST_ALO(st) + aw1, pa + 8); \
    pa = Whi + (size_t)(n0 + br0) * DM_ + ka; \
    CP_ASYNC16(sb + ST_BHI(st) + bw0, pa); \
    CP_ASYNC16(sb + ST_BHI(st) + bw1, pa + 8); \
    pa = Whi + (size_t)(n0 + br1) * DM_ + ka; \
    CP_ASYNC16(sb + ST_BHI(st) + bw2, pa); \
    CP_ASYNC16(sb + ST_BHI(st) + bw3, pa + 8); \
    pa = Wlo + (size_t)(n0 + br0) * DM_ + ka; \
    CP_ASYNC16(sb + ST_BLO(st) + bw0, pa); \
    CP_ASYNC16(sb + ST_BLO(st) + bw1, pa + 8); \
    pa = Wlo + (size_t)(n0 + br1) * DM_ + ka; \
    CP_ASYNC16(sb + ST_BLO(st) + bw2, pa); \
    CP_ASYNC16(sb + ST_BLO(st) + bw3, pa + 8); \
} while (0)

    ISSUE_STAGE(0, 0);
    CP_COMMIT();
    CP_WAIT0();
    __syncthreads();

    const int a_row_in = lane & 15;
    const int a_kh     = lane >> 4;
    const int b_col_in = (lane & 7) + ((lane >> 4) << 3);
    const int b_kh     = (lane >> 3) & 1;

    for (int kt = 0; kt < 32; kt++) {
        const int cur = kt & 1;

        if (kt < 31) {
            ISSUE_STAGE((kt + 1) & 1, kt + 1);
            CP_COMMIT();
        }

        const uint32_t ahiB = sb + ST_AHI(cur), aloB = sb + ST_ALO(cur);
        const uint32_t bhiB = sb + ST_BHI(cur), bloB = sb + ST_BLO(cur);

#pragma unroll
        for (int ks = 0; ks < 2; ks++) {
            uint32_t ahi[4][4], alo[4][4];
#pragma unroll
            for (int mf = 0; mf < 4; mf++) {
                int row = wm * 64 + mf * 16 + a_row_in;
                int ch  = ks * 2 + a_kh;
                uint32_t so = swz(row, ch);
                ldsm_x4(ahi[mf][0], ahi[mf][1], ahi[mf][2], ahi[mf][3], ahiB + so);
                ldsm_x4(alo[mf][0], alo[mf][1], alo[mf][2], alo[mf][3], aloB + so);
            }
            uint32_t bhi[8][2], blo[8][2];
#pragma unroll
            for (int bi = 0; bi < 4; bi++) {
                int col = wn * 64 + bi * 16 + b_col_in;
                int ch  = ks * 2 + b_kh;
                uint32_t so = swz(col, ch);
                uint32_t r0, r1, r2, r3;
                ldsm_x4(r0, r1, r2, r3, bhiB + so);
                bhi[bi * 2][0] = r0; bhi[bi * 2][1] = r1;
                bhi[bi * 2 + 1][0] = r2; bhi[bi * 2 + 1][1] = r3;
                ldsm_x4(r0, r1, r2, r3, bloB + so);
                blo[bi * 2][0] = r0; blo[bi * 2][1] = r1;
                blo[bi * 2 + 1][0] = r2; blo[bi * 2 + 1][1] = r3;
            }
#pragma unroll
            for (int mf = 0; mf < 4; mf++)
#pragma unroll
                for (int nf = 0; nf < 8; nf++) {
                    mma_bf16(acc[mf][nf], ahi[mf], bhi[nf]);
                    mma_bf16(acc[mf][nf], ahi[mf], blo[nf]);
                    mma_bf16(acc[mf][nf], alo[mf], bhi[nf]);
                }
        }
        if (kt < 31) {
            CP_WAIT0();
            __syncthreads();
        }
    }
#undef ISSUE_STAGE

    const int g  = lane >> 2;
    const int c2 = (lane & 3) * 2;
#pragma unroll
    for (int nf = 0; nf < 8; nf++) {
        const int n = n0 + wn * 64 + nf * 8 + c2;
        const float b0 = bias[n], b1 = bias[n + 1];
#pragma unroll
        for (int mf = 0; mf < 4; mf++) {
            const int m = m0 + wm * 64 + mf * 16 + g;
            if (OUT_MODE == 0) {
                int hh = n >> 6;
                int dk = n & 63;
                uint32_t hi0, lo0, hi1, lo1;
                split2(acc[mf][nf][0] + b0, acc[mf][nf][1] + b1, hi0, lo0);
                split2(acc[mf][nf][2] + b0, acc[mf][nf][3] + b1, hi1, lo1);
                int bb = m / S_;
                int ss = m - bb * S_;
                size_t off0 = (((size_t)bb * H_ + hh) * S_ + ss) * DK_ + dk;
                *(uint32_t*)(Chi + off0) = hi0;
                *(uint32_t*)(Clo + off0) = lo0;
                int m2 = m + 8;
                int bb2 = m2 / S_;
                int ss2 = m2 - bb2 * S_;
                size_t off1 = (((size_t)bb2 * H_ + hh) * S_ + ss2) * DK_ + dk;
                *(uint32_t*)(Chi + off1) = hi1;
                *(uint32_t*)(Clo + off1) = lo1;
            } else {
                float2 v0 = make_float2(acc[mf][nf][0] + b0, acc[mf][nf][1] + b1);
                float2 v1 = make_float2(acc[mf][nf][2] + b0, acc[mf][nf][3] + b1);
                *(float2*)(Cf + (size_t)m * DM_ + n)       = v0;
                *(float2*)(Cf + (size_t)(m + 8) * DM_ + n) = v1;
            }
        }
    }
}

// ===========================================================================
// Fused attention (R5 config): CTA = (64 q-rows, bh). 128 threads, 2 CTAs/SM.
// ===========================================================================
#define FK_HI   0u
#define FK_LO   26624u
#define FV_HI   53248u
#define FV_LO   79872u
#define FA_SMEM 106496

__global__ void __launch_bounds__(128, 2) attn_fused(
    const int* __restrict__ mask, float* __restrict__ attn)
{
    extern __shared__ char smem[];
    const uint32_t sb = smem_to_u32(smem);
    const int tid  = threadIdx.x;
    const int lane = tid & 31;
    const int w    = tid >> 5;
    const int qt   = blockIdx.x;          // 0..3
    const int bh   = blockIdx.y;
    const int b    = bh >> 4;

    const __nv_bfloat16* Khi = g_Khi + (size_t)bh * S_ * DK_;
    const __nv_bfloat16* Klo = g_Klo + (size_t)bh * S_ * DK_;
    const __nv_bfloat16* Vhi = g_Vhi + (size_t)bh * S_ * DK_;
    const __nv_bfloat16* Vlo = g_Vlo + (size_t)bh * S_ * DK_;
    const __nv_bfloat16* Qhi = g_Qhi + (size_t)bh * S_ * DK_;
    const __nv_bfloat16* Qlo = g_Qlo + (size_t)bh * S_ * DK_;

    // ---- cp.async K/V hi/lo (200 rows x 8 chunks of 16B each) ----
    for (int c = tid; c < 1600; c += 128) {
        int r = c >> 3, cc = c & 7;
        uint32_t so = swz128(r, cc);
        size_t go = (size_t)r * DK_ + cc * 8;
        CP_ASYNC16(sb + FK_HI + so, Khi + go);
        CP_ASYNC16(sb + FK_LO + so, Klo + go);
        CP_ASYNC16(sb + FV_HI + so, Vhi + go);
        CP_ASYNC16(sb + FV_LO + so, Vlo + go);
    }
    CP_COMMIT();
    // zero-pad rows 200..207
    if (tid < 64) {
        int r = 200 + (tid >> 3), cc = tid & 7;
        uint32_t so = swz128(r, cc);
        STS128(sb + FK_HI + so, 0u, 0u, 0u, 0u);
        STS128(sb + FK_LO + so, 0u, 0u, 0u, 0u);
        STS128(sb + FV_HI + so, 0u, 0u, 0u, 0u);
        STS128(sb + FV_LO + so, 0u, 0u, 0u, 0u);
    }
    CP_WAIT0();
    __syncthreads();

    // ---- Scores ----
    float acc[25][4];
#pragma unroll
    for (int f = 0; f < 25; f++)
#pragma unroll
        for (int r = 0; r < 4; r++) acc[f][r] = 0.f;

    const int g  = lane >> 2;
    const int c2 = (lane & 3) * 2;
    const int b_col_in = (lane & 7) + ((lane >> 4) << 3);
    const int b_kh     = (lane >> 3) & 1;

    const int qr0 = qt * 64 + w * 16 + g;
    const int qr1 = qr0 + 8;
    const size_t qo0 = (size_t)min(qr0, S_ - 1) * DK_;
    const size_t qo1 = (size_t)min(qr1, S_ - 1) * DK_;

    for (int kb = 0; kb < 4; kb++) {
        const int col = kb * 16 + c2;
        uint32_t ahi[4], alo[4];
        ahi[0] = *(const uint32_t*)(Qhi + qo0 + col);
        ahi[1] = *(const uint32_t*)(Qhi + qo1 + col);
        ahi[2] = *(const uint32_t*)(Qhi + qo0 + col + 8);
        ahi[3] = *(const uint32_t*)(Qhi + qo1 + col + 8);
        alo[0] = *(const uint32_t*)(Qlo + qo0 + col);
        alo[1] = *(const uint32_t*)(Qlo + qo1 + col);
        alo[2] = *(const uint32_t*)(Qlo + qo0 + col + 8);
        alo[3] = *(const uint32_t*)(Qlo + qo1 + col + 8);
#pragma unroll
        for (int nb = 0; nb < 13; nb++) {
            int row = nb * 16 + b_col_in;
            int ch  = kb * 2 + b_kh;
            uint32_t so = swz128(row, ch);
            uint32_t h0, h1, h2, h3, l0, l1, l2, l3;
            ldsm_x4(h0, h1, h2, h3, sb + FK_HI + so);
            ldsm_x4(l0, l1, l2, l3, sb + FK_LO + so);
            uint32_t bh0[2] = {h0, h1}, bl0[2] = {l0, l1};
            mma_bf16(acc[nb * 2], ahi, bh0);
            mma_bf16(acc[nb * 2], ahi, bl0);
            mma_bf16(acc[nb * 2], alo, bh0);
            if (nb < 12) {
                uint32_t bh1[2] = {h2, h3}, bl1[2] = {l2, l3};
                mma_bf16(acc[nb * 2 + 1], ahi, bh1);
                mma_bf16(acc[nb * 2 + 1], ahi, bl1);
                mma_bf16(acc[nb * 2 + 1], alo, bh1);
            }
        }
    }

    // ---- scale + temporal bias + mask + softmax in registers ----
    const int gi0 = qr0;
    const int gi1 = qr1;
    const bool v0ok = (gi0 < S_);
    const bool v1ok = (gi1 < S_);
    const int* mrow0 = mask + (size_t)b * S_ * S_ + (size_t)gi0 * S_;
    const int* mrow1 = mask + (size_t)b * S_ * S_ + (size_t)gi1 * S_;
    const float BC = -0.1f / 200.0f;

    float mx0 = -1e30f, mx1 = -1e30f;
#pragma unroll
    for (int f = 0; f < 25; f++) {
        int gj = f * 8 + c2;
        int2 m0v = v0ok ? *(const int2*)(mrow0 + gj) : make_int2(1, 1);
        int2 m1v = v1ok ? *(const int2*)(mrow1 + gj) : make_int2(1, 1);
        float t00 = BC * fabsf((float)(gi0 - gj));
        float t01 = BC * fabsf((float)(gi0 - gj - 1));
        float t10 = BC * fabsf((float)(gi1 - gj));
        float t11 = BC * fabsf((float)(gi1 - gj - 1));
        acc[f][0] = (m0v.x == 0) ? -1e9f : fmaf(acc[f][0], 0.125f, t00);
        acc[f][1] = (m0v.y == 0) ? -1e9f : fmaf(acc[f][1], 0.125f, t01);
        acc[f][2] = (m1v.x == 0) ? -1e9f : fmaf(acc[f][2], 0.125f, t10);
        acc[f][3] = (m1v.y == 0) ? -1e9f : fmaf(acc[f][3], 0.125f, t11);
        mx0 = fmaxf(mx0, fmaxf(acc[f][0], acc[f][1]));
        mx1 = fmaxf(mx1, fmaxf(acc[f][2], acc[f][3]));
    }
    mx0 = fmaxf(mx0, __shfl_xor_sync(0xffffffffu, mx0, 1));
    mx0 = fmaxf(mx0, __shfl_xor_sync(0xffffffffu, mx0, 2));
    mx1 = fmaxf(mx1, __shfl_xor_sync(0xffffffffu, mx1, 1));
    mx1 = fmaxf(mx1, __shfl_xor_sync(0xffffffffu, mx1, 2));

    float s0 = 0.f, s1 = 0.f;
#pragma unroll
    for (int f = 0; f < 25; f++) {
        acc[f][0] = expf(acc[f][0] - mx0);
        acc[f][1] = expf(acc[f][1] - mx0);
        acc[f][2] = expf(acc[f][2] - mx1);
        acc[f][3] = expf(acc[f][3] - mx1);
        s0 += acc[f][0] + acc[f][1];
        s1 += acc[f][2] + acc[f][3];
    }
    s0 += __shfl_xor_sync(0xffffffffu, s0, 1);
    s0 += __shfl_xor_sync(0xffffffffu, s0, 2);
    s1 += __shfl_xor_sync(0xffffffffu, s1, 1);
    s1 += __shfl_xor_sync(0xffffffffu, s1, 2);
    const float i0 = 1.f / s0;
    const float i1 = 1.f / s1;

    float* arow0 = attn + (size_t)bh * S_ * S_ + (size_t)gi0 * S_;
    float* arow1 = attn + (size_t)bh * S_ * S_ + (size_t)gi1 * S_;
#pragma unroll
    for (int f = 0; f < 25; f++) {
        int gj = f * 8 + c2;
        acc[f][0] *= i0; acc[f][1] *= i0;
        acc[f][2] *= i1; acc[f][3] *= i1;
        if (v0ok) *(float2*)(arow0 + gj) = make_float2(acc[f][0], acc[f][1]);
        if (v1ok) *(float2*)(arow1 + gj) = make_float2(acc[f][2], acc[f][3]);
    }

    // ---- ctx = attn @ V ----
    float cacc[8][4];
#pragma unroll
    for (int nf = 0; nf < 8; nf++)
#pragma unroll
        for (int r = 0; r < 4; r++) cacc[nf][r] = 0.f;

#pragma unroll
    for (int kf = 0; kf < 13; kf++) {
        uint32_t ahi[4], alo[4];
        split2(acc[2 * kf][0], acc[2 * kf][1], ahi[0], alo[0]);
        split2(acc[2 * kf][2], acc[2 * kf][3], ahi[1], alo[1]);
        if (kf < 12) {
            split2(acc[2 * kf + 1][0], acc[2 * kf + 1][1], ahi[2], alo[2]);
            split2(acc[2 * kf + 1][2], acc[2 * kf + 1][3], ahi[3], alo[3]);
        } else {
            ahi[2] = alo[2] = ahi[3] = alo[3] = 0u;
        }
#pragma unroll
        for (int nb = 0; nb < 4; nb++) {
            int row = kf * 16 + (lane & 15);
            int ch  = nb * 2 + (lane >> 4);
            uint32_t so = swz128(row, ch);
            uint32_t h0, h1, h2, h3, l0, l1, l2, l3;
            ldsm_x4_t(h0, h1, h2, h3, sb + FV_HI + so);
            ldsm_x4_t(l0, l1, l2, l3, sb + FV_LO + so);
            uint32_t bh0[2] = {h0, h1}, bl0[2] = {l0, l1};
            uint32_t bh1[2] = {h2, h3}, bl1[2] = {l2, l3};
            mma_bf16(cacc[nb * 2], ahi, bh0);
            mma_bf16(cacc[nb * 2], ahi, bl0);
            mma_bf16(cacc[nb * 2], alo, bh0);
            mma_bf16(cacc[nb * 2 + 1], ahi, bh1);
            mma_bf16(cacc[nb * 2 + 1], ahi, bl1);
            mma_bf16(cacc[nb * 2 + 1], alo, bh1);
        }
    }

    const int h = bh & 15;
    __nv_bfloat16* chi0 = g_ctxhi + ((size_t)b * S_ + gi0) * DM_ + h * DK_;
    __nv_bfloat16* clo0 = g_ctxlo + ((size_t)b * S_ + gi0) * DM_ + h * DK_;
    __nv_bfloat16* chi1 = g_ctxhi + ((size_t)b * S_ + gi1) * DM_ + h * DK_;
    __nv_bfloat16* clo1 = g_ctxlo + ((size_t)b * S_ + gi1) * DM_ + h * DK_;
#pragma unroll
    for (int nf = 0; nf < 8; nf++) {
        int n = nf * 8 + c2;
        uint32_t hi0, lo0, hi1, lo1;
        split2(cacc[nf][0], cacc[nf][1], hi0, lo0);
        split2(cacc[nf][2], cacc[nf][3], hi1, lo1);
        if (v0ok) { *(uint32_t*)(chi0 + n) = hi0; *(uint32_t*)(clo0 + n) = lo0; }
        if (v1ok) { *(uint32_t*)(chi1 + n) = hi1; *(uint32_t*)(clo1 + n) = lo1; }
    }
}

// ---------------------------------------------------------------------------
extern "C" void kernel_launch(void* const* d_in, const int* in_sizes, int n_in,
                              void* d_out, int out_size)
{
    const float* x    = (const float*)d_in[0];
    const int*   mask = (const int*)  d_in[1];
    const float* wq   = (const float*)d_in[2];
    const float* bq   = (const float*)d_in[3];
    const float* wk   = (const float*)d_in[4];
    const float* bk   = (const float*)d_in[5];
    const float* wv   = (const float*)d_in[6];
    const float* bv   = (const float*)d_in[7];
    const float* wo   = (const float*)d_in[8];
    const float* bo   = (const float*)d_in[9];

    void *pxh, *pxl, *pwh, *pwl;
    void *pQh, *pQl, *pKh, *pKl, *pVh, *pVl, *pch, *pcl, *pAttnFb, *pOutFb;
    cudaGetSymbolAddress(&pxh, g_xhi);  cudaGetSymbolAddress(&pxl, g_xlo);
    cudaGetSymbolAddress(&pwh, g_whi);  cudaGetSymbolAddress(&pwl, g_wlo);
    cudaGetSymbolAddress(&pQh, g_Qhi);  cudaGetSymbolAddress(&pQl, g_Qlo);
    cudaGetSymbolAddress(&pKh, g_Khi);  cudaGetSymbolAddress(&pKl, g_Klo);
    cudaGetSymbolAddress(&pVh, g_Vhi);  cudaGetSymbolAddress(&pVl, g_Vlo);
    cudaGetSymbolAddress(&pch, g_ctxhi); cudaGetSymbolAddress(&pcl, g_ctxlo);
    cudaGetSymbolAddress(&pAttnFb, g_attn_fb);
    cudaGetSymbolAddress(&pOutFb, g_out_fb);

    __nv_bfloat16* wh = (__nv_bfloat16*)pwh;
    __nv_bfloat16* wl = (__nv_bfloat16*)pwl;

    float* outp;
    float* attnp;
    size_t osz = (size_t)out_size;
    if (osz >= OUT_N + ATTN_N) {
        outp  = (float*)d_out;
        attnp = (float*)d_out + OUT_N;
    } else if (osz == ATTN_N) {
        attnp = (float*)d_out;
        outp  = (float*)pOutFb;
    } else {
        outp  = (float*)d_out;
        attnp = (float*)pAttnFb;
    }

    cudaFuncSetAttribute(gemm_mma<0>, cudaFuncAttributeMaxDynamicSharedMemorySize, GEMM_SMEM);
    cudaFuncSetAttribute(gemm_mma<1>, cudaFuncAttributeMaxDynamicSharedMemorySize, GEMM_SMEM);
    cudaFuncSetAttribute(attn_fused, cudaFuncAttributeMaxDynamicSharedMemorySize, FA_SMEM);

    // One combined split launch: x + 4 weights
    const size_t total = (size_t)XN + 4 * (size_t)WN;   // 17301504
    split_all<<<(unsigned)(total / 2048), 256>>>(x, wq, wk, wv, wo);

    dim3 gProj(DM_ / 256, MROWS / 128);   // (4, 100)
    gemm_mma<0><<<gProj, 256, GEMM_SMEM>>>((__nv_bfloat16*)pxh, (__nv_bfloat16*)pxl,
        wh + 0 * (size_t)WN, wl + 0 * (size_t)WN, bq,
        (__nv_bfloat16*)pQh, (__nv_bfloat16*)pQl, nullptr);
    gemm_mma<0><<<gProj, 256, GEMM_SMEM>>>((__nv_bfloat16*)pxh, (__nv_bfloat16*)pxl,
        wh + 1 * (size_t)WN, wl + 1 * (size_t)WN, bk,
        (__nv_bfloat16*)pKh, (__nv_bfloat16*)pKl, nullptr);
    gemm_mma<0><<<gProj, 256, GEMM_SMEM>>>((__nv_bfloat16*)pxh, (__nv_bfloat16*)pxl,
        wh + 2 * (size_t)WN, wl + 2 * (size_t)WN, bv,
        (__nv_bfloat16*)pVh, (__nv_bfloat16*)pVl, nullptr);

    dim3 gFA(4, BH_);
    attn_fused<<<gFA, 128, FA_SMEM>>>(mask, attnp);

    gemm_mma<1><<<gProj, 256, GEMM_SMEM>>>((__nv_bfloat16*)pch, (__nv_bfloat16*)pcl,
        wh + 3 * (size_t)WN, wl + 3 * (size_t)WN, bo, nullptr, nullptr, outp);
}

// round 8
// speedup vs baseline: 1.0004x; 1.0004x over previous
#include <cuda_runtime.h>
#include <cuda_bf16.h>
#include <math.h>
#include <stdint.h>

// Problem constants
#define B_    64
#define S_    200
#define H_    16
#define DK_   64
#define DM_   1024
#define MROWS (B_ * S_)          // 12800
#define BH_   (B_ * H_)          // 1024
#define OUT_N  ((size_t)MROWS * DM_)       // 13107200
#define ATTN_N ((size_t)BH_ * S_ * S_)     // 40960000
#define XN    (MROWS * DM_)                // 13107200
#define WN    (DM_ * DM_)                  // 1048576

// Scratch (allocation-free rule: __device__ globals)
__device__ __nv_bfloat16 g_xhi[XN];
__device__ __nv_bfloat16 g_xlo[XN];
__device__ __nv_bfloat16 g_whi[4][WN];
__device__ __nv_bfloat16 g_wlo[4][WN];
__device__ __nv_bfloat16 g_Qhi[BH_ * S_ * DK_];
__device__ __nv_bfloat16 g_Qlo[BH_ * S_ * DK_];
__device__ __nv_bfloat16 g_Khi[BH_ * S_ * DK_];
__device__ __nv_bfloat16 g_Klo[BH_ * S_ * DK_];
__device__ __nv_bfloat16 g_Vhi[BH_ * S_ * DK_];
__device__ __nv_bfloat16 g_Vlo[BH_ * S_ * DK_];
__device__ __nv_bfloat16 g_ctxhi[MROWS * DM_];
__device__ __nv_bfloat16 g_ctxlo[MROWS * DM_];
__device__ float g_attn_fb[BH_ * S_ * S_];
__device__ float g_out_fb[MROWS * DM_];

// ===========================================================================
// Helpers
// ===========================================================================
__device__ __forceinline__ uint32_t smem_to_u32(const void* p) {
    uint32_t a;
    asm("{ .reg .u64 t; cvta.to.shared.u64 t, %1; cvt.u32.u64 %0, t; }"
        : "=r"(a) : "l"(p));
    return a;
}

__device__ __forceinline__ void ldsm_x4(uint32_t& r0, uint32_t& r1,
                                        uint32_t& r2, uint32_t& r3, uint32_t addr) {
    asm volatile("ldmatrix.sync.aligned.m8n8.x4.shared.b16 {%0,%1,%2,%3}, [%4];"
                 : "=r"(r0), "=r"(r1), "=r"(r2), "=r"(r3) : "r"(addr));
}
__device__ __forceinline__ void ldsm_x4_t(uint32_t& r0, uint32_t& r1,
                                          uint32_t& r2, uint32_t& r3, uint32_t addr) {
    asm volatile("ldmatrix.sync.aligned.m8n8.x4.trans.shared.b16 {%0,%1,%2,%3}, [%4];"
                 : "=r"(r0), "=r"(r1), "=r"(r2), "=r"(r3) : "r"(addr));
}

__device__ __forceinline__ void mma_bf16(float* d, const uint32_t* a, const uint32_t* b) {
    asm volatile(
        "mma.sync.aligned.m16n8k16.row.col.f32.bf16.bf16.f32 "
        "{%0,%1,%2,%3}, {%4,%5,%6,%7}, {%8,%9}, {%0,%1,%2,%3};"
        : "+f"(d[0]), "+f"(d[1]), "+f"(d[2]), "+f"(d[3])
        : "r"(a[0]), "r"(a[1]), "r"(a[2]), "r"(a[3]), "r"(b[0]), "r"(b[1]));
}

#define STS128(addr, r0, r1, r2, r3) \
    asm volatile("st.shared.v4.b32 [%0], {%1,%2,%3,%4};" \
        :: "r"(addr), "r"(r0), "r"(r1), "r"(r2), "r"(r3) : "memory")

#define CP_ASYNC16(sm, gp) \
    asm volatile("{ .reg .u64 g; cvta.to.global.u64 g, %1; " \
                 "cp.async.cg.shared.global [%0], [g], 16; }" \
                 :: "r"(sm), "l"(gp) : "memory")
#define CP_COMMIT() asm volatile("cp.async.commit_group;" ::: "memory")
#define CP_WAIT0()  asm volatile("cp.async.wait_group 0;" ::: "memory")
#define CP_WAIT1()  asm volatile("cp.async.wait_group 1;" ::: "memory")
#define CP_WAIT2()  asm volatile("cp.async.wait_group 2;" ::: "memory")

// hi/lo bf16 split of a float pair, packed as 2x uint32 (bf16x2)
__device__ __forceinline__ void split2(float x, float y, uint32_t& hi, uint32_t& lo) {
    __nv_bfloat162 h = __floats2bfloat162_rn(x, y);
    float rx = x - __bfloat162float(h.x);
    float ry = y - __bfloat162float(h.y);
    __nv_bfloat162 l = __floats2bfloat162_rn(rx, ry);
    hi = *(uint32_t*)&h;
    lo = *(uint32_t*)&l;
}

// 64B-row swizzle (gemm): 4 chunks of 16B; chunk ^= (row>>1)&3
__device__ __forceinline__ uint32_t swz(int row, int chunk) {
    return (uint32_t)(row * 64 + ((chunk ^ ((row >> 1) & 3)) << 4));
}
// 128B-row swizzle (attention): 8 chunks of 16B; chunk ^= row&7
__device__ __forceinline__ uint32_t swz128(int row, int chunk) {
    return (uint32_t)(row * 128 + ((chunk ^ (row & 7)) << 4));
}

// ===========================================================================
// Combined split kernel: x + 4 weight matrices in one launch
// ===========================================================================
__global__ void __launch_bounds__(256) split_all(
    const float* __restrict__ x,
    const float* __restrict__ wq, const float* __restrict__ wk,
    const float* __restrict__ wv, const float* __restrict__ wo)
{
    size_t i = ((size_t)blockIdx.x * 256 + threadIdx.x) * 8;
    const float* src;
    __nv_bfloat16 *hi, *lo;
    size_t off;
    if (i < (size_t)XN) {
        src = x; hi = g_xhi; lo = g_xlo; off = i;
    } else {
        size_t j = i - XN;
        int wsel = (int)(j >> 20);            // WN = 2^20
        off = j & (WN - 1);
        const float* ws[4] = {wq, wk, wv, wo};
        src = ws[wsel]; hi = g_whi[wsel]; lo = g_wlo[wsel];
    }
    float4 v0 = *(const float4*)(src + off);
    float4 v1 = *(const float4*)(src + off + 4);
    uint32_t h[4], l[4];
    split2(v0.x, v0.y, h[0], l[0]); split2(v0.z, v0.w, h[1], l[1]);
    split2(v1.x, v1.y, h[2], l[2]); split2(v1.z, v1.w, h[3], l[3]);
    *(uint4*)(hi + off) = make_uint4(h[0], h[1], h[2], h[3]);
    *(uint4*)(lo + off) = make_uint4(l[0], l[1], l[2], l[3]);
}

// ===========================================================================
// GEMM core: CTA tile 128x128, 8 warps (2m x 4n of 64x32), K-chunk 32,
// 4-stage cp.async pipeline. Computes acc = A @ W^T (hi/lo 3-pass bf16).
// ===========================================================================
#define NSTAGE     4
#define STG_SZ     32768u
#define ST_AHI(s)  ((uint32_t)(s) * STG_SZ + 0u)
#define ST_ALO(s)  ((uint32_t)(s) * STG_SZ + 8192u)
#define ST_BHI(s)  ((uint32_t)(s) * STG_SZ + 16384u)
#define ST_BLO(s)  ((uint32_t)(s) * STG_SZ + 24576u)
#define GEMM_SMEM  (NSTAGE * 32768)   // 131072

struct GemmCore {
    uint32_t sb;
    int tid, lane, wid, wm, wn;
    int m0, n0;
    const __nv_bfloat16 *Ahi, *Alo, *Whi, *Wlo;
    float acc[4][4][4];

    __device__ __forceinline__ void issue_stage(int st, int kt) {
        const int r0c = tid >> 1;
        const int cc0 = (tid & 1) << 1;
        const uint32_t s0 = swz(r0c, cc0), s1 = swz(r0c, cc0 + 1);
        size_t ka = (size_t)kt * 32 + cc0 * 8;
        const __nv_bfloat16* p = Ahi + (size_t)(m0 + r0c) * DM_ + ka;
        CP_ASYNC16(sb + ST_AHI(st) + s0, p);
        CP_ASYNC16(sb + ST_AHI(st) + s1, p + 8);
        p = Alo + (size_t)(m0 + r0c) * DM_ + ka;
        CP_ASYNC16(sb + ST_ALO(st) + s0, p);
        CP_ASYNC16(sb + ST_ALO(st) + s1, p + 8);
        p = Whi + (size_t)(n0 + r0c) * DM_ + ka;
        CP_ASYNC16(sb + ST_BHI(st) + s0, p);
        CP_ASYNC16(sb + ST_BHI(st) + s1, p + 8);
        p = Wlo + (size_t)(n0 + r0c) * DM_ + ka;
        CP_ASYNC16(sb + ST_BLO(st) + s0, p);
        CP_ASYNC16(sb + ST_BLO(st) + s1, p + 8);
    }

    __device__ __forceinline__ void run() {
#pragma unroll
        for (int i = 0; i < 4; i++)
#pragma unroll
            for (int j = 0; j < 4; j++)
#pragma unroll
                for (int r = 0; r < 4; r++) acc[i][j][r] = 0.f;

        issue_stage(0, 0); CP_COMMIT();
        issue_stage(1, 1); CP_COMMIT();
        issue_stage(2, 2); CP_COMMIT();

        const int a_row_in = lane & 15;
        const int a_kh     = lane >> 4;
        const int b_col_in = (lane & 7) + ((lane >> 4) << 3);
        const int b_kh     = (lane >> 3) & 1;

        for (int kt = 0; kt < 32; kt++) {
            // wait until stage kt's group has landed
            if (kt <= 29)      CP_WAIT2();
            else if (kt == 30) CP_WAIT1();
            else               CP_WAIT0();
            __syncthreads();
            // refill: buffer (kt+3)%4 was consumed at iter kt-1 (all warps past it)
            if (kt + 3 < 32) {
                issue_stage((kt + 3) & 3, kt + 3);
                CP_COMMIT();
            }

            const int cur = kt & 3;
            const uint32_t ahiB = sb + ST_AHI(cur), aloB = sb + ST_ALO(cur);
            const uint32_t bhiB = sb + ST_BHI(cur), bloB = sb + ST_BLO(cur);

#pragma unroll
            for (int ks = 0; ks < 2; ks++) {
                uint32_t ahi[4][4], alo[4][4];
#pragma unroll
                for (int mf = 0; mf < 4; mf++) {
                    int row = wm * 64 + mf * 16 + a_row_in;
                    int ch  = ks * 2 + a_kh;
                    uint32_t so = swz(row, ch);
                    ldsm_x4(ahi[mf][0], ahi[mf][1], ahi[mf][2], ahi[mf][3], ahiB + so);
                    ldsm_x4(alo[mf][0], alo[mf][1], alo[mf][2], alo[mf][3], aloB + so);
                }
                uint32_t bhi[4][2], blo[4][2];
#pragma unroll
                for (int bi = 0; bi < 2; bi++) {
                    int col = wn * 32 + bi * 16 + b_col_in;
                    int ch  = ks * 2 + b_kh;
                    uint32_t so = swz(col, ch);
                    uint32_t r0, r1, r2, r3;
                    ldsm_x4(r0, r1, r2, r3, bhiB + so);
                    bhi[bi * 2][0] = r0; bhi[bi * 2][1] = r1;
                    bhi[bi * 2 + 1][0] = r2; bhi[bi * 2 + 1][1] = r3;
                    ldsm_x4(r0, r1, r2, r3, bloB + so);
                    blo[bi * 2][0] = r0; blo[bi * 2][1] = r1;
                    blo[bi * 2 + 1][0] = r2; blo[bi * 2 + 1][1] = r3;
                }
#pragma unroll
                for (int mf = 0; mf < 4; mf++)
#pragma unroll
                    for (int nf = 0; nf < 4; nf++) {
                        mma_bf16(acc[mf][nf], ahi[mf], bhi[nf]);
                        mma_bf16(acc[mf][nf], ahi[mf], blo[nf]);
                        mma_bf16(acc[mf][nf], alo[mf], bhi[nf]);
                    }
            }
        }
    }
};

// QKV GEMM: grid (8, 100, 3); z selects weight/bias/output; bf16 hi/lo scatter
__global__ void __launch_bounds__(256, 1) gemm_qkv(
    const float* __restrict__ bq, const float* __restrict__ bk,
    const float* __restrict__ bv)
{
    extern __shared__ char smem[];
    GemmCore gc;
    gc.sb   = smem_to_u32(smem);
    gc.tid  = threadIdx.x;
    gc.lane = gc.tid & 31;
    gc.wid  = gc.tid >> 5;
    gc.wm   = gc.wid >> 2;
    gc.wn   = gc.wid & 3;
    gc.m0   = blockIdx.y * 128;
    gc.n0   = blockIdx.x * 128;
    const int z = blockIdx.z;
    gc.Ahi = g_xhi;       gc.Alo = g_xlo;
    gc.Whi = g_whi[z];    gc.Wlo = g_wlo[z];
    const float* bias = (z == 0) ? bq : (z == 1) ? bk : bv;
    __nv_bfloat16* Chi = (z == 0) ? g_Qhi : (z == 1) ? g_Khi : g_Vhi;
    __nv_bfloat16* Clo = (z == 0) ? g_Qlo : (z == 1) ? g_Klo : g_Vlo;

    gc.run();

    const int g  = gc.lane >> 2;
    const int c2 = (gc.lane & 3) * 2;
#pragma unroll
    for (int nf = 0; nf < 4; nf++) {
        const int n = gc.n0 + gc.wn * 32 + nf * 8 + c2;
        const float b0 = bias[n], b1 = bias[n + 1];
        const int hh = n >> 6;
        const int dk = n & 63;
#pragma unroll
        for (int mf = 0; mf < 4; mf++) {
            const int m = gc.m0 + gc.wm * 64 + mf * 16 + g;
            uint32_t hi0, lo0, hi1, lo1;
            split2(gc.acc[mf][nf][0] + b0, gc.acc[mf][nf][1] + b1, hi0, lo0);
            split2(gc.acc[mf][nf][2] + b0, gc.acc[mf][nf][3] + b1, hi1, lo1);
            int bb = m / S_;
            int ss = m - bb * S_;
            size_t off0 = (((size_t)bb * H_ + hh) * S_ + ss) * DK_ + dk;
            *(uint32_t*)(Chi + off0) = hi0;
            *(uint32_t*)(Clo + off0) = lo0;
            int m2 = m + 8;
            int bb2 = m2 / S_;
            int ss2 = m2 - bb2 * S_;
            size_t off1 = (((size_t)bb2 * H_ + hh) * S_ + ss2) * DK_ + dk;
            *(uint32_t*)(Chi + off1) = hi1;
            *(uint32_t*)(Clo + off1) = lo1;
        }
    }
}

// Output GEMM: ctx (bf16 hi/lo) @ wo^T + bo -> fp32 row-major
__global__ void __launch_bounds__(256, 1) gemm_out(
    const float* __restrict__ bias, float* __restrict__ Cf)
{
    extern __shared__ char smem[];
    GemmCore gc;
    gc.sb   = smem_to_u32(smem);
    gc.tid  = threadIdx.x;
    gc.lane = gc.tid & 31;
    gc.wid  = gc.tid >> 5;
    gc.wm   = gc.wid >> 2;
    gc.wn   = gc.wid & 3;
    gc.m0   = blockIdx.y * 128;
    gc.n0   = blockIdx.x * 128;
    gc.Ahi = g_ctxhi;   gc.Alo = g_ctxlo;
    gc.Whi = g_whi[3];  gc.Wlo = g_wlo[3];

    gc.run();

    const int g  = gc.lane >> 2;
    const int c2 = (gc.lane & 3) * 2;
#pragma unroll
    for (int nf = 0; nf < 4; nf++) {
        const int n = gc.n0 + gc.wn * 32 + nf * 8 + c2;
        const float b0 = bias[n], b1 = bias[n + 1];
#pragma unroll
        for (int mf = 0; mf < 4; mf++) {
            const int m = gc.m0 + gc.wm * 64 + mf * 16 + g;
            *(float2*)(Cf + (size_t)m * DM_ + n) =
                make_float2(gc.acc[mf][nf][0] + b0, gc.acc[mf][nf][1] + b1);
            *(float2*)(Cf + (size_t)(m + 8) * DM_ + n) =
                make_float2(gc.acc[mf][nf][2] + b0, gc.acc[mf][nf][3] + b1);
        }
    }
}

// ===========================================================================
// Fused attention (R5 config): CTA = (64 q-rows, bh). 128 threads, 2 CTAs/SM.
// ===========================================================================
#define FK_HI   0u
#define FK_LO   26624u
#define FV_HI   53248u
#define FV_LO   79872u
#define FA_SMEM 106496

__global__ void __launch_bounds__(128, 2) attn_fused(
    const int* __restrict__ mask, float* __restrict__ attn)
{
    extern __shared__ char smem[];
    const uint32_t sb = smem_to_u32(smem);
    const int tid  = threadIdx.x;
    const int lane = tid & 31;
    const int w    = tid >> 5;
    const int qt   = blockIdx.x;          // 0..3
    const int bh   = blockIdx.y;
    const int b    = bh >> 4;

    const __nv_bfloat16* Khi = g_Khi + (size_t)bh * S_ * DK_;
    const __nv_bfloat16* Klo = g_Klo + (size_t)bh * S_ * DK_;
    const __nv_bfloat16* Vhi = g_Vhi + (size_t)bh * S_ * DK_;
    const __nv_bfloat16* Vlo = g_Vlo + (size_t)bh * S_ * DK_;
    const __nv_bfloat16* Qhi = g_Qhi + (size_t)bh * S_ * DK_;
    const __nv_bfloat16* Qlo = g_Qlo + (size_t)bh * S_ * DK_;

    for (int c = tid; c < 1600; c += 128) {
        int r = c >> 3, cc = c & 7;
        uint32_t so = swz128(r, cc);
        size_t go = (size_t)r * DK_ + cc * 8;
        CP_ASYNC16(sb + FK_HI + so, Khi + go);
        CP_ASYNC16(sb + FK_LO + so, Klo + go);
        CP_ASYNC16(sb + FV_HI + so, Vhi + go);
        CP_ASYNC16(sb + FV_LO + so, Vlo + go);
    }
    CP_COMMIT();
    if (tid < 64) {
        int r = 200 + (tid >> 3), cc = tid & 7;
        uint32_t so = swz128(r, cc);
        STS128(sb + FK_HI + so, 0u, 0u, 0u, 0u);
        STS128(sb + FK_LO + so, 0u, 0u, 0u, 0u);
        STS128(sb + FV_HI + so, 0u, 0u, 0u, 0u);
        STS128(sb + FV_LO + so, 0u, 0u, 0u, 0u);
    }
    CP_WAIT0();
    __syncthreads();

    float acc[25][4];
#pragma unroll
    for (int f = 0; f < 25; f++)
#pragma unroll
        for (int r = 0; r < 4; r++) acc[f][r] = 0.f;

    const int g  = lane >> 2;
    const int c2 = (lane & 3) * 2;
    const int b_col_in = (lane & 7) + ((lane >> 4) << 3);
    const int b_kh     = (lane >> 3) & 1;

    const int qr0 = qt * 64 + w * 16 + g;
    const int qr1 = qr0 + 8;
    const size_t qo0 = (size_t)min(qr0, S_ - 1) * DK_;
    const size_t qo1 = (size_t)min(qr1, S_ - 1) * DK_;

    for (int kb = 0; kb < 4; kb++) {
        const int col = kb * 16 + c2;
        uint32_t ahi[4], alo[4];
        ahi[0] = *(const uint32_t*)(Qhi + qo0 + col);
        ahi[1] = *(const uint32_t*)(Qhi + qo1 + col);
        ahi[2] = *(const uint32_t*)(Qhi + qo0 + col + 8);
        ahi[3] = *(const uint32_t*)(Qhi + qo1 + col + 8);
        alo[0] = *(const uint32_t*)(Qlo + qo0 + col);
        alo[1] = *(const uint32_t*)(Qlo + qo1 + col);
        alo[2] = *(const uint32_t*)(Qlo + qo0 + col + 8);
        alo[3] = *(const uint32_t*)(Qlo + qo1 + col + 8);
#pragma unroll
        for (int nb = 0; nb < 13; nb++) {
            int row = nb * 16 + b_col_in;
            int ch  = kb * 2 + b_kh;
            uint32_t so = swz128(row, ch);
            uint32_t h0, h1, h2, h3, l0, l1, l2, l3;
            ldsm_x4(h0, h1, h2, h3, sb + FK_HI + so);
            ldsm_x4(l0, l1, l2, l3, sb + FK_LO + so);
            uint32_t bh0[2] = {h0, h1}, bl0[2] = {l0, l1};
            mma_bf16(acc[nb * 2], ahi, bh0);
            mma_bf16(acc[nb * 2], ahi, bl0);
            mma_bf16(acc[nb * 2], alo, bh0);
            if (nb < 12) {
                uint32_t bh1[2] = {h2, h3}, bl1[2] = {l2, l3};
                mma_bf16(acc[nb * 2 + 1], ahi, bh1);
                mma_bf16(acc[nb * 2 + 1], ahi, bl1);
                mma_bf16(acc[nb * 2 + 1], alo, bh1);
            }
        }
    }

    const int gi0 = qr0;
    const int gi1 = qr1;
    const bool v0ok = (gi0 < S_);
    const bool v1ok = (gi1 < S_);
    const int* mrow0 = mask + (size_t)b * S_ * S_ + (size_t)gi0 * S_;
    const int* mrow1 = mask + (size_t)b * S_ * S_ + (size_t)gi1 * S_;
    const float BC = -0.1f / 200.0f;

    float mx0 = -1e30f, mx1 = -1e30f;
#pragma unroll
    for (int f = 0; f < 25; f++) {
        int gj = f * 8 + c2;
        int2 m0v = v0ok ? *(const int2*)(mrow0 + gj) : make_int2(1, 1);
        int2 m1v = v1ok ? *(const int2*)(mrow1 + gj) : make_int2(1, 1);
        float t00 = BC * fabsf((float)(gi0 - gj));
        float t01 = BC * fabsf((float)(gi0 - gj - 1));
        float t10 = BC * fabsf((float)(gi1 - gj));
        float t11 = BC * fabsf((float)(gi1 - gj - 1));
        acc[f][0] = (m0v.x == 0) ? -1e9f : fmaf(acc[f][0], 0.125f, t00);
        acc[f][1] = (m0v.y == 0) ? -1e9f : fmaf(acc[f][1], 0.125f, t01);
        acc[f][2] = (m1v.x == 0) ? -1e9f : fmaf(acc[f][2], 0.125f, t10);
        acc[f][3] = (m1v.y == 0) ? -1e9f : fmaf(acc[f][3], 0.125f, t11);
        mx0 = fmaxf(mx0, fmaxf(acc[f][0], acc[f][1]));
        mx1 = fmaxf(mx1, fmaxf(acc[f][2], acc[f][3]));
    }
    mx0 = fmaxf(mx0, __shfl_xor_sync(0xffffffffu, mx0, 1));
    mx0 = fmaxf(mx0, __shfl_xor_sync(0xffffffffu, mx0, 2));
    mx1 = fmaxf(mx1, __shfl_xor_sync(0xffffffffu, mx1, 1));
    mx1 = fmaxf(mx1, __shfl_xor_sync(0xffffffffu, mx1, 2));

    float s0 = 0.f, s1 = 0.f;
#pragma unroll
    for (int f = 0; f < 25; f++) {
        acc[f][0] = expf(acc[f][0] - mx0);
        acc[f][1] = expf(acc[f][1] - mx0);
        acc[f][2] = expf(acc[f][2] - mx1);
        acc[f][3] = expf(acc[f][3] - mx1);
        s0 += acc[f][0] + acc[f][1];
        s1 += acc[f][2] + acc[f][3];
    }
    s0 += __shfl_xor_sync(0xffffffffu, s0, 1);
    s0 += __shfl_xor_sync(0xffffffffu, s0, 2);
    s1 += __shfl_xor_sync(0xffffffffu, s1, 1);
    s1 += __shfl_xor_sync(0xffffffffu, s1, 2);
    const float i0 = 1.f / s0;
    const float i1 = 1.f / s1;

    float* arow0 = attn + (size_t)bh * S_ * S_ + (size_t)gi0 * S_;
    float* arow1 = attn + (size_t)bh * S_ * S_ + (size_t)gi1 * S_;
#pragma unroll
    for (int f = 0; f < 25; f++) {
        int gj = f * 8 + c2;
        acc[f][0] *= i0; acc[f][1] *= i0;
        acc[f][2] *= i1; acc[f][3] *= i1;
        if (v0ok) *(float2*)(arow0 + gj) = make_float2(acc[f][0], acc[f][1]);
        if (v1ok) *(float2*)(arow1 + gj) = make_float2(acc[f][2], acc[f][3]);
    }

    float cacc[8][4];
#pragma unroll
    for (int nf = 0; nf < 8; nf++)
#pragma unroll
        for (int r = 0; r < 4; r++) cacc[nf][r] = 0.f;

#pragma unroll
    for (int kf = 0; kf < 13; kf++) {
        uint32_t ahi[4], alo[4];
        split2(acc[2 * kf][0], acc[2 * kf][1], ahi[0], alo[0]);
        split2(acc[2 * kf][2], acc[2 * kf][3], ahi[1], alo[1]);
        if (kf < 12) {
            split2(acc[2 * kf + 1][0], acc[2 * kf + 1][1], ahi[2], alo[2]);
            split2(acc[2 * kf + 1][2], acc[2 * kf + 1][3], ahi[3], alo[3]);
        } else {
            ahi[2] = alo[2] = ahi[3] = alo[3] = 0u;
        }
#pragma unroll
        for (int nb = 0; nb < 4; nb++) {
            int row = kf * 16 + (lane & 15);
            int ch  = nb * 2 + (lane >> 4);
            uint32_t so = swz128(row, ch);
            uint32_t h0, h1, h2, h3, l0, l1, l2, l3;
            ldsm_x4_t(h0, h1, h2, h3, sb + FV_HI + so);
            ldsm_x4_t(l0, l1, l2, l3, sb + FV_LO + so);
            uint32_t bh0[2] = {h0, h1}, bl0[2] = {l0, l1};
            uint32_t bh1[2] = {h2, h3}, bl1[2] = {l2, l3};
            mma_bf16(cacc[nb * 2], ahi, bh0);
            mma_bf16(cacc[nb * 2], ahi, bl0);
            mma_bf16(cacc[nb * 2], alo, bh0);
            mma_bf16(cacc[nb * 2 + 1], ahi, bh1);
            mma_bf16(cacc[nb * 2 + 1], ahi, bl1);
            mma_bf16(cacc[nb * 2 + 1], alo, bh1);
        }
    }

    const int h = bh & 15;
    __nv_bfloat16* chi0 = g_ctxhi + ((size_t)b * S_ + gi0) * DM_ + h * DK_;
    __nv_bfloat16* clo0 = g_ctxlo + ((size_t)b * S_ + gi0) * DM_ + h * DK_;
    __nv_bfloat16* chi1 = g_ctxhi + ((size_t)b * S_ + gi1) * DM_ + h * DK_;
    __nv_bfloat16* clo1 = g_ctxlo + ((size_t)b * S_ + gi1) * DM_ + h * DK_;
#pragma unroll
    for (int nf = 0; nf < 8; nf++) {
        int n = nf * 8 + c2;
        uint32_t hi0, lo0, hi1, lo1;
        split2(cacc[nf][0], cacc[nf][1], hi0, lo0);
        split2(cacc[nf][2], cacc[nf][3], hi1, lo1);
        if (v0ok) { *(uint32_t*)(chi0 + n) = hi0; *(uint32_t*)(clo0 + n) = lo0; }
        if (v1ok) { *(uint32_t*)(chi1 + n) = hi1; *(uint32_t*)(clo1 + n) = lo1; }
    }
}

// ---------------------------------------------------------------------------
extern "C" void kernel_launch(void* const* d_in, const int* in_sizes, int n_in,
                              void* d_out, int out_size)
{
    const float* x    = (const float*)d_in[0];
    const int*   mask = (const int*)  d_in[1];
    const float* bq   = (const float*)d_in[3];
    const float* bk   = (const float*)d_in[5];
    const float* bv   = (const float*)d_in[7];
    const float* bo   = (const float*)d_in[9];
    const float* wq   = (const float*)d_in[2];
    const float* wk   = (const float*)d_in[4];
    const float* wv   = (const float*)d_in[6];
    const float* wo   = (const float*)d_in[8];

    void *pAttnFb, *pOutFb;
    cudaGetSymbolAddress(&pAttnFb, g_attn_fb);
    cudaGetSymbolAddress(&pOutFb, g_out_fb);

    float* outp;
    float* attnp;
    size_t osz = (size_t)out_size;
    if (osz >= OUT_N + ATTN_N) {
        outp  = (float*)d_out;
        attnp = (float*)d_out + OUT_N;
    } else if (osz == ATTN_N) {
        attnp = (float*)d_out;
        outp  = (float*)pOutFb;
    } else {
        outp  = (float*)d_out;
        attnp = (float*)pAttnFb;
    }

    cudaFuncSetAttribute(gemm_qkv, cudaFuncAttributeMaxDynamicSharedMemorySize, GEMM_SMEM);
    cudaFuncSetAttribute(gemm_out, cudaFuncAttributeMaxDynamicSharedMemorySize, GEMM_SMEM);
    cudaFuncSetAttribute(attn_fused, cudaFuncAttributeMaxDynamicSharedMemorySize, FA_SMEM);

    const size_t total = (size_t)XN + 4 * (size_t)WN;   // 17301504
    split_all<<<(unsigned)(total / 2048), 256>>>(x, wq, wk, wv, wo);

    dim3 gQKV(DM_ / 128, MROWS / 128, 3);   // (8, 100, 3)
    gemm_qkv<<<gQKV, 256, GEMM_SMEM>>>(bq, bk, bv);

    dim3 gFA(4, BH_);
    attn_fused<<<gFA, 128, FA_SMEM>>>(mask, attnp);

    dim3 gOut(DM_ / 128, MROWS / 128);      // (8, 100)
    gemm_out<<<gOut, 256, GEMM_SMEM>>>(bo, outp);
}

// round 10
// speedup vs baseline: 1.1091x; 1.1087x over previous
#include <cuda_runtime.h>
#include <cuda_bf16.h>
#include <math.h>
#include <stdint.h>

// Problem constants
#define B_    64
#define S_    200
#define H_    16
#define DK_   64
#define DM_   1024
#define MROWS (B_ * S_)          // 12800
#define BH_   (B_ * H_)          // 1024
#define OUT_N  ((size_t)MROWS * DM_)       // 13107200
#define ATTN_N ((size_t)BH_ * S_ * S_)     // 40960000
#define XN    (MROWS * DM_)                // 13107200
#define WN    (DM_ * DM_)                  // 1048576

// Scratch (allocation-free rule: __device__ globals)
__device__ __nv_bfloat16 g_xhi[XN];
__device__ __nv_bfloat16 g_xlo[XN];
__device__ __nv_bfloat16 g_whi[4][WN];
__device__ __nv_bfloat16 g_wlo[4][WN];
__device__ __nv_bfloat16 g_Qhi[BH_ * S_ * DK_];
__device__ __nv_bfloat16 g_Qlo[BH_ * S_ * DK_];
__device__ __nv_bfloat16 g_Khi[BH_ * S_ * DK_];
__device__ __nv_bfloat16 g_Klo[BH_ * S_ * DK_];
__device__ __nv_bfloat16 g_Vhi[BH_ * S_ * DK_];
__device__ __nv_bfloat16 g_Vlo[BH_ * S_ * DK_];
__device__ __nv_bfloat16 g_ctxhi[MROWS * DM_];
__device__ __nv_bfloat16 g_ctxlo[MROWS * DM_];
__device__ float g_attn_fb[BH_ * S_ * S_];
__device__ float g_out_fb[MROWS * DM_];

// ===========================================================================
// Helpers
// ===========================================================================
__device__ __forceinline__ uint32_t smem_to_u32(const void* p) {
    uint32_t a;
    asm("{ .reg .u64 t; cvta.to.shared.u64 t, %1; cvt.u32.u64 %0, t; }"
        : "=r"(a) : "l"(p));
    return a;
}

__device__ __forceinline__ void ldsm_x4(uint32_t& r0, uint32_t& r1,
                                        uint32_t& r2, uint32_t& r3, uint32_t addr) {
    asm volatile("ldmatrix.sync.aligned.m8n8.x4.shared.b16 {%0,%1,%2,%3}, [%4];"
                 : "=r"(r0), "=r"(r1), "=r"(r2), "=r"(r3) : "r"(addr));
}
__device__ __forceinline__ void ldsm_x4_t(uint32_t& r0, uint32_t& r1,
                                          uint32_t& r2, uint32_t& r3, uint32_t addr) {
    asm volatile("ldmatrix.sync.aligned.m8n8.x4.trans.shared.b16 {%0,%1,%2,%3}, [%4];"
                 : "=r"(r0), "=r"(r1), "=r"(r2), "=r"(r3) : "r"(addr));
}

__device__ __forceinline__ void mma_bf16(float* d, const uint32_t* a, const uint32_t* b) {
    asm volatile(
        "mma.sync.aligned.m16n8k16.row.col.f32.bf16.bf16.f32 "
        "{%0,%1,%2,%3}, {%4,%5,%6,%7}, {%8,%9}, {%0,%1,%2,%3};"
        : "+f"(d[0]), "+f"(d[1]), "+f"(d[2]), "+f"(d[3])
        : "r"(a[0]), "r"(a[1]), "r"(a[2]), "r"(a[3]), "r"(b[0]), "r"(b[1]));
}

#define STS128(addr, r0, r1, r2, r3) \
    asm volatile("st.shared.v4.b32 [%0], {%1,%2,%3,%4};" \
        :: "r"(addr), "r"(r0), "r"(r1), "r"(r2), "r"(r3) : "memory")

#define CP_ASYNC16(sm, gp) \
    asm volatile("{ .reg .u64 g; cvta.to.global.u64 g, %1; " \
                 "cp.async.cg.shared.global [%0], [g], 16; }" \
                 :: "r"(sm), "l"(gp) : "memory")
#define CP_COMMIT() asm volatile("cp.async.commit_group;" ::: "memory")
#define CP_WAIT0()  asm volatile("cp.async.wait_group 0;" ::: "memory")
#define CP_WAIT1()  asm volatile("cp.async.wait_group 1;" ::: "memory")

// hi/lo bf16 split of a float pair, packed as 2x uint32 (bf16x2)
__device__ __forceinline__ void split2(float x, float y, uint32_t& hi, uint32_t& lo) {
    __nv_bfloat162 h = __floats2bfloat162_rn(x, y);
    float rx = x - __bfloat162float(h.x);
    float ry = y - __bfloat162float(h.y);
    __nv_bfloat162 l = __floats2bfloat162_rn(rx, ry);
    hi = *(uint32_t*)&h;
    lo = *(uint32_t*)&l;
}

// 64B-row swizzle (gemm): 4 chunks of 16B; chunk ^= (row>>1)&3
__device__ __forceinline__ uint32_t swz(int row, int chunk) {
    return (uint32_t)(row * 64 + ((chunk ^ ((row >> 1) & 3)) << 4));
}
// 128B-row swizzle (attention): 8 chunks of 16B; chunk ^= row&7
__device__ __forceinline__ uint32_t swz128(int row, int chunk) {
    return (uint32_t)(row * 128 + ((chunk ^ (row & 7)) << 4));
}

// ===========================================================================
// Combined split kernel: x + 4 weight matrices in one launch
// ===========================================================================
__global__ void __launch_bounds__(256) split_all(
    const float* __restrict__ x,
    const float* __restrict__ wq, const float* __restrict__ wk,
    const float* __restrict__ wv, const float* __restrict__ wo)
{
    size_t i = ((size_t)blockIdx.x * 256 + threadIdx.x) * 8;
    const float* src;
    __nv_bfloat16 *hi, *lo;
    size_t off;
    if (i < (size_t)XN) {
        src = x; hi = g_xhi; lo = g_xlo; off = i;
    } else {
        size_t j = i - XN;
        int wsel = (int)(j >> 20);            // WN = 2^20
        off = j & (WN - 1);
        const float* ws[4] = {wq, wk, wv, wo};
        src = ws[wsel]; hi = g_whi[wsel]; lo = g_wlo[wsel];
    }
    float4 v0 = *(const float4*)(src + off);
    float4 v1 = *(const float4*)(src + off + 4);
    uint32_t h[4], l[4];
    split2(v0.x, v0.y, h[0], l[0]); split2(v0.z, v0.w, h[1], l[1]);
    split2(v1.x, v1.y, h[2], l[2]); split2(v1.z, v1.w, h[3], l[3]);
    *(uint4*)(hi + off) = make_uint4(h[0], h[1], h[2], h[3]);
    *(uint4*)(lo + off) = make_uint4(l[0], l[1], l[2], l[3]);
}

// ===========================================================================
// GEMM core: CTA tile 64(M) x 128(N), 128 threads (4 warps, each 64x32),
// K-chunk 32, 2-stage cp.async, 48KB smem, 4 CTAs/SM (16 warps/SM).
// acc = A @ W^T (hi/lo 3-pass bf16).
// ===========================================================================
#define STG_SZ     24576u
#define ST_AHI(s)  ((uint32_t)(s) * STG_SZ + 0u)
#define ST_ALO(s)  ((uint32_t)(s) * STG_SZ + 4096u)
#define ST_BHI(s)  ((uint32_t)(s) * STG_SZ + 8192u)
#define ST_BLO(s)  ((uint32_t)(s) * STG_SZ + 16384u)
#define GEMM_SMEM  49152

struct GemmCore {
    uint32_t sb;
    int tid, lane, wn;
    int m0, n0;
    const __nv_bfloat16 *Ahi, *Alo, *Whi, *Wlo;
    float acc[4][4][4];

    __device__ __forceinline__ void issue_stage(int st, int kt) {
        const int r = tid >> 1;               // 0..63
        const int cc = (tid & 1) << 1;        // 0 or 2
        const uint32_t s0 = swz(r, cc), s1 = swz(r, cc + 1);
        const uint32_t s2 = swz(r + 64, cc), s3 = swz(r + 64, cc + 1);
        size_t ka = (size_t)kt * 32 + cc * 8;
        const __nv_bfloat16* p = Ahi + (size_t)(m0 + r) * DM_ + ka;
        CP_ASYNC16(sb + ST_AHI(st) + s0, p);
        CP_ASYNC16(sb + ST_AHI(st) + s1, p + 8);
        p = Alo + (size_t)(m0 + r) * DM_ + ka;
        CP_ASYNC16(sb + ST_ALO(st) + s0, p);
        CP_ASYNC16(sb + ST_ALO(st) + s1, p + 8);
        p = Whi + (size_t)(n0 + r) * DM_ + ka;
        CP_ASYNC16(sb + ST_BHI(st) + s0, p);
        CP_ASYNC16(sb + ST_BHI(st) + s1, p + 8);
        p = Whi + (size_t)(n0 + r + 64) * DM_ + ka;
        CP_ASYNC16(sb + ST_BHI(st) + s2, p);
        CP_ASYNC16(sb + ST_BHI(st) + s3, p + 8);
        p = Wlo + (size_t)(n0 + r) * DM_ + ka;
        CP_ASYNC16(sb + ST_BLO(st) + s0, p);
        CP_ASYNC16(sb + ST_BLO(st) + s1, p + 8);
        p = Wlo + (size_t)(n0 + r + 64) * DM_ + ka;
        CP_ASYNC16(sb + ST_BLO(st) + s2, p);
        CP_ASYNC16(sb + ST_BLO(st) + s3, p + 8);
    }

    __device__ __forceinline__ void run() {
#pragma unroll
        for (int i = 0; i < 4; i++)
#pragma unroll
            for (int j = 0; j < 4; j++)
#pragma unroll
                for (int r = 0; r < 4; r++) acc[i][j][r] = 0.f;

        issue_stage(0, 0);
        CP_COMMIT();

        const int a_row_in = lane & 15;
        const int a_kh     = lane >> 4;
        const int b_col_in = (lane & 7) + ((lane >> 4) << 3);
        const int b_kh     = (lane >> 3) & 1;

        for (int kt = 0; kt < 32; kt++) {
            const int cur = kt & 1;
            if (kt < 31) {
                issue_stage(cur ^ 1, kt + 1);
                CP_COMMIT();
                CP_WAIT1();      // stage kt has landed, kt+1 in flight
            } else {
                CP_WAIT0();
            }
            __syncthreads();

            const uint32_t ahiB = sb + ST_AHI(cur), aloB = sb + ST_ALO(cur);
            const uint32_t bhiB = sb + ST_BHI(cur), bloB = sb + ST_BLO(cur);

#pragma unroll
            for (int ks = 0; ks < 2; ks++) {
                uint32_t ahi[4][4], alo[4][4];
#pragma unroll
                for (int mf = 0; mf < 4; mf++) {
                    int row = mf * 16 + a_row_in;
                    int ch  = ks * 2 + a_kh;
                    uint32_t so = swz(row, ch);
                    ldsm_x4(ahi[mf][0], ahi[mf][1], ahi[mf][2], ahi[mf][3], ahiB + so);
                    ldsm_x4(alo[mf][0], alo[mf][1], alo[mf][2], alo[mf][3], aloB + so);
                }
                uint32_t bhi[4][2], blo[4][2];
#pragma unroll
                for (int bi = 0; bi < 2; bi++) {
                    int col = wn * 32 + bi * 16 + b_col_in;
                    int ch  = ks * 2 + b_kh;
                    uint32_t so = swz(col, ch);
                    uint32_t r0, r1, r2, r3;
                    ldsm_x4(r0, r1, r2, r3, bhiB + so);
                    bhi[bi * 2][0] = r0; bhi[bi * 2][1] = r1;
                    bhi[bi * 2 + 1][0] = r2; bhi[bi * 2 + 1][1] = r3;
                    ldsm_x4(r0, r1, r2, r3, bloB + so);
                    blo[bi * 2][0] = r0; blo[bi * 2][1] = r1;
                    blo[bi * 2 + 1][0] = r2; blo[bi * 2 + 1][1] = r3;
                }
#pragma unroll
                for (int mf = 0; mf < 4; mf++)
#pragma unroll
                    for (int nf = 0; nf < 4; nf++) {
                        mma_bf16(acc[mf][nf], ahi[mf], bhi[nf]);
                        mma_bf16(acc[mf][nf], ahi[mf], blo[nf]);
                        mma_bf16(acc[mf][nf], alo[mf], bhi[nf]);
                    }
            }
            __syncthreads();
        }
    }
};

// QKV GEMM: grid (8, 200, 3); z selects weight/bias/output; bf16 hi/lo scatter
__global__ void __launch_bounds__(128, 4) gemm_qkv(
    const float* __restrict__ bq, const float* __restrict__ bk,
    const float* __restrict__ bv)
{
    extern __shared__ char smem[];
    GemmCore gc;
    gc.sb   = smem_to_u32(smem);
    gc.tid  = threadIdx.x;
    gc.lane = gc.tid & 31;
    gc.wn   = gc.tid >> 5;
    gc.m0   = blockIdx.y * 64;
    gc.n0   = blockIdx.x * 128;
    const int z = blockIdx.z;
    gc.Ahi = g_xhi;       gc.Alo = g_xlo;
    gc.Whi = g_whi[z];    gc.Wlo = g_wlo[z];
    const float* bias = (z == 0) ? bq : (z == 1) ? bk : bv;
    __nv_bfloat16* Chi = (z == 0) ? g_Qhi : (z == 1) ? g_Khi : g_Vhi;
    __nv_bfloat16* Clo = (z == 0) ? g_Qlo : (z == 1) ? g_Klo : g_Vlo;

    gc.run();

    const int g  = gc.lane >> 2;
    const int c2 = (gc.lane & 3) * 2;
#pragma unroll
    for (int nf = 0; nf < 4; nf++) {
        const int n = gc.n0 + gc.wn * 32 + nf * 8 + c2;
        const float b0 = bias[n], b1 = bias[n + 1];
        const int hh = n >> 6;
        const int dk = n & 63;
#pragma unroll
        for (int mf = 0; mf < 4; mf++) {
            const int m = gc.m0 + mf * 16 + g;
            uint32_t hi0, lo0, hi1, lo1;
            split2(gc.acc[mf][nf][0] + b0, gc.acc[mf][nf][1] + b1, hi0, lo0);
            split2(gc.acc[mf][nf][2] + b0, gc.acc[mf][nf][3] + b1, hi1, lo1);
            int bb = m / S_;
            int ss = m - bb * S_;
            size_t off0 = (((size_t)bb * H_ + hh) * S_ + ss) * DK_ + dk;
            *(uint32_t*)(Chi + off0) = hi0;
            *(uint32_t*)(Clo + off0) = lo0;
            int m2 = m + 8;
            int bb2 = m2 / S_;
            int ss2 = m2 - bb2 * S_;
            size_t off1 = (((size_t)bb2 * H_ + hh) * S_ + ss2) * DK_ + dk;
            *(uint32_t*)(Chi + off1) = hi1;
            *(uint32_t*)(Clo + off1) = lo1;
        }
    }
}

// Output GEMM: ctx (bf16 hi/lo) @ wo^T + bo -> fp32 row-major
__global__ void __launch_bounds__(128, 4) gemm_out(
    const float* __restrict__ bias, float* __restrict__ Cf)
{
    extern __shared__ char smem[];
    GemmCore gc;
    gc.sb   = smem_to_u32(smem);
    gc.tid  = threadIdx.x;
    gc.lane = gc.tid & 31;
    gc.wn   = gc.tid >> 5;
    gc.m0   = blockIdx.y * 64;
    gc.n0   = blockIdx.x * 128;
    gc.Ahi = g_ctxhi;   gc.Alo = g_ctxlo;
    gc.Whi = g_whi[3];  gc.Wlo = g_wlo[3];

    gc.run();

    const int g  = gc.lane >> 2;
    const int c2 = (gc.lane & 3) * 2;
#pragma unroll
    for (int nf = 0; nf < 4; nf++) {
        const int n = gc.n0 + gc.wn * 32 + nf * 8 + c2;
        const float b0 = bias[n], b1 = bias[n + 1];
#pragma unroll
        for (int mf = 0; mf < 4; mf++) {
            const int m = gc.m0 + mf * 16 + g;
            *(float2*)(Cf + (size_t)m * DM_ + n) =
                make_float2(gc.acc[mf][nf][0] + b0, gc.acc[mf][nf][1] + b1);
            *(float2*)(Cf + (size_t)(m + 8) * DM_ + n) =
                make_float2(gc.acc[mf][nf][2] + b0, gc.acc[mf][nf][3] + b1);
        }
    }
}

// ===========================================================================
// Fused attention (R5 config): CTA = (64 q-rows, bh). 128 threads, 2 CTAs/SM.
// ===========================================================================
#define FK_HI   0u
#define FK_LO   26624u
#define FV_HI   53248u
#define FV_LO   79872u
#define FA_SMEM 106496

__global__ void __launch_bounds__(128, 2) attn_fused(
    const int* __restrict__ mask, float* __restrict__ attn)
{
    extern __shared__ char smem[];
    const uint32_t sb = smem_to_u32(smem);
    const int tid  = threadIdx.x;
    const int lane = tid & 31;
    const int w    = tid >> 5;
    const int qt   = blockIdx.x;          // 0..3
    const int bh   = blockIdx.y;
    const int b    = bh >> 4;

    const __nv_bfloat16* Khi = g_Khi + (size_t)bh * S_ * DK_;
    const __nv_bfloat16* Klo = g_Klo + (size_t)bh * S_ * DK_;
    const __nv_bfloat16* Vhi = g_Vhi + (size_t)bh * S_ * DK_;
    const __nv_bfloat16* Vlo = g_Vlo + (size_t)bh * S_ * DK_;
    const __nv_bfloat16* Qhi = g_Qhi + (size_t)bh * S_ * DK_;
    const __nv_bfloat16* Qlo = g_Qlo + (size_t)bh * S_ * DK_;

    for (int c = tid; c < 1600; c += 128) {
        int r = c >> 3, cc = c & 7;
        uint32_t so = swz128(r, cc);
        size_t go = (size_t)r * DK_ + cc * 8;
        CP_ASYNC16(sb + FK_HI + so, Khi + go);
        CP_ASYNC16(sb + FK_LO + so, Klo + go);
        CP_ASYNC16(sb + FV_HI + so, Vhi + go);
        CP_ASYNC16(sb + FV_LO + so, Vlo + go);
    }
    CP_COMMIT();
    if (tid < 64) {
        int r = 200 + (tid >> 3), cc = tid & 7;
        uint32_t so = swz128(r, cc);
        STS128(sb + FK_HI + so, 0u, 0u, 0u, 0u);
        STS128(sb + FK_LO + so, 0u, 0u, 0u, 0u);
        STS128(sb + FV_HI + so, 0u, 0u, 0u, 0u);
        STS128(sb + FV_LO + so, 0u, 0u, 0u, 0u);
    }
    CP_WAIT0();
    __syncthreads();

    float acc[25][4];
#pragma unroll
    for (int f = 0; f < 25; f++)
#pragma unroll
        for (int r = 0; r < 4; r++) acc[f][r] = 0.f;

    const int g  = lane >> 2;
    const int c2 = (lane & 3) * 2;
    const int b_col_in = (lane & 7) + ((lane >> 4) << 3);
    const int b_kh     = (lane >> 3) & 1;

    const int qr0 = qt * 64 + w * 16 + g;
    const int qr1 = qr0 + 8;
    const size_t qo0 = (size_t)min(qr0, S_ - 1) * DK_;
    const size_t qo1 = (size_t)min(qr1, S_ - 1) * DK_;

    for (int kb = 0; kb < 4; kb++) {
        const int col = kb * 16 + c2;
        uint32_t ahi[4], alo[4];
        ahi[0] = *(const uint32_t*)(Qhi + qo0 + col);
        ahi[1] = *(const uint32_t*)(Qhi + qo1 + col);
        ahi[2] = *(const uint32_t*)(Qhi + qo0 + col + 8);
        ahi[3] = *(const uint32_t*)(Qhi + qo1 + col + 8);
        alo[0] = *(const uint32_t*)(Qlo + qo0 + col);
        alo[1] = *(const uint32_t*)(Qlo + qo1 + col);
        alo[2] = *(const uint32_t*)(Qlo + qo0 + col + 8);
        alo[3] = *(const uint32_t*)(Qlo + qo1 + col + 8);
#pragma unroll
        for (int nb = 0; nb < 13; nb++) {
            int row = nb * 16 + b_col_in;
            int ch  = kb * 2 + b_kh;
            uint32_t so = swz128(row, ch);
            uint32_t h0, h1, h2, h3, l0, l1, l2, l3;
            ldsm_x4(h0, h1, h2, h3, sb + FK_HI + so);
            ldsm_x4(l0, l1, l2, l3, sb + FK_LO + so);
            uint32_t bh0[2] = {h0, h1}, bl0[2] = {l0, l1};
            mma_bf16(acc[nb * 2], ahi, bh0);
            mma_bf16(acc[nb * 2], ahi, bl0);
            mma_bf16(acc[nb * 2], alo, bh0);
            if (nb < 12) {
                uint32_t bh1[2] = {h2, h3}, bl1[2] = {l2, l3};
                mma_bf16(acc[nb * 2 + 1], ahi, bh1);
                mma_bf16(acc[nb * 2 + 1], ahi, bl1);
                mma_bf16(acc[nb * 2 + 1], alo, bh1);
            }
        }
    }

    const int gi0 = qr0;
    const int gi1 = qr1;
    const bool v0ok = (gi0 < S_);
    const bool v1ok = (gi1 < S_);
    const int* mrow0 = mask + (size_t)b * S_ * S_ + (size_t)gi0 * S_;
    const int* mrow1 = mask + (size_t)b * S_ * S_ + (size_t)gi1 * S_;
    const float BC = -0.1f / 200.0f;

    float mx0 = -1e30f, mx1 = -1e30f;
#pragma unroll
    for (int f = 0; f < 25; f++) {
        int gj = f * 8 + c2;
        int2 m0v = v0ok ? *(const int2*)(mrow0 + gj) : make_int2(1, 1);
        int2 m1v = v1ok ? *(const int2*)(mrow1 + gj) : make_int2(1, 1);
        float t00 = BC * fabsf((float)(gi0 - gj));
        float t01 = BC * fabsf((float)(gi0 - gj - 1));
        float t10 = BC * fabsf((float)(gi1 - gj));
        float t11 = BC * fabsf((float)(gi1 - gj - 1));
        acc[f][0] = (m0v.x == 0) ? -1e9f : fmaf(acc[f][0], 0.125f, t00);
        acc[f][1] = (m0v.y == 0) ? -1e9f : fmaf(acc[f][1], 0.125f, t01);
        acc[f][2] = (m1v.x == 0) ? -1e9f : fmaf(acc[f][2], 0.125f, t10);
        acc[f][3] = (m1v.y == 0) ? -1e9f : fmaf(acc[f][3], 0.125f, t11);
        mx0 = fmaxf(mx0, fmaxf(acc[f][0], acc[f][1]));
        mx1 = fmaxf(mx1, fmaxf(acc[f][2], acc[f][3]));
    }
    mx0 = fmaxf(mx0, __shfl_xor_sync(0xffffffffu, mx0, 1));
    mx0 = fmaxf(mx0, __shfl_xor_sync(0xffffffffu, mx0, 2));
    mx1 = fmaxf(mx1, __shfl_xor_sync(0xffffffffu, mx1, 1));
    mx1 = fmaxf(mx1, __shfl_xor_sync(0xffffffffu, mx1, 2));

    float s0 = 0.f, s1 = 0.f;
#pragma unroll
    for (int f = 0; f < 25; f++) {
        acc[f][0] = expf(acc[f][0] - mx0);
        acc[f][1] = expf(acc[f][1] - mx0);
        acc[f][2] = expf(acc[f][2] - mx1);
        acc[f][3] = expf(acc[f][3] - mx1);
        s0 += acc[f][0] + acc[f][1];
        s1 += acc[f][2] + acc[f][3];
    }
    s0 += __shfl_xor_sync(0xffffffffu, s0, 1);
    s0 += __shfl_xor_sync(0xffffffffu, s0, 2);
    s1 += __shfl_xor_sync(0xffffffffu, s1, 1);
    s1 += __shfl_xor_sync(0xffffffffu, s1, 2);
    const float i0 = 1.f / s0;
    const float i1 = 1.f / s1;

    float* arow0 = attn + (size_t)bh * S_ * S_ + (size_t)gi0 * S_;
    float* arow1 = attn + (size_t)bh * S_ * S_ + (size_t)gi1 * S_;
#pragma unroll
    for (int f = 0; f < 25; f++) {
        int gj = f * 8 + c2;
        acc[f][0] *= i0; acc[f][1] *= i0;
        acc[f][2] *= i1; acc[f][3] *= i1;
        if (v0ok) *(float2*)(arow0 + gj) = make_float2(acc[f][0], acc[f][1]);
        if (v1ok) *(float2*)(arow1 + gj) = make_float2(acc[f][2], acc[f][3]);
    }

    float cacc[8][4];
#pragma unroll
    for (int nf = 0; nf < 8; nf++)
#pragma unroll
        for (int r = 0; r < 4; r++) cacc[nf][r] = 0.f;

#pragma unroll
    for (int kf = 0; kf < 13; kf++) {
        uint32_t ahi[4], alo[4];
        split2(acc[2 * kf][0], acc[2 * kf][1], ahi[0], alo[0]);
        split2(acc[2 * kf][2], acc[2 * kf][3], ahi[1], alo[1]);
        if (kf < 12) {
            split2(acc[2 * kf + 1][0], acc[2 * kf + 1][1], ahi[2], alo[2]);
            split2(acc[2 * kf + 1][2], acc[2 * kf + 1][3], ahi[3], alo[3]);
        } else {
            ahi[2] = alo[2] = ahi[3] = alo[3] = 0u;
        }
#pragma unroll
        for (int nb = 0; nb < 4; nb++) {
            int row = kf * 16 + (lane & 15);
            int ch  = nb * 2 + (lane >> 4);
            uint32_t so = swz128(row, ch);
            uint32_t h0, h1, h2, h3, l0, l1, l2, l3;
            ldsm_x4_t(h0, h1, h2, h3, sb + FV_HI + so);
            ldsm_x4_t(l0, l1, l2, l3, sb + FV_LO + so);
            uint32_t bh0[2] = {h0, h1}, bl0[2] = {l0, l1};
            uint32_t bh1[2] = {h2, h3}, bl1[2] = {l2, l3};
            mma_bf16(cacc[nb * 2], ahi, bh0);
            mma_bf16(cacc[nb * 2], ahi, bl0);
            mma_bf16(cacc[nb * 2], alo, bh0);
            mma_bf16(cacc[nb * 2 + 1], ahi, bh1);
            mma_bf16(cacc[nb * 2 + 1], ahi, bl1);
            mma_bf16(cacc[nb * 2 + 1], alo, bh1);
        }
    }

    const int h = bh & 15;
    __nv_bfloat16* chi0 = g_ctxhi + ((size_t)b * S_ + gi0) * DM_ + h * DK_;
    __nv_bfloat16* clo0 = g_ctxlo + ((size_t)b * S_ + gi0) * DM_ + h * DK_;
    __nv_bfloat16* chi1 = g_ctxhi + ((size_t)b * S_ + gi1) * DM_ + h * DK_;
    __nv_bfloat16* clo1 = g_ctxlo + ((size_t)b * S_ + gi1) * DM_ + h * DK_;
#pragma unroll
    for (int nf = 0; nf < 8; nf++) {
        int n = nf * 8 + c2;
        uint32_t hi0, lo0, hi1, lo1;
        split2(cacc[nf][0], cacc[nf][1], hi0, lo0);
        split2(cacc[nf][2], cacc[nf][3], hi1, lo1);
        if (v0ok) { *(uint32_t*)(chi0 + n) = hi0; *(uint32_t*)(clo0 + n) = lo0; }
        if (v1ok) { *(uint32_t*)(chi1 + n) = hi1; *(uint32_t*)(clo1 + n) = lo1; }
    }
}

// ---------------------------------------------------------------------------
extern "C" void kernel_launch(void* const* d_in, const int* in_sizes, int n_in,
                              void* d_out, int out_size)
{
    const float* x    = (const float*)d_in[0];
    const int*   mask = (const int*)  d_in[1];
    const float* wq   = (const float*)d_in[2];
    const float* bq   = (const float*)d_in[3];
    const float* wk   = (const float*)d_in[4];
    const float* bk   = (const float*)d_in[5];
    const float* wv   = (const float*)d_in[6];
    const float* bv   = (const float*)d_in[7];
    const float* wo   = (const float*)d_in[8];
    const float* bo   = (const float*)d_in[9];

    void *pAttnFb, *pOutFb;
    cudaGetSymbolAddress(&pAttnFb, g_attn_fb);
    cudaGetSymbolAddress(&pOutFb, g_out_fb);

    float* outp;
    float* attnp;
    size_t osz = (size_t)out_size;
    if (osz >= OUT_N + ATTN_N) {
        outp  = (float*)d_out;
        attnp = (float*)d_out + OUT_N;
    } else if (osz == ATTN_N) {
        attnp = (float*)d_out;
        outp  = (float*)pOutFb;
    } else {
        outp  = (float*)d_out;
        attnp = (float*)pAttnFb;
    }

    cudaFuncSetAttribute(gemm_qkv, cudaFuncAttributeMaxDynamicSharedMemorySize, GEMM_SMEM);
    cudaFuncSetAttribute(gemm_out, cudaFuncAttributeMaxDynamicSharedMemorySize, GEMM_SMEM);
    cudaFuncSetAttribute(attn_fused, cudaFuncAttributeMaxDynamicSharedMemorySize, FA_SMEM);

    const size_t total = (size_t)XN + 4 * (size_t)WN;   // 17301504
    split_all<<<(unsigned)(total / 2048), 256>>>(x, wq, wk, wv, wo);

    dim3 gQKV(DM_ / 128, MROWS / 64, 3);   // (8, 200, 3)
    gemm_qkv<<<gQKV, 128, GEMM_SMEM>>>(bq, bk, bv);

    dim3 gFA(4, BH_);
    attn_fused<<<gFA, 128, FA_SMEM>>>(mask, attnp);

    dim3 gOut(DM_ / 128, MROWS / 64);      // (8, 200)
    gemm_out<<<gOut, 128, GEMM_SMEM>>>(bo, outp);
}

// round 11
// speedup vs baseline: 1.5085x; 1.3601x over previous
#include <cuda_runtime.h>
#include <cuda_fp16.h>
#include <math.h>
#include <stdint.h>

// Problem constants
#define B_    64
#define S_    200
#define H_    16
#define DK_   64
#define DM_   1024
#define MROWS (B_ * S_)          // 12800
#define BH_   (B_ * H_)          // 1024
#define OUT_N  ((size_t)MROWS * DM_)       // 13107200
#define ATTN_N ((size_t)BH_ * S_ * S_)     // 40960000
#define XN    (MROWS * DM_)                // 13107200
#define WN    (DM_ * DM_)                  // 1048576

// Scratch (allocation-free rule: __device__ globals)
__device__ __half g_xhi[XN];
__device__ __half g_xlo[XN];
__device__ __half g_whi[4][WN];
__device__ __half g_Qhi[BH_ * S_ * DK_];
__device__ __half g_Qlo[BH_ * S_ * DK_];
__device__ __half g_Khi[BH_ * S_ * DK_];
__device__ __half g_Vhi[BH_ * S_ * DK_];
__device__ __half g_ctxhi[MROWS * DM_];
__device__ __half g_ctxlo[MROWS * DM_];
__device__ float g_attn_fb[BH_ * S_ * S_];
__device__ float g_out_fb[MROWS * DM_];

// ===========================================================================
// Helpers
// ===========================================================================
__device__ __forceinline__ uint32_t smem_to_u32(const void* p) {
    uint32_t a;
    asm("{ .reg .u64 t; cvta.to.shared.u64 t, %1; cvt.u32.u64 %0, t; }"
        : "=r"(a) : "l"(p));
    return a;
}

__device__ __forceinline__ void ldsm_x4(uint32_t& r0, uint32_t& r1,
                                        uint32_t& r2, uint32_t& r3, uint32_t addr) {
    asm volatile("ldmatrix.sync.aligned.m8n8.x4.shared.b16 {%0,%1,%2,%3}, [%4];"
                 : "=r"(r0), "=r"(r1), "=r"(r2), "=r"(r3) : "r"(addr));
}
__device__ __forceinline__ void ldsm_x4_t(uint32_t& r0, uint32_t& r1,
                                          uint32_t& r2, uint32_t& r3, uint32_t addr) {
    asm volatile("ldmatrix.sync.aligned.m8n8.x4.trans.shared.b16 {%0,%1,%2,%3}, [%4];"
                 : "=r"(r0), "=r"(r1), "=r"(r2), "=r"(r3) : "r"(addr));
}

__device__ __forceinline__ void mma_fp16(float* d, const uint32_t* a, const uint32_t* b) {
    asm volatile(
        "mma.sync.aligned.m16n8k16.row.col.f32.f16.f16.f32 "
        "{%0,%1,%2,%3}, {%4,%5,%6,%7}, {%8,%9}, {%0,%1,%2,%3};"
        : "+f"(d[0]), "+f"(d[1]), "+f"(d[2]), "+f"(d[3])
        : "r"(a[0]), "r"(a[1]), "r"(a[2]), "r"(a[3]), "r"(b[0]), "r"(b[1]));
}

#define STS128(addr, r0, r1, r2, r3) \
    asm volatile("st.shared.v4.b32 [%0], {%1,%2,%3,%4};" \
        :: "r"(addr), "r"(r0), "r"(r1), "r"(r2), "r"(r3) : "memory")

#define CP_ASYNC16(sm, gp) \
    asm volatile("{ .reg .u64 g; cvta.to.global.u64 g, %1; " \
                 "cp.async.cg.shared.global [%0], [g], 16; }" \
                 :: "r"(sm), "l"(gp) : "memory")
#define CP_COMMIT() asm volatile("cp.async.commit_group;" ::: "memory")
#define CP_WAIT0()  asm volatile("cp.async.wait_group 0;" ::: "memory")
#define CP_WAIT1()  asm volatile("cp.async.wait_group 1;" ::: "memory")

// hi/lo fp16 split of a float pair, packed as 2x uint32 (half2)
__device__ __forceinline__ void split2h(float x, float y, uint32_t& hi, uint32_t& lo) {
    __half2 h = __floats2half2_rn(x, y);
    float rx = x - __half2float(__low2half(h));
    float ry = y - __half2float(__high2half(h));
    __half2 l = __floats2half2_rn(rx, ry);
    hi = *(uint32_t*)&h;
    lo = *(uint32_t*)&l;
}
__device__ __forceinline__ uint32_t cvt2h(float x, float y) {
    __half2 h = __floats2half2_rn(x, y);
    return *(uint32_t*)&h;
}

// 64B-row swizzle (gemm): 4 chunks of 16B; chunk ^= (row>>1)&3
__device__ __forceinline__ uint32_t swz(int row, int chunk) {
    return (uint32_t)(row * 64 + ((chunk ^ ((row >> 1) & 3)) << 4));
}
// 128B-row swizzle (attention): 8 chunks of 16B; chunk ^= row&7
__device__ __forceinline__ uint32_t swz128(int row, int chunk) {
    return (uint32_t)(row * 128 + ((chunk ^ (row & 7)) << 4));
}

// ===========================================================================
// Combined split kernel: x (hi/lo) + 4 weight matrices (hi only), one launch
// ===========================================================================
__global__ void __launch_bounds__(256) split_all(
    const float* __restrict__ x,
    const float* __restrict__ wq, const float* __restrict__ wk,
    const float* __restrict__ wv, const float* __restrict__ wo)
{
    size_t i = ((size_t)blockIdx.x * 256 + threadIdx.x) * 8;
    if (i < (size_t)XN) {
        float4 v0 = *(const float4*)(x + i);
        float4 v1 = *(const float4*)(x + i + 4);
        uint32_t h[4], l[4];
        split2h(v0.x, v0.y, h[0], l[0]); split2h(v0.z, v0.w, h[1], l[1]);
        split2h(v1.x, v1.y, h[2], l[2]); split2h(v1.z, v1.w, h[3], l[3]);
        *(uint4*)(g_xhi + i) = make_uint4(h[0], h[1], h[2], h[3]);
        *(uint4*)(g_xlo + i) = make_uint4(l[0], l[1], l[2], l[3]);
    } else {
        size_t j = i - XN;
        int wsel = (int)(j >> 20);            // WN = 2^20
        size_t off = j & (WN - 1);
        const float* ws[4] = {wq, wk, wv, wo};
        const float* src = ws[wsel];
        float4 v0 = *(const float4*)(src + off);
        float4 v1 = *(const float4*)(src + off + 4);
        uint4 out;
        out.x = cvt2h(v0.x, v0.y); out.y = cvt2h(v0.z, v0.w);
        out.z = cvt2h(v1.x, v1.y); out.w = cvt2h(v1.z, v1.w);
        *(uint4*)(g_whi[wsel] + off) = out;
    }
}

// ===========================================================================
// GEMM core: CTA 64(M) x 128(N), 128 threads (4 warps of 64x32), K-chunk 32,
// 2-stage cp.async, 32KB smem, 4 CTAs/SM. fp16 2-pass: acc = (Ahi+Alo)@Whi^T.
// ===========================================================================
#define STG_SZ     16384u
#define ST_AHI(s)  ((uint32_t)(s) * STG_SZ + 0u)
#define ST_ALO(s)  ((uint32_t)(s) * STG_SZ + 4096u)
#define ST_BHI(s)  ((uint32_t)(s) * STG_SZ + 8192u)
#define GEMM_SMEM  32768

struct GemmCore {
    uint32_t sb;
    int tid, lane, wn;
    int m0, n0;
    const __half *Ahi, *Alo, *Whi;
    float acc[4][4][4];

    __device__ __forceinline__ void issue_stage(int st, int kt) {
        const int r = tid >> 1;               // 0..63
        const int cc = (tid & 1) << 1;        // 0 or 2
        const uint32_t s0 = swz(r, cc), s1 = swz(r, cc + 1);
        const uint32_t s2 = swz(r + 64, cc), s3 = swz(r + 64, cc + 1);
        size_t ka = (size_t)kt * 32 + cc * 8;
        const __half* p = Ahi + (size_t)(m0 + r) * DM_ + ka;
        CP_ASYNC16(sb + ST_AHI(st) + s0, p);
        CP_ASYNC16(sb + ST_AHI(st) + s1, p + 8);
        p = Alo + (size_t)(m0 + r) * DM_ + ka;
        CP_ASYNC16(sb + ST_ALO(st) + s0, p);
        CP_ASYNC16(sb + ST_ALO(st) + s1, p + 8);
        p = Whi + (size_t)(n0 + r) * DM_ + ka;
        CP_ASYNC16(sb + ST_BHI(st) + s0, p);
        CP_ASYNC16(sb + ST_BHI(st) + s1, p + 8);
        p = Whi + (size_t)(n0 + r + 64) * DM_ + ka;
        CP_ASYNC16(sb + ST_BHI(st) + s2, p);
        CP_ASYNC16(sb + ST_BHI(st) + s3, p + 8);
    }

    __device__ __forceinline__ void run() {
#pragma unroll
        for (int i = 0; i < 4; i++)
#pragma unroll
            for (int j = 0; j < 4; j++)
#pragma unroll
                for (int r = 0; r < 4; r++) acc[i][j][r] = 0.f;

        issue_stage(0, 0);
        CP_COMMIT();

        const int a_row_in = lane & 15;
        const int a_kh     = lane >> 4;
        const int b_col_in = (lane & 7) + ((lane >> 4) << 3);
        const int b_kh     = (lane >> 3) & 1;

        for (int kt = 0; kt < 32; kt++) {
            const int cur = kt & 1;
            if (kt < 31) {
                issue_stage(cur ^ 1, kt + 1);
                CP_COMMIT();
                CP_WAIT1();
            } else {
                CP_WAIT0();
            }
            __syncthreads();

            const uint32_t ahiB = sb + ST_AHI(cur), aloB = sb + ST_ALO(cur);
            const uint32_t bhiB = sb + ST_BHI(cur);

#pragma unroll
            for (int ks = 0; ks < 2; ks++) {
                uint32_t ahi[4][4], alo[4][4];
#pragma unroll
                for (int mf = 0; mf < 4; mf++) {
                    int row = mf * 16 + a_row_in;
                    int ch  = ks * 2 + a_kh;
                    uint32_t so = swz(row, ch);
                    ldsm_x4(ahi[mf][0], ahi[mf][1], ahi[mf][2], ahi[mf][3], ahiB + so);
                    ldsm_x4(alo[mf][0], alo[mf][1], alo[mf][2], alo[mf][3], aloB + so);
                }
                uint32_t bhi[4][2];
#pragma unroll
                for (int bi = 0; bi < 2; bi++) {
                    int col = wn * 32 + bi * 16 + b_col_in;
                    int ch  = ks * 2 + b_kh;
                    uint32_t so = swz(col, ch);
                    uint32_t r0, r1, r2, r3;
                    ldsm_x4(r0, r1, r2, r3, bhiB + so);
                    bhi[bi * 2][0] = r0; bhi[bi * 2][1] = r1;
                    bhi[bi * 2 + 1][0] = r2; bhi[bi * 2 + 1][1] = r3;
                }
#pragma unroll
                for (int mf = 0; mf < 4; mf++)
#pragma unroll
                    for (int nf = 0; nf < 4; nf++) {
                        mma_fp16(acc[mf][nf], ahi[mf], bhi[nf]);
                        mma_fp16(acc[mf][nf], alo[mf], bhi[nf]);
                    }
            }
            __syncthreads();
        }
    }
};

// QKV GEMM: grid (8, 200, 3). z=0: Q (split hi/lo), z=1: K (hi), z=2: V (hi)
__global__ void __launch_bounds__(128, 4) gemm_qkv(
    const float* __restrict__ bq, const float* __restrict__ bk,
    const float* __restrict__ bv)
{
    extern __shared__ char smem[];
    GemmCore gc;
    gc.sb   = smem_to_u32(smem);
    gc.tid  = threadIdx.x;
    gc.lane = gc.tid & 31;
    gc.wn   = gc.tid >> 5;
    gc.m0   = blockIdx.y * 64;
    gc.n0   = blockIdx.x * 128;
    const int z = blockIdx.z;
    gc.Ahi = g_xhi;  gc.Alo = g_xlo;  gc.Whi = g_whi[z];
    const float* bias = (z == 0) ? bq : (z == 1) ? bk : bv;
    __half* Chi = (z == 0) ? g_Qhi : (z == 1) ? g_Khi : g_Vhi;

    gc.run();

    const int g  = gc.lane >> 2;
    const int c2 = (gc.lane & 3) * 2;
#pragma unroll
    for (int nf = 0; nf < 4; nf++) {
        const int n = gc.n0 + gc.wn * 32 + nf * 8 + c2;
        const float b0 = bias[n], b1 = bias[n + 1];
        const int hh = n >> 6;
        const int dk = n & 63;
#pragma unroll
        for (int mf = 0; mf < 4; mf++) {
            const int m = gc.m0 + mf * 16 + g;
            float v00 = gc.acc[mf][nf][0] + b0, v01 = gc.acc[mf][nf][1] + b1;
            float v10 = gc.acc[mf][nf][2] + b0, v11 = gc.acc[mf][nf][3] + b1;
            int bb = m / S_;
            int ss = m - bb * S_;
            size_t off0 = (((size_t)bb * H_ + hh) * S_ + ss) * DK_ + dk;
            int m2 = m + 8;
            int bb2 = m2 / S_;
            int ss2 = m2 - bb2 * S_;
            size_t off1 = (((size_t)bb2 * H_ + hh) * S_ + ss2) * DK_ + dk;
            if (z == 0) {
                uint32_t hi0, lo0, hi1, lo1;
                split2h(v00, v01, hi0, lo0);
                split2h(v10, v11, hi1, lo1);
                *(uint32_t*)(g_Qhi + off0) = hi0;
                *(uint32_t*)(g_Qlo + off0) = lo0;
                *(uint32_t*)(g_Qhi + off1) = hi1;
                *(uint32_t*)(g_Qlo + off1) = lo1;
            } else {
                *(uint32_t*)(Chi + off0) = cvt2h(v00, v01);
                *(uint32_t*)(Chi + off1) = cvt2h(v10, v11);
            }
        }
    }
}

// Output GEMM: ctx (fp16 hi/lo) @ wo^T + bo -> fp32 row-major
__global__ void __launch_bounds__(128, 4) gemm_out(
    const float* __restrict__ bias, float* __restrict__ Cf)
{
    extern __shared__ char smem[];
    GemmCore gc;
    gc.sb   = smem_to_u32(smem);
    gc.tid  = threadIdx.x;
    gc.lane = gc.tid & 31;
    gc.wn   = gc.tid >> 5;
    gc.m0   = blockIdx.y * 64;
    gc.n0   = blockIdx.x * 128;
    gc.Ahi = g_ctxhi;  gc.Alo = g_ctxlo;  gc.Whi = g_whi[3];

    gc.run();

    const int g  = gc.lane >> 2;
    const int c2 = (gc.lane & 3) * 2;
#pragma unroll
    for (int nf = 0; nf < 4; nf++) {
        const int n = gc.n0 + gc.wn * 32 + nf * 8 + c2;
        const float b0 = bias[n], b1 = bias[n + 1];
#pragma unroll
        for (int mf = 0; mf < 4; mf++) {
            const int m = gc.m0 + mf * 16 + g;
            *(float2*)(Cf + (size_t)m * DM_ + n) =
                make_float2(gc.acc[mf][nf][0] + b0, gc.acc[mf][nf][1] + b1);
            *(float2*)(Cf + (size_t)(m + 8) * DM_ + n) =
                make_float2(gc.acc[mf][nf][2] + b0, gc.acc[mf][nf][3] + b1);
        }
    }
}

// ===========================================================================
// Fused attention: CTA = (64 q-rows, bh). 128 threads, 2 CTAs/SM.
// K/V single fp16 in smem; Q hi/lo from gmem; 2-pass MMAs.
// ===========================================================================
#define FK_HI   0u
#define FV_HI   26624u
#define FA_SMEM 53248

__global__ void __launch_bounds__(128, 2) attn_fused(
    const int* __restrict__ mask, float* __restrict__ attn)
{
    extern __shared__ char smem[];
    const uint32_t sb = smem_to_u32(smem);
    const int tid  = threadIdx.x;
    const int lane = tid & 31;
    const int w    = tid >> 5;
    const int qt   = blockIdx.x;          // 0..3
    const int bh   = blockIdx.y;
    const int b    = bh >> 4;

    const __half* Khi = g_Khi + (size_t)bh * S_ * DK_;
    const __half* Vhi = g_Vhi + (size_t)bh * S_ * DK_;
    const __half* Qhi = g_Qhi + (size_t)bh * S_ * DK_;
    const __half* Qlo = g_Qlo + (size_t)bh * S_ * DK_;

    for (int c = tid; c < 1600; c += 128) {
        int r = c >> 3, cc = c & 7;
        uint32_t so = swz128(r, cc);
        size_t go = (size_t)r * DK_ + cc * 8;
        CP_ASYNC16(sb + FK_HI + so, Khi + go);
        CP_ASYNC16(sb + FV_HI + so, Vhi + go);
    }
    CP_COMMIT();
    if (tid < 64) {
        int r = 200 + (tid >> 3), cc = tid & 7;
        uint32_t so = swz128(r, cc);
        STS128(sb + FK_HI + so, 0u, 0u, 0u, 0u);
        STS128(sb + FV_HI + so, 0u, 0u, 0u, 0u);
    }
    CP_WAIT0();
    __syncthreads();

    float acc[25][4];
#pragma unroll
    for (int f = 0; f < 25; f++)
#pragma unroll
        for (int r = 0; r < 4; r++) acc[f][r] = 0.f;

    const int g  = lane >> 2;
    const int c2 = (lane & 3) * 2;
    const int b_col_in = (lane & 7) + ((lane >> 4) << 3);
    const int b_kh     = (lane >> 3) & 1;

    const int qr0 = qt * 64 + w * 16 + g;
    const int qr1 = qr0 + 8;
    const size_t qo0 = (size_t)min(qr0, S_ - 1) * DK_;
    const size_t qo1 = (size_t)min(qr1, S_ - 1) * DK_;

    for (int kb = 0; kb < 4; kb++) {
        const int col = kb * 16 + c2;
        uint32_t ahi[4], alo[4];
        ahi[0] = *(const uint32_t*)(Qhi + qo0 + col);
        ahi[1] = *(const uint32_t*)(Qhi + qo1 + col);
        ahi[2] = *(const uint32_t*)(Qhi + qo0 + col + 8);
        ahi[3] = *(const uint32_t*)(Qhi + qo1 + col + 8);
        alo[0] = *(const uint32_t*)(Qlo + qo0 + col);
        alo[1] = *(const uint32_t*)(Qlo + qo1 + col);
        alo[2] = *(const uint32_t*)(Qlo + qo0 + col + 8);
        alo[3] = *(const uint32_t*)(Qlo + qo1 + col + 8);
#pragma unroll
        for (int nb = 0; nb < 13; nb++) {
            int row = nb * 16 + b_col_in;
            int ch  = kb * 2 + b_kh;
            uint32_t so = swz128(row, ch);
            uint32_t h0, h1, h2, h3;
            ldsm_x4(h0, h1, h2, h3, sb + FK_HI + so);
            uint32_t bh0[2] = {h0, h1};
            mma_fp16(acc[nb * 2], ahi, bh0);
            mma_fp16(acc[nb * 2], alo, bh0);
            if (nb < 12) {
                uint32_t bh1[2] = {h2, h3};
                mma_fp16(acc[nb * 2 + 1], ahi, bh1);
                mma_fp16(acc[nb * 2 + 1], alo, bh1);
            }
        }
    }

    const int gi0 = qr0;
    const int gi1 = qr1;
    const bool v0ok = (gi0 < S_);
    const bool v1ok = (gi1 < S_);
    const int* mrow0 = mask + (size_t)b * S_ * S_ + (size_t)gi0 * S_;
    const int* mrow1 = mask + (size_t)b * S_ * S_ + (size_t)gi1 * S_;
    const float BC = -0.1f / 200.0f;

    float mx0 = -1e30f, mx1 = -1e30f;
#pragma unroll
    for (int f = 0; f < 25; f++) {
        int gj = f * 8 + c2;
        int2 m0v = v0ok ? *(const int2*)(mrow0 + gj) : make_int2(1, 1);
        int2 m1v = v1ok ? *(const int2*)(mrow1 + gj) : make_int2(1, 1);
        float t00 = BC * fabsf((float)(gi0 - gj));
        float t01 = BC * fabsf((float)(gi0 - gj - 1));
        float t10 = BC * fabsf((float)(gi1 - gj));
        float t11 = BC * fabsf((float)(gi1 - gj - 1));
        acc[f][0] = (m0v.x == 0) ? -1e9f : fmaf(acc[f][0], 0.125f, t00);
        acc[f][1] = (m0v.y == 0) ? -1e9f : fmaf(acc[f][1], 0.125f, t01);
        acc[f][2] = (m1v.x == 0) ? -1e9f : fmaf(acc[f][2], 0.125f, t10);
        acc[f][3] = (m1v.y == 0) ? -1e9f : fmaf(acc[f][3], 0.125f, t11);
        mx0 = fmaxf(mx0, fmaxf(acc[f][0], acc[f][1]));
        mx1 = fmaxf(mx1, fmaxf(acc[f][2], acc[f][3]));
    }
    mx0 = fmaxf(mx0, __shfl_xor_sync(0xffffffffu, mx0, 1));
    mx0 = fmaxf(mx0, __shfl_xor_sync(0xffffffffu, mx0, 2));
    mx1 = fmaxf(mx1, __shfl_xor_sync(0xffffffffu, mx1, 1));
    mx1 = fmaxf(mx1, __shfl_xor_sync(0xffffffffu, mx1, 2));

    float s0 = 0.f, s1 = 0.f;
#pragma unroll
    for (int f = 0; f < 25; f++) {
        acc[f][0] = expf(acc[f][0] - mx0);
        acc[f][1] = expf(acc[f][1] - mx0);
        acc[f][2] = expf(acc[f][2] - mx1);
        acc[f][3] = expf(acc[f][3] - mx1);
        s0 += acc[f][0] + acc[f][1];
        s1 += acc[f][2] + acc[f][3];
    }
    s0 += __shfl_xor_sync(0xffffffffu, s0, 1);
    s0 += __shfl_xor_sync(0xffffffffu, s0, 2);
    s1 += __shfl_xor_sync(0xffffffffu, s1, 1);
    s1 += __shfl_xor_sync(0xffffffffu, s1, 2);
    const float i0 = 1.f / s0;
    const float i1 = 1.f / s1;

    float* arow0 = attn + (size_t)bh * S_ * S_ + (size_t)gi0 * S_;
    float* arow1 = attn + (size_t)bh * S_ * S_ + (size_t)gi1 * S_;
#pragma unroll
    for (int f = 0; f < 25; f++) {
        int gj = f * 8 + c2;
        acc[f][0] *= i0; acc[f][1] *= i0;
        acc[f][2] *= i1; acc[f][3] *= i1;
        if (v0ok) *(float2*)(arow0 + gj) = make_float2(acc[f][0], acc[f][1]);
        if (v1ok) *(float2*)(arow1 + gj) = make_float2(acc[f][2], acc[f][3]);
    }

    float cacc[8][4];
#pragma unroll
    for (int nf = 0; nf < 8; nf++)
#pragma unroll
        for (int r = 0; r < 4; r++) cacc[nf][r] = 0.f;

#pragma unroll
    for (int kf = 0; kf < 13; kf++) {
        uint32_t ahi[4], alo[4];
        split2h(acc[2 * kf][0], acc[2 * kf][1], ahi[0], alo[0]);
        split2h(acc[2 * kf][2], acc[2 * kf][3], ahi[1], alo[1]);
        if (kf < 12) {
            split2h(acc[2 * kf + 1][0], acc[2 * kf + 1][1], ahi[2], alo[2]);
            split2h(acc[2 * kf + 1][2], acc[2 * kf + 1][3], ahi[3], alo[3]);
        } else {
            ahi[2] = alo[2] = ahi[3] = alo[3] = 0u;
        }
#pragma unroll
        for (int nb = 0; nb < 4; nb++) {
            int row = kf * 16 + (lane & 15);
            int ch  = nb * 2 + (lane >> 4);
            uint32_t so = swz128(row, ch);
            uint32_t h0, h1, h2, h3;
            ldsm_x4_t(h0, h1, h2, h3, sb + FV_HI + so);
            uint32_t bh0[2] = {h0, h1};
            uint32_t bh1[2] = {h2, h3};
            mma_fp16(cacc[nb * 2], ahi, bh0);
            mma_fp16(cacc[nb * 2], alo, bh0);
            mma_fp16(cacc[nb * 2 + 1], ahi, bh1);
            mma_fp16(cacc[nb * 2 + 1], alo, bh1);
        }
    }

    const int h = bh & 15;
    __half* chi0 = g_ctxhi + ((size_t)b * S_ + gi0) * DM_ + h * DK_;
    __half* clo0 = g_ctxlo + ((size_t)b * S_ + gi0) * DM_ + h * DK_;
    __half* chi1 = g_ctxhi + ((size_t)b * S_ + gi1) * DM_ + h * DK_;
    __half* clo1 = g_ctxlo + ((size_t)b * S_ + gi1) * DM_ + h * DK_;
#pragma unroll
    for (int nf = 0; nf < 8; nf++) {
        int n = nf * 8 + c2;
        uint32_t hi0, lo0, hi1, lo1;
        split2h(cacc[nf][0], cacc[nf][1], hi0, lo0);
        split2h(cacc[nf][2], cacc[nf][3], hi1, lo1);
        if (v0ok) { *(uint32_t*)(chi0 + n) = hi0; *(uint32_t*)(clo0 + n) = lo0; }
        if (v1ok) { *(uint32_t*)(chi1 + n) = hi1; *(uint32_t*)(clo1 + n) = lo1; }
    }
}

// ---------------------------------------------------------------------------
extern "C" void kernel_launch(void* const* d_in, const int* in_sizes, int n_in,
                              void* d_out, int out_size)
{
    const float* x    = (const float*)d_in[0];
    const int*   mask = (const int*)  d_in[1];
    const float* wq   = (const float*)d_in[2];
    const float* bq   = (const float*)d_in[3];
    const float* wk   = (const float*)d_in[4];
    const float* bk   = (const float*)d_in[5];
    const float* wv   = (const float*)d_in[6];
    const float* bv   = (const float*)d_in[7];
    const float* wo   = (const float*)d_in[8];
    const float* bo   = (const float*)d_in[9];

    void *pAttnFb, *pOutFb;
    cudaGetSymbolAddress(&pAttnFb, g_attn_fb);
    cudaGetSymbolAddress(&pOutFb, g_out_fb);

    float* outp;
    float* attnp;
    size_t osz = (size_t)out_size;
    if (osz >= OUT_N + ATTN_N) {
        outp  = (float*)d_out;
        attnp = (float*)d_out + OUT_N;
    } else if (osz == ATTN_N) {
        attnp = (float*)d_out;
        outp  = (float*)pOutFb;
    } else {
        outp  = (float*)d_out;
        attnp = (float*)pAttnFb;
    }

    cudaFuncSetAttribute(gemm_qkv, cudaFuncAttributeMaxDynamicSharedMemorySize, GEMM_SMEM);
    cudaFuncSetAttribute(gemm_out, cudaFuncAttributeMaxDynamicSharedMemorySize, GEMM_SMEM);
    cudaFuncSetAttribute(attn_fused, cudaFuncAttributeMaxDynamicSharedMemorySize, FA_SMEM);

    const size_t total = (size_t)XN + 4 * (size_t)WN;   // 17301504
    split_all<<<(unsigned)(total / 2048), 256>>>(x, wq, wk, wv, wo);

    dim3 gQKV(DM_ / 128, MROWS / 64, 3);   // (8, 200, 3)
    gemm_qkv<<<gQKV, 128, GEMM_SMEM>>>(bq, bk, bv);

    dim3 gFA(4, BH_);
    attn_fused<<<gFA, 128, FA_SMEM>>>(mask, attnp);

    dim3 gOut(DM_ / 128, MROWS / 64);      // (8, 200)
    gemm_out<<<gOut, 128, GEMM_SMEM>>>(bo, outp);
}

// round 12
// speedup vs baseline: 1.6708x; 1.1076x over previous
#include <cuda_runtime.h>
#include <cuda_fp16.h>
#include <math.h>
#include <stdint.h>

// Problem constants
#define B_    64
#define S_    200
#define H_    16
#define DK_   64
#define DM_   1024
#define MROWS (B_ * S_)          // 12800
#define BH_   (B_ * H_)          // 1024
#define OUT_N  ((size_t)MROWS * DM_)       // 13107200
#define ATTN_N ((size_t)BH_ * S_ * S_)     // 40960000
#define XN    (MROWS * DM_)                // 13107200
#define WN    (DM_ * DM_)                  // 1048576

// Scratch (allocation-free rule: __device__ globals)
__device__ __half g_xhi[XN];
__device__ __half g_xlo[XN];
__device__ __half g_whi[4][WN];
__device__ __half g_Qhi[BH_ * S_ * DK_];
__device__ __half g_Qlo[BH_ * S_ * DK_];
__device__ __half g_Khi[BH_ * S_ * DK_];
__device__ __half g_Vhi[BH_ * S_ * DK_];
__device__ __half g_ctxhi[MROWS * DM_];
__device__ __half g_ctxlo[MROWS * DM_];
__device__ float g_attn_fb[BH_ * S_ * S_];
__device__ float g_out_fb[MROWS * DM_];

// ===========================================================================
// Helpers
// ===========================================================================
__device__ __forceinline__ uint32_t smem_to_u32(const void* p) {
    uint32_t a;
    asm("{ .reg .u64 t; cvta.to.shared.u64 t, %1; cvt.u32.u64 %0, t; }"
        : "=r"(a) : "l"(p));
    return a;
}

__device__ __forceinline__ void ldsm_x4(uint32_t& r0, uint32_t& r1,
                                        uint32_t& r2, uint32_t& r3, uint32_t addr) {
    asm volatile("ldmatrix.sync.aligned.m8n8.x4.shared.b16 {%0,%1,%2,%3}, [%4];"
                 : "=r"(r0), "=r"(r1), "=r"(r2), "=r"(r3) : "r"(addr));
}
__device__ __forceinline__ void ldsm_x4_t(uint32_t& r0, uint32_t& r1,
                                          uint32_t& r2, uint32_t& r3, uint32_t addr) {
    asm volatile("ldmatrix.sync.aligned.m8n8.x4.trans.shared.b16 {%0,%1,%2,%3}, [%4];"
                 : "=r"(r0), "=r"(r1), "=r"(r2), "=r"(r3) : "r"(addr));
}

__device__ __forceinline__ void mma_fp16(float* d, const uint32_t* a, const uint32_t* b) {
    asm volatile(
        "mma.sync.aligned.m16n8k16.row.col.f32.f16.f16.f32 "
        "{%0,%1,%2,%3}, {%4,%5,%6,%7}, {%8,%9}, {%0,%1,%2,%3};"
        : "+f"(d[0]), "+f"(d[1]), "+f"(d[2]), "+f"(d[3])
        : "r"(a[0]), "r"(a[1]), "r"(a[2]), "r"(a[3]), "r"(b[0]), "r"(b[1]));
}

#define STS128(addr, r0, r1, r2, r3) \
    asm volatile("st.shared.v4.b32 [%0], {%1,%2,%3,%4};" \
        :: "r"(addr), "r"(r0), "r"(r1), "r"(r2), "r"(r3) : "memory")

#define CP_ASYNC16(sm, gp) \
    asm volatile("{ .reg .u64 g; cvta.to.global.u64 g, %1; " \
                 "cp.async.cg.shared.global [%0], [g], 16; }" \
                 :: "r"(sm), "l"(gp) : "memory")
#define CP_COMMIT() asm volatile("cp.async.commit_group;" ::: "memory")
#define CP_WAIT0()  asm volatile("cp.async.wait_group 0;" ::: "memory")
#define CP_WAIT1()  asm volatile("cp.async.wait_group 1;" ::: "memory")

// hi/lo fp16 split of a float pair, packed as 2x uint32 (half2)
__device__ __forceinline__ void split2h(float x, float y, uint32_t& hi, uint32_t& lo) {
    __half2 h = __floats2half2_rn(x, y);
    float rx = x - __half2float(__low2half(h));
    float ry = y - __half2float(__high2half(h));
    __half2 l = __floats2half2_rn(rx, ry);
    hi = *(uint32_t*)&h;
    lo = *(uint32_t*)&l;
}
__device__ __forceinline__ uint32_t cvt2h(float x, float y) {
    __half2 h = __floats2half2_rn(x, y);
    return *(uint32_t*)&h;
}

// 64B-row swizzle (gemm): 4 chunks of 16B; chunk ^= (row>>1)&3
__device__ __forceinline__ uint32_t swz(int row, int chunk) {
    return (uint32_t)(row * 64 + ((chunk ^ ((row >> 1) & 3)) << 4));
}
// 128B-row swizzle (attention): 8 chunks of 16B; chunk ^= row&7
__device__ __forceinline__ uint32_t swz128(int row, int chunk) {
    return (uint32_t)(row * 128 + ((chunk ^ (row & 7)) << 4));
}

// ===========================================================================
// Combined split kernel: x (hi/lo) + 4 weight matrices (hi only), one launch
// ===========================================================================
__global__ void __launch_bounds__(256) split_all(
    const float* __restrict__ x,
    const float* __restrict__ wq, const float* __restrict__ wk,
    const float* __restrict__ wv, const float* __restrict__ wo)
{
    size_t i = ((size_t)blockIdx.x * 256 + threadIdx.x) * 8;
    if (i < (size_t)XN) {
        float4 v0 = *(const float4*)(x + i);
        float4 v1 = *(const float4*)(x + i + 4);
        uint32_t h[4], l[4];
        split2h(v0.x, v0.y, h[0], l[0]); split2h(v0.z, v0.w, h[1], l[1]);
        split2h(v1.x, v1.y, h[2], l[2]); split2h(v1.z, v1.w, h[3], l[3]);
        *(uint4*)(g_xhi + i) = make_uint4(h[0], h[1], h[2], h[3]);
        *(uint4*)(g_xlo + i) = make_uint4(l[0], l[1], l[2], l[3]);
    } else {
        size_t j = i - XN;
        int wsel = (int)(j >> 20);            // WN = 2^20
        size_t off = j & (WN - 1);
        const float* ws[4] = {wq, wk, wv, wo};
        const float* src = ws[wsel];
        float4 v0 = *(const float4*)(src + off);
        float4 v1 = *(const float4*)(src + off + 4);
        uint4 out;
        out.x = cvt2h(v0.x, v0.y); out.y = cvt2h(v0.z, v0.w);
        out.z = cvt2h(v1.x, v1.y); out.w = cvt2h(v1.z, v1.w);
        *(uint4*)(g_whi[wsel] + off) = out;
    }
}

// ===========================================================================
// GEMM core: CTA 64(M) x 128(N), 128 threads, warp grid 2m x 2n, warp tile
// 32x64. K-chunk 32, 2-stage cp.async, 32KB smem, 4 CTAs/SM.
// fp16 2-pass: acc = (Ahi+Alo)@Whi^T.
// ===========================================================================
#define STG_SZ     16384u
#define ST_AHI(s)  ((uint32_t)(s) * STG_SZ + 0u)
#define ST_ALO(s)  ((uint32_t)(s) * STG_SZ + 4096u)
#define ST_BHI(s)  ((uint32_t)(s) * STG_SZ + 8192u)
#define GEMM_SMEM  32768

struct GemmCore {
    uint32_t sb;
    int tid, lane, wm, wn;
    int m0, n0;
    const __half *Ahi, *Alo, *Whi;
    float acc[2][8][4];

    __device__ __forceinline__ void issue_stage(int st, int kt) {
        const int r = tid >> 1;               // 0..63
        const int cc = (tid & 1) << 1;        // 0 or 2
        const uint32_t s0 = swz(r, cc), s1 = swz(r, cc + 1);
        const uint32_t s2 = swz(r + 64, cc), s3 = swz(r + 64, cc + 1);
        size_t ka = (size_t)kt * 32 + cc * 8;
        const __half* p = Ahi + (size_t)(m0 + r) * DM_ + ka;
        CP_ASYNC16(sb + ST_AHI(st) + s0, p);
        CP_ASYNC16(sb + ST_AHI(st) + s1, p + 8);
        p = Alo + (size_t)(m0 + r) * DM_ + ka;
        CP_ASYNC16(sb + ST_ALO(st) + s0, p);
        CP_ASYNC16(sb + ST_ALO(st) + s1, p + 8);
        p = Whi + (size_t)(n0 + r) * DM_ + ka;
        CP_ASYNC16(sb + ST_BHI(st) + s0, p);
        CP_ASYNC16(sb + ST_BHI(st) + s1, p + 8);
        p = Whi + (size_t)(n0 + r + 64) * DM_ + ka;
        CP_ASYNC16(sb + ST_BHI(st) + s2, p);
        CP_ASYNC16(sb + ST_BHI(st) + s3, p + 8);
    }

    __device__ __forceinline__ void run() {
#pragma unroll
        for (int i = 0; i < 2; i++)
#pragma unroll
            for (int j = 0; j < 8; j++)
#pragma unroll
                for (int r = 0; r < 4; r++) acc[i][j][r] = 0.f;

        issue_stage(0, 0);
        CP_COMMIT();

        const int a_row_in = lane & 15;
        const int a_kh     = lane >> 4;
        const int b_col_in = (lane & 7) + ((lane >> 4) << 3);
        const int b_kh     = (lane >> 3) & 1;

        for (int kt = 0; kt < 32; kt++) {
            const int cur = kt & 1;
            if (kt < 31) {
                issue_stage(cur ^ 1, kt + 1);
                CP_COMMIT();
                CP_WAIT1();
            } else {
                CP_WAIT0();
            }
            __syncthreads();

            const uint32_t ahiB = sb + ST_AHI(cur), aloB = sb + ST_ALO(cur);
            const uint32_t bhiB = sb + ST_BHI(cur);

#pragma unroll
            for (int ks = 0; ks < 2; ks++) {
                uint32_t ahi[2][4], alo[2][4];
#pragma unroll
                for (int mf = 0; mf < 2; mf++) {
                    int row = wm * 32 + mf * 16 + a_row_in;
                    int ch  = ks * 2 + a_kh;
                    uint32_t so = swz(row, ch);
                    ldsm_x4(ahi[mf][0], ahi[mf][1], ahi[mf][2], ahi[mf][3], ahiB + so);
                    ldsm_x4(alo[mf][0], alo[mf][1], alo[mf][2], alo[mf][3], aloB + so);
                }
                uint32_t bhi[8][2];
#pragma unroll
                for (int bi = 0; bi < 4; bi++) {
                    int col = wn * 64 + bi * 16 + b_col_in;
                    int ch  = ks * 2 + b_kh;
                    uint32_t so = swz(col, ch);
                    uint32_t r0, r1, r2, r3;
                    ldsm_x4(r0, r1, r2, r3, bhiB + so);
                    bhi[bi * 2][0] = r0; bhi[bi * 2][1] = r1;
                    bhi[bi * 2 + 1][0] = r2; bhi[bi * 2 + 1][1] = r3;
                }
#pragma unroll
                for (int mf = 0; mf < 2; mf++)
#pragma unroll
                    for (int nf = 0; nf < 8; nf++) {
                        mma_fp16(acc[mf][nf], ahi[mf], bhi[nf]);
                        mma_fp16(acc[mf][nf], alo[mf], bhi[nf]);
                    }
            }
            __syncthreads();
        }
    }
};

// QKV GEMM: grid (8, 200, 3). z=0: Q (split hi/lo), z=1: K (hi), z=2: V (hi)
__global__ void __launch_bounds__(128, 4) gemm_qkv(
    const float* __restrict__ bq, const float* __restrict__ bk,
    const float* __restrict__ bv)
{
    extern __shared__ char smem[];
    GemmCore gc;
    gc.sb   = smem_to_u32(smem);
    gc.tid  = threadIdx.x;
    gc.lane = gc.tid & 31;
    gc.wm   = (gc.tid >> 5) >> 1;
    gc.wn   = (gc.tid >> 5) & 1;
    gc.m0   = blockIdx.y * 64;
    gc.n0   = blockIdx.x * 128;
    const int z = blockIdx.z;
    gc.Ahi = g_xhi;  gc.Alo = g_xlo;  gc.Whi = g_whi[z];
    const float* bias = (z == 0) ? bq : (z == 1) ? bk : bv;
    __half* Chi = (z == 0) ? g_Qhi : (z == 1) ? g_Khi : g_Vhi;

    gc.run();

    const int g  = gc.lane >> 2;
    const int c2 = (gc.lane & 3) * 2;
#pragma unroll
    for (int nf = 0; nf < 8; nf++) {
        const int n = gc.n0 + gc.wn * 64 + nf * 8 + c2;
        const float b0 = bias[n], b1 = bias[n + 1];
        const int hh = n >> 6;
        const int dk = n & 63;
#pragma unroll
        for (int mf = 0; mf < 2; mf++) {
            const int m = gc.m0 + gc.wm * 32 + mf * 16 + g;
            float v00 = gc.acc[mf][nf][0] + b0, v01 = gc.acc[mf][nf][1] + b1;
            float v10 = gc.acc[mf][nf][2] + b0, v11 = gc.acc[mf][nf][3] + b1;
            int bb = m / S_;
            int ss = m - bb * S_;
            size_t off0 = (((size_t)bb * H_ + hh) * S_ + ss) * DK_ + dk;
            int m2 = m + 8;
            int bb2 = m2 / S_;
            int ss2 = m2 - bb2 * S_;
            size_t off1 = (((size_t)bb2 * H_ + hh) * S_ + ss2) * DK_ + dk;
            if (z == 0) {
                uint32_t hi0, lo0, hi1, lo1;
                split2h(v00, v01, hi0, lo0);
                split2h(v10, v11, hi1, lo1);
                *(uint32_t*)(g_Qhi + off0) = hi0;
                *(uint32_t*)(g_Qlo + off0) = lo0;
                *(uint32_t*)(g_Qhi + off1) = hi1;
                *(uint32_t*)(g_Qlo + off1) = lo1;
            } else {
                *(uint32_t*)(Chi + off0) = cvt2h(v00, v01);
                *(uint32_t*)(Chi + off1) = cvt2h(v10, v11);
            }
        }
    }
}

// Output GEMM: ctx (fp16 hi/lo) @ wo^T + bo -> fp32 row-major
__global__ void __launch_bounds__(128, 4) gemm_out(
    const float* __restrict__ bias, float* __restrict__ Cf)
{
    extern __shared__ char smem[];
    GemmCore gc;
    gc.sb   = smem_to_u32(smem);
    gc.tid  = threadIdx.x;
    gc.lane = gc.tid & 31;
    gc.wm   = (gc.tid >> 5) >> 1;
    gc.wn   = (gc.tid >> 5) & 1;
    gc.m0   = blockIdx.y * 64;
    gc.n0   = blockIdx.x * 128;
    gc.Ahi = g_ctxhi;  gc.Alo = g_ctxlo;  gc.Whi = g_whi[3];

    gc.run();

    const int g  = gc.lane >> 2;
    const int c2 = (gc.lane & 3) * 2;
#pragma unroll
    for (int nf = 0; nf < 8; nf++) {
        const int n = gc.n0 + gc.wn * 64 + nf * 8 + c2;
        const float b0 = bias[n], b1 = bias[n + 1];
#pragma unroll
        for (int mf = 0; mf < 2; mf++) {
            const int m = gc.m0 + gc.wm * 32 + mf * 16 + g;
            *(float2*)(Cf + (size_t)m * DM_ + n) =
                make_float2(gc.acc[mf][nf][0] + b0, gc.acc[mf][nf][1] + b1);
            *(float2*)(Cf + (size_t)(m + 8) * DM_ + n) =
                make_float2(gc.acc[mf][nf][2] + b0, gc.acc[mf][nf][3] + b1);
        }
    }
}

// ===========================================================================
// Fused attention: CTA = (64 q-rows, bh). 128 threads, 3 CTAs/SM.
// K/V single fp16 in smem; Q hi/lo from gmem; 2-pass MMAs.
// ===========================================================================
#define FK_HI   0u
#define FV_HI   26624u
#define FA_SMEM 53248

__global__ void __launch_bounds__(128, 3) attn_fused(
    const int* __restrict__ mask, float* __restrict__ attn)
{
    extern __shared__ char smem[];
    const uint32_t sb = smem_to_u32(smem);
    const int tid  = threadIdx.x;
    const int lane = tid & 31;
    const int w    = tid >> 5;
    const int qt   = blockIdx.x;          // 0..3
    const int bh   = blockIdx.y;
    const int b    = bh >> 4;

    const __half* Khi = g_Khi + (size_t)bh * S_ * DK_;
    const __half* Vhi = g_Vhi + (size_t)bh * S_ * DK_;
    const __half* Qhi = g_Qhi + (size_t)bh * S_ * DK_;
    const __half* Qlo = g_Qlo + (size_t)bh * S_ * DK_;

    for (int c = tid; c < 1600; c += 128) {
        int r = c >> 3, cc = c & 7;
        uint32_t so = swz128(r, cc);
        size_t go = (size_t)r * DK_ + cc * 8;
        CP_ASYNC16(sb + FK_HI + so, Khi + go);
        CP_ASYNC16(sb + FV_HI + so, Vhi + go);
    }
    CP_COMMIT();
    if (tid < 64) {
        int r = 200 + (tid >> 3), cc = tid & 7;
        uint32_t so = swz128(r, cc);
        STS128(sb + FK_HI + so, 0u, 0u, 0u, 0u);
        STS128(sb + FV_HI + so, 0u, 0u, 0u, 0u);
    }
    CP_WAIT0();
    __syncthreads();

    float acc[25][4];
#pragma unroll
    for (int f = 0; f < 25; f++)
#pragma unroll
        for (int r = 0; r < 4; r++) acc[f][r] = 0.f;

    const int g  = lane >> 2;
    const int c2 = (lane & 3) * 2;
    const int b_col_in = (lane & 7) + ((lane >> 4) << 3);
    const int b_kh     = (lane >> 3) & 1;

    const int qr0 = qt * 64 + w * 16 + g;
    const int qr1 = qr0 + 8;
    const size_t qo0 = (size_t)min(qr0, S_ - 1) * DK_;
    const size_t qo1 = (size_t)min(qr1, S_ - 1) * DK_;

    for (int kb = 0; kb < 4; kb++) {
        const int col = kb * 16 + c2;
        uint32_t ahi[4], alo[4];
        ahi[0] = *(const uint32_t*)(Qhi + qo0 + col);
        ahi[1] = *(const uint32_t*)(Qhi + qo1 + col);
        ahi[2] = *(const uint32_t*)(Qhi + qo0 + col + 8);
        ahi[3] = *(const uint32_t*)(Qhi + qo1 + col + 8);
        alo[0] = *(const uint32_t*)(Qlo + qo0 + col);
        alo[1] = *(const uint32_t*)(Qlo + qo1 + col);
        alo[2] = *(const uint32_t*)(Qlo + qo0 + col + 8);
        alo[3] = *(const uint32_t*)(Qlo + qo1 + col + 8);
#pragma unroll
        for (int nb = 0; nb < 13; nb++) {
            int row = nb * 16 + b_col_in;
            int ch  = kb * 2 + b_kh;
            uint32_t so = swz128(row, ch);
            uint32_t h0, h1, h2, h3;
            ldsm_x4(h0, h1, h2, h3, sb + FK_HI + so);
            uint32_t bh0[2] = {h0, h1};
            mma_fp16(acc[nb * 2], ahi, bh0);
            mma_fp16(acc[nb * 2], alo, bh0);
            if (nb < 12) {
                uint32_t bh1[2] = {h2, h3};
                mma_fp16(acc[nb * 2 + 1], ahi, bh1);
                mma_fp16(acc[nb * 2 + 1], alo, bh1);
            }
        }
    }

    const int gi0 = qr0;
    const int gi1 = qr1;
    const bool v0ok = (gi0 < S_);
    const bool v1ok = (gi1 < S_);
    const int* mrow0 = mask + (size_t)b * S_ * S_ + (size_t)gi0 * S_;
    const int* mrow1 = mask + (size_t)b * S_ * S_ + (size_t)gi1 * S_;
    const float BC = -0.1f / 200.0f;

    float mx0 = -1e30f, mx1 = -1e30f;
#pragma unroll
    for (int f = 0; f < 25; f++) {
        int gj = f * 8 + c2;
        int2 m0v = v0ok ? *(const int2*)(mrow0 + gj) : make_int2(1, 1);
        int2 m1v = v1ok ? *(const int2*)(mrow1 + gj) : make_int2(1, 1);
        float t00 = BC * fabsf((float)(gi0 - gj));
        float t01 = BC * fabsf((float)(gi0 - gj - 1));
        float t10 = BC * fabsf((float)(gi1 - gj));
        float t11 = BC * fabsf((float)(gi1 - gj - 1));
        acc[f][0] = (m0v.x == 0) ? -1e9f : fmaf(acc[f][0], 0.125f, t00);
        acc[f][1] = (m0v.y == 0) ? -1e9f : fmaf(acc[f][1], 0.125f, t01);
        acc[f][2] = (m1v.x == 0) ? -1e9f : fmaf(acc[f][2], 0.125f, t10);
        acc[f][3] = (m1v.y == 0) ? -1e9f : fmaf(acc[f][3], 0.125f, t11);
        mx0 = fmaxf(mx0, fmaxf(acc[f][0], acc[f][1]));
        mx1 = fmaxf(mx1, fmaxf(acc[f][2], acc[f][3]));
    }
    mx0 = fmaxf(mx0, __shfl_xor_sync(0xffffffffu, mx0, 1));
    mx0 = fmaxf(mx0, __shfl_xor_sync(0xffffffffu, mx0, 2));
    mx1 = fmaxf(mx1, __shfl_xor_sync(0xffffffffu, mx1, 1));
    mx1 = fmaxf(mx1, __shfl_xor_sync(0xffffffffu, mx1, 2));

    float s0 = 0.f, s1 = 0.f;
#pragma unroll
    for (int f = 0; f < 25; f++) {
        acc[f][0] = expf(acc[f][0] - mx0);
        acc[f][1] = expf(acc[f][1] - mx0);
        acc[f][2] = expf(acc[f][2] - mx1);
        acc[f][3] = expf(acc[f][3] - mx1);
        s0 += acc[f][0] + acc[f][1];
        s1 += acc[f][2] + acc[f][3];
    }
    s0 += __shfl_xor_sync(0xffffffffu, s0, 1);
    s0 += __shfl_xor_sync(0xffffffffu, s0, 2);
    s1 += __shfl_xor_sync(0xffffffffu, s1, 1);
    s1 += __shfl_xor_sync(0xffffffffu, s1, 2);
    const float i0 = 1.f / s0;
    const float i1 = 1.f / s1;

    float* arow0 = attn + (size_t)bh * S_ * S_ + (size_t)gi0 * S_;
    float* arow1 = attn + (size_t)bh * S_ * S_ + (size_t)gi1 * S_;
#pragma unroll
    for (int f = 0; f < 25; f++) {
        int gj = f * 8 + c2;
        acc[f][0] *= i0; acc[f][1] *= i0;
        acc[f][2] *= i1; acc[f][3] *= i1;
        if (v0ok) *(float2*)(arow0 + gj) = make_float2(acc[f][0], acc[f][1]);
        if (v1ok) *(float2*)(arow1 + gj) = make_float2(acc[f][2], acc[f][3]);
    }

    float cacc[8][4];
#pragma unroll
    for (int nf = 0; nf < 8; nf++)
#pragma unroll
        for (int r = 0; r < 4; r++) cacc[nf][r] = 0.f;

#pragma unroll
    for (int kf = 0; kf < 13; kf++) {
        uint32_t ahi[4], alo[4];
        split2h(acc[2 * kf][0], acc[2 * kf][1], ahi[0], alo[0]);
        split2h(acc[2 * kf][2], acc[2 * kf][3], ahi[1], alo[1]);
        if (kf < 12) {
            split2h(acc[2 * kf + 1][0], acc[2 * kf + 1][1], ahi[2], alo[2]);
            split2h(acc[2 * kf + 1][2], acc[2 * kf + 1][3], ahi[3], alo[3]);
        } else {
            ahi[2] = alo[2] = ahi[3] = alo[3] = 0u;
        }
#pragma unroll
        for (int nb = 0; nb < 4; nb++) {
            int row = kf * 16 + (lane & 15);
            int ch  = nb * 2 + (lane >> 4);
            uint32_t so = swz128(row, ch);
            uint32_t h0, h1, h2, h3;
            ldsm_x4_t(h0, h1, h2, h3, sb + FV_HI + so);
            uint32_t bh0[2] = {h0, h1};
            uint32_t bh1[2] = {h2, h3};
            mma_fp16(cacc[nb * 2], ahi, bh0);
            mma_fp16(cacc[nb * 2], alo, bh0);
            mma_fp16(cacc[nb * 2 + 1], ahi, bh1);
            mma_fp16(cacc[nb * 2 + 1], alo, bh1);
        }
    }

    const int h = bh & 15;
    __half* chi0 = g_ctxhi + ((size_t)b * S_ + gi0) * DM_ + h * DK_;
    __half* clo0 = g_ctxlo + ((size_t)b * S_ + gi0) * DM_ + h * DK_;
    __half* chi1 = g_ctxhi + ((size_t)b * S_ + gi1) * DM_ + h * DK_;
    __half* clo1 = g_ctxlo + ((size_t)b * S_ + gi1) * DM_ + h * DK_;
#pragma unroll
    for (int nf = 0; nf < 8; nf++) {
        int n = nf * 8 + c2;
        uint32_t hi0, lo0, hi1, lo1;
        split2h(cacc[nf][0], cacc[nf][1], hi0, lo0);
        split2h(cacc[nf][2], cacc[nf][3], hi1, lo1);
        if (v0ok) { *(uint32_t*)(chi0 + n) = hi0; *(uint32_t*)(clo0 + n) = lo0; }
        if (v1ok) { *(uint32_t*)(chi1 + n) = hi1; *(uint32_t*)(clo1 + n) = lo1; }
    }
}

// ---------------------------------------------------------------------------
extern "C" void kernel_launch(void* const* d_in, const int* in_sizes, int n_in,
                              void* d_out, int out_size)
{
    const float* x    = (const float*)d_in[0];
    const int*   mask = (const int*)  d_in[1];
    const float* wq   = (const float*)d_in[2];
    const float* bq   = (const float*)d_in[3];
    const float* wk   = (const float*)d_in[4];
    const float* bk   = (const float*)d_in[5];
    const float* wv   = (const float*)d_in[6];
    const float* bv   = (const float*)d_in[7];
    const float* wo   = (const float*)d_in[8];
    const float* bo   = (const float*)d_in[9];

    void *pAttnFb, *pOutFb;
    cudaGetSymbolAddress(&pAttnFb, g_attn_fb);
    cudaGetSymbolAddress(&pOutFb, g_out_fb);

    float* outp;
    float* attnp;
    size_t osz = (size_t)out_size;
    if (osz >= OUT_N + ATTN_N) {
        outp  = (float*)d_out;
        attnp = (float*)d_out + OUT_N;
    } else if (osz == ATTN_N) {
        attnp = (float*)d_out;
        outp  = (float*)pOutFb;
    } else {
        outp  = (float*)d_out;
        attnp = (float*)pAttnFb;
    }

    cudaFuncSetAttribute(gemm_qkv, cudaFuncAttributeMaxDynamicSharedMemorySize, GEMM_SMEM);
    cudaFuncSetAttribute(gemm_out, cudaFuncAttributeMaxDynamicSharedMemorySize, GEMM_SMEM);
    cudaFuncSetAttribute(attn_fused, cudaFuncAttributeMaxDynamicSharedMemorySize, FA_SMEM);

    const size_t total = (size_t)XN + 4 * (size_t)WN;   // 17301504
    split_all<<<(unsigned)(total / 2048), 256>>>(x, wq, wk, wv, wo);

    dim3 gQKV(DM_ / 128, MROWS / 64, 3);   // (8, 200, 3)
    gemm_qkv<<<gQKV, 128, GEMM_SMEM>>>(bq, bk, bv);

    dim3 gFA(4, BH_);
    attn_fused<<<gFA, 128, FA_SMEM>>>(mask, attnp);

    dim3 gOut(DM_ / 128, MROWS / 64);      // (8, 200)
    gemm_out<<<gOut, 128, GEMM_SMEM>>>(bo, outp);
}

// round 13
// speedup vs baseline: 1.8345x; 1.0980x over previous
#include <cuda_runtime.h>
#include <cuda_fp16.h>
#include <math.h>
#include <stdint.h>

// Problem constants
#define B_    64
#define S_    200
#define H_    16
#define DK_   64
#define DM_   1024
#define MROWS (B_ * S_)          // 12800
#define BH_   (B_ * H_)          // 1024
#define OUT_N  ((size_t)MROWS * DM_)       // 13107200
#define ATTN_N ((size_t)BH_ * S_ * S_)     // 40960000
#define XN    (MROWS * DM_)                // 13107200
#define WN    (DM_ * DM_)                  // 1048576

// Scratch (allocation-free rule: __device__ globals)
__device__ __half g_xhi[XN];
__device__ __half g_xlo[XN];
__device__ __half g_whi[4][WN];
__device__ __half g_Qhi[BH_ * S_ * DK_];
__device__ __half g_Qlo[BH_ * S_ * DK_];
__device__ __half g_Khi[BH_ * S_ * DK_];
__device__ __half g_Vhi[BH_ * S_ * DK_];
__device__ __half g_ctxhi[MROWS * DM_];
__device__ __half g_ctxlo[MROWS * DM_];
__device__ float g_attn_fb[BH_ * S_ * S_];
__device__ float g_out_fb[MROWS * DM_];

// ===========================================================================
// Helpers
// ===========================================================================
__device__ __forceinline__ uint32_t smem_to_u32(const void* p) {
    uint32_t a;
    asm("{ .reg .u64 t; cvta.to.shared.u64 t, %1; cvt.u32.u64 %0, t; }"
        : "=r"(a) : "l"(p));
    return a;
}

__device__ __forceinline__ void ldsm_x4(uint32_t& r0, uint32_t& r1,
                                        uint32_t& r2, uint32_t& r3, uint32_t addr) {
    asm volatile("ldmatrix.sync.aligned.m8n8.x4.shared.b16 {%0,%1,%2,%3}, [%4];"
                 : "=r"(r0), "=r"(r1), "=r"(r2), "=r"(r3) : "r"(addr));
}
__device__ __forceinline__ void ldsm_x4_t(uint32_t& r0, uint32_t& r1,
                                          uint32_t& r2, uint32_t& r3, uint32_t addr) {
    asm volatile("ldmatrix.sync.aligned.m8n8.x4.trans.shared.b16 {%0,%1,%2,%3}, [%4];"
                 : "=r"(r0), "=r"(r1), "=r"(r2), "=r"(r3) : "r"(addr));
}

__device__ __forceinline__ void mma_fp16(float* d, const uint32_t* a, const uint32_t* b) {
    asm volatile(
        "mma.sync.aligned.m16n8k16.row.col.f32.f16.f16.f32 "
        "{%0,%1,%2,%3}, {%4,%5,%6,%7}, {%8,%9}, {%0,%1,%2,%3};"
        : "+f"(d[0]), "+f"(d[1]), "+f"(d[2]), "+f"(d[3])
        : "r"(a[0]), "r"(a[1]), "r"(a[2]), "r"(a[3]), "r"(b[0]), "r"(b[1]));
}

#define STS128(addr, r0, r1, r2, r3) \
    asm volatile("st.shared.v4.b32 [%0], {%1,%2,%3,%4};" \
        :: "r"(addr), "r"(r0), "r"(r1), "r"(r2), "r"(r3) : "memory")

#define CP_ASYNC16(sm, gp) \
    asm volatile("{ .reg .u64 g; cvta.to.global.u64 g, %1; " \
                 "cp.async.cg.shared.global [%0], [g], 16; }" \
                 :: "r"(sm), "l"(gp) : "memory")
#define CP_COMMIT() asm volatile("cp.async.commit_group;" ::: "memory")
#define CP_WAIT0()  asm volatile("cp.async.wait_group 0;" ::: "memory")
#define CP_WAIT1()  asm volatile("cp.async.wait_group 1;" ::: "memory")

// hi/lo fp16 split of a float pair, packed as 2x uint32 (half2)
__device__ __forceinline__ void split2h(float x, float y, uint32_t& hi, uint32_t& lo) {
    __half2 h = __floats2half2_rn(x, y);
    float rx = x - __half2float(__low2half(h));
    float ry = y - __half2float(__high2half(h));
    __half2 l = __floats2half2_rn(rx, ry);
    hi = *(uint32_t*)&h;
    lo = *(uint32_t*)&l;
}
__device__ __forceinline__ uint32_t cvt2h(float x, float y) {
    __half2 h = __floats2half2_rn(x, y);
    return *(uint32_t*)&h;
}

// 64B-row swizzle (gemm): 4 chunks of 16B; chunk ^= (row>>1)&3
__device__ __forceinline__ uint32_t swz(int row, int chunk) {
    return (uint32_t)(row * 64 + ((chunk ^ ((row >> 1) & 3)) << 4));
}
// 128B-row swizzle (attention): 8 chunks of 16B; chunk ^= row&7
__device__ __forceinline__ uint32_t swz128(int row, int chunk) {
    return (uint32_t)(row * 128 + ((chunk ^ (row & 7)) << 4));
}

// ===========================================================================
// Combined split kernel: x (hi/lo) + 4 weight matrices (hi only), one launch
// ===========================================================================
__global__ void __launch_bounds__(256) split_all(
    const float* __restrict__ x,
    const float* __restrict__ wq, const float* __restrict__ wk,
    const float* __restrict__ wv, const float* __restrict__ wo)
{
    size_t i = ((size_t)blockIdx.x * 256 + threadIdx.x) * 8;
    if (i < (size_t)XN) {
        float4 v0 = *(const float4*)(x + i);
        float4 v1 = *(const float4*)(x + i + 4);
        uint32_t h[4], l[4];
        split2h(v0.x, v0.y, h[0], l[0]); split2h(v0.z, v0.w, h[1], l[1]);
        split2h(v1.x, v1.y, h[2], l[2]); split2h(v1.z, v1.w, h[3], l[3]);
        *(uint4*)(g_xhi + i) = make_uint4(h[0], h[1], h[2], h[3]);
        *(uint4*)(g_xlo + i) = make_uint4(l[0], l[1], l[2], l[3]);
    } else {
        size_t j = i - XN;
        int wsel = (int)(j >> 20);            // WN = 2^20
        size_t off = j & (WN - 1);
        const float* ws[4] = {wq, wk, wv, wo};
        const float* src = ws[wsel];
        float4 v0 = *(const float4*)(src + off);
        float4 v1 = *(const float4*)(src + off + 4);
        uint4 out;
        out.x = cvt2h(v0.x, v0.y); out.y = cvt2h(v0.z, v0.w);
        out.z = cvt2h(v1.x, v1.y); out.w = cvt2h(v1.z, v1.w);
        *(uint4*)(g_whi[wsel] + off) = out;
    }
}

// ===========================================================================
// GEMM core: CTA 64(M) x 128(N), 128 threads, warp grid 2m x 2n (32x64 tile),
// K-chunk 32, 2-stage cp.async, 32KB smem, 4 CTAs/SM.
// TP=1: acc = (Ahi+Alo)@Whi^T (2-pass). TP=0: acc = Ahi@Whi^T (1-pass).
// ===========================================================================
#define STG_SZ     16384u
#define ST_AHI(s)  ((uint32_t)(s) * STG_SZ + 0u)
#define ST_ALO(s)  ((uint32_t)(s) * STG_SZ + 4096u)
#define ST_BHI(s)  ((uint32_t)(s) * STG_SZ + 8192u)
#define GEMM_SMEM  32768

template <int TP>
struct GemmCore {
    uint32_t sb;
    int tid, lane, wm, wn;
    int m0, n0;
    const __half *Ahi, *Alo, *Whi;
    float acc[2][8][4];

    __device__ __forceinline__ void issue_stage(int st, int kt) {
        const int r = tid >> 1;               // 0..63
        const int cc = (tid & 1) << 1;        // 0 or 2
        const uint32_t s0 = swz(r, cc), s1 = swz(r, cc + 1);
        const uint32_t s2 = swz(r + 64, cc), s3 = swz(r + 64, cc + 1);
        size_t ka = (size_t)kt * 32 + cc * 8;
        const __half* p = Ahi + (size_t)(m0 + r) * DM_ + ka;
        CP_ASYNC16(sb + ST_AHI(st) + s0, p);
        CP_ASYNC16(sb + ST_AHI(st) + s1, p + 8);
        if (TP) {
            p = Alo + (size_t)(m0 + r) * DM_ + ka;
            CP_ASYNC16(sb + ST_ALO(st) + s0, p);
            CP_ASYNC16(sb + ST_ALO(st) + s1, p + 8);
        }
        p = Whi + (size_t)(n0 + r) * DM_ + ka;
        CP_ASYNC16(sb + ST_BHI(st) + s0, p);
        CP_ASYNC16(sb + ST_BHI(st) + s1, p + 8);
        p = Whi + (size_t)(n0 + r + 64) * DM_ + ka;
        CP_ASYNC16(sb + ST_BHI(st) + s2, p);
        CP_ASYNC16(sb + ST_BHI(st) + s3, p + 8);
    }

    __device__ __forceinline__ void run() {
#pragma unroll
        for (int i = 0; i < 2; i++)
#pragma unroll
            for (int j = 0; j < 8; j++)
#pragma unroll
                for (int r = 0; r < 4; r++) acc[i][j][r] = 0.f;

        issue_stage(0, 0);
        CP_COMMIT();

        const int a_row_in = lane & 15;
        const int a_kh     = lane >> 4;
        const int b_col_in = (lane & 7) + ((lane >> 4) << 3);
        const int b_kh     = (lane >> 3) & 1;

        for (int kt = 0; kt < 32; kt++) {
            const int cur = kt & 1;
            if (kt < 31) {
                issue_stage(cur ^ 1, kt + 1);
                CP_COMMIT();
                CP_WAIT1();
            } else {
                CP_WAIT0();
            }
            __syncthreads();

            const uint32_t ahiB = sb + ST_AHI(cur), aloB = sb + ST_ALO(cur);
            const uint32_t bhiB = sb + ST_BHI(cur);

#pragma unroll
            for (int ks = 0; ks < 2; ks++) {
                uint32_t ahi[2][4], alo[2][4];
#pragma unroll
                for (int mf = 0; mf < 2; mf++) {
                    int row = wm * 32 + mf * 16 + a_row_in;
                    int ch  = ks * 2 + a_kh;
                    uint32_t so = swz(row, ch);
                    ldsm_x4(ahi[mf][0], ahi[mf][1], ahi[mf][2], ahi[mf][3], ahiB + so);
                    if (TP)
                        ldsm_x4(alo[mf][0], alo[mf][1], alo[mf][2], alo[mf][3], aloB + so);
                }
                uint32_t bhi[8][2];
#pragma unroll
                for (int bi = 0; bi < 4; bi++) {
                    int col = wn * 64 + bi * 16 + b_col_in;
                    int ch  = ks * 2 + b_kh;
                    uint32_t so = swz(col, ch);
                    uint32_t r0, r1, r2, r3;
                    ldsm_x4(r0, r1, r2, r3, bhiB + so);
                    bhi[bi * 2][0] = r0; bhi[bi * 2][1] = r1;
                    bhi[bi * 2 + 1][0] = r2; bhi[bi * 2 + 1][1] = r3;
                }
#pragma unroll
                for (int mf = 0; mf < 2; mf++)
#pragma unroll
                    for (int nf = 0; nf < 8; nf++) {
                        mma_fp16(acc[mf][nf], ahi[mf], bhi[nf]);
                        if (TP) mma_fp16(acc[mf][nf], alo[mf], bhi[nf]);
                    }
            }
            __syncthreads();
        }
    }
};

// Q GEMM (2-pass): grid (8, 200). Writes Qhi/Qlo split.
__global__ void __launch_bounds__(128, 4) gemm_q(const float* __restrict__ bq)
{
    extern __shared__ char smem[];
    GemmCore<1> gc;
    gc.sb   = smem_to_u32(smem);
    gc.tid  = threadIdx.x;
    gc.lane = gc.tid & 31;
    gc.wm   = (gc.tid >> 5) >> 1;
    gc.wn   = (gc.tid >> 5) & 1;
    gc.m0   = blockIdx.y * 64;
    gc.n0   = blockIdx.x * 128;
    gc.Ahi = g_xhi;  gc.Alo = g_xlo;  gc.Whi = g_whi[0];

    gc.run();

    const int g  = gc.lane >> 2;
    const int c2 = (gc.lane & 3) * 2;
#pragma unroll
    for (int nf = 0; nf < 8; nf++) {
        const int n = gc.n0 + gc.wn * 64 + nf * 8 + c2;
        const float b0 = bq[n], b1 = bq[n + 1];
        const int hh = n >> 6;
        const int dk = n & 63;
#pragma unroll
        for (int mf = 0; mf < 2; mf++) {
            const int m = gc.m0 + gc.wm * 32 + mf * 16 + g;
            float v00 = gc.acc[mf][nf][0] + b0, v01 = gc.acc[mf][nf][1] + b1;
            float v10 = gc.acc[mf][nf][2] + b0, v11 = gc.acc[mf][nf][3] + b1;
            int bb = m / S_;
            int ss = m - bb * S_;
            size_t off0 = (((size_t)bb * H_ + hh) * S_ + ss) * DK_ + dk;
            int m2 = m + 8;
            int bb2 = m2 / S_;
            int ss2 = m2 - bb2 * S_;
            size_t off1 = (((size_t)bb2 * H_ + hh) * S_ + ss2) * DK_ + dk;
            uint32_t hi0, lo0, hi1, lo1;
            split2h(v00, v01, hi0, lo0);
            split2h(v10, v11, hi1, lo1);
            *(uint32_t*)(g_Qhi + off0) = hi0;
            *(uint32_t*)(g_Qlo + off0) = lo0;
            *(uint32_t*)(g_Qhi + off1) = hi1;
            *(uint32_t*)(g_Qlo + off1) = lo1;
        }
    }
}

// K/V GEMM (1-pass): grid (8, 200, 2). z=0: K, z=1: V. Writes hi only.
__global__ void __launch_bounds__(128, 4) gemm_kv(
    const float* __restrict__ bk, const float* __restrict__ bv)
{
    extern __shared__ char smem[];
    GemmCore<0> gc;
    gc.sb   = smem_to_u32(smem);
    gc.tid  = threadIdx.x;
    gc.lane = gc.tid & 31;
    gc.wm   = (gc.tid >> 5) >> 1;
    gc.wn   = (gc.tid >> 5) & 1;
    gc.m0   = blockIdx.y * 64;
    gc.n0   = blockIdx.x * 128;
    const int z = blockIdx.z;
    gc.Ahi = g_xhi;  gc.Alo = nullptr;  gc.Whi = g_whi[1 + z];
    const float* bias = (z == 0) ? bk : bv;
    __half* Chi = (z == 0) ? g_Khi : g_Vhi;

    gc.run();

    const int g  = gc.lane >> 2;
    const int c2 = (gc.lane & 3) * 2;
#pragma unroll
    for (int nf = 0; nf < 8; nf++) {
        const int n = gc.n0 + gc.wn * 64 + nf * 8 + c2;
        const float b0 = bias[n], b1 = bias[n + 1];
        const int hh = n >> 6;
        const int dk = n & 63;
#pragma unroll
        for (int mf = 0; mf < 2; mf++) {
            const int m = gc.m0 + gc.wm * 32 + mf * 16 + g;
            float v00 = gc.acc[mf][nf][0] + b0, v01 = gc.acc[mf][nf][1] + b1;
            float v10 = gc.acc[mf][nf][2] + b0, v11 = gc.acc[mf][nf][3] + b1;
            int bb = m / S_;
            int ss = m - bb * S_;
            size_t off0 = (((size_t)bb * H_ + hh) * S_ + ss) * DK_ + dk;
            int m2 = m + 8;
            int bb2 = m2 / S_;
            int ss2 = m2 - bb2 * S_;
            size_t off1 = (((size_t)bb2 * H_ + hh) * S_ + ss2) * DK_ + dk;
            *(uint32_t*)(Chi + off0) = cvt2h(v00, v01);
            *(uint32_t*)(Chi + off1) = cvt2h(v10, v11);
        }
    }
}

// Output GEMM (2-pass): ctx (fp16 hi/lo) @ wo^T + bo -> fp32 row-major
__global__ void __launch_bounds__(128, 4) gemm_out(
    const float* __restrict__ bias, float* __restrict__ Cf)
{
    extern __shared__ char smem[];
    GemmCore<1> gc;
    gc.sb   = smem_to_u32(smem);
    gc.tid  = threadIdx.x;
    gc.lane = gc.tid & 31;
    gc.wm   = (gc.tid >> 5) >> 1;
    gc.wn   = (gc.tid >> 5) & 1;
    gc.m0   = blockIdx.y * 64;
    gc.n0   = blockIdx.x * 128;
    gc.Ahi = g_ctxhi;  gc.Alo = g_ctxlo;  gc.Whi = g_whi[3];

    gc.run();

    const int g  = gc.lane >> 2;
    const int c2 = (gc.lane & 3) * 2;
#pragma unroll
    for (int nf = 0; nf < 8; nf++) {
        const int n = gc.n0 + gc.wn * 64 + nf * 8 + c2;
        const float b0 = bias[n], b1 = bias[n + 1];
#pragma unroll
        for (int mf = 0; mf < 2; mf++) {
            const int m = gc.m0 + gc.wm * 32 + mf * 16 + g;
            *(float2*)(Cf + (size_t)m * DM_ + n) =
                make_float2(gc.acc[mf][nf][0] + b0, gc.acc[mf][nf][1] + b1);
            *(float2*)(Cf + (size_t)(m + 8) * DM_ + n) =
                make_float2(gc.acc[mf][nf][2] + b0, gc.acc[mf][nf][3] + b1);
        }
    }
}

// ===========================================================================
// Fused attention: CTA = (64 q-rows, bh). 128 threads, 3 CTAs/SM.
// K/V single fp16 in smem; Q hi/lo from gmem; 2-pass MMAs.
// ===========================================================================
#define FK_HI   0u
#define FV_HI   26624u
#define FA_SMEM 53248

__global__ void __launch_bounds__(128, 3) attn_fused(
    const int* __restrict__ mask, float* __restrict__ attn)
{
    extern __shared__ char smem[];
    const uint32_t sb = smem_to_u32(smem);
    const int tid  = threadIdx.x;
    const int lane = tid & 31;
    const int w    = tid >> 5;
    const int qt   = blockIdx.x;          // 0..3
    const int bh   = blockIdx.y;
    const int b    = bh >> 4;

    const __half* Khi = g_Khi + (size_t)bh * S_ * DK_;
    const __half* Vhi = g_Vhi + (size_t)bh * S_ * DK_;
    const __half* Qhi = g_Qhi + (size_t)bh * S_ * DK_;
    const __half* Qlo = g_Qlo + (size_t)bh * S_ * DK_;

    for (int c = tid; c < 1600; c += 128) {
        int r = c >> 3, cc = c & 7;
        uint32_t so = swz128(r, cc);
        size_t go = (size_t)r * DK_ + cc * 8;
        CP_ASYNC16(sb + FK_HI + so, Khi + go);
        CP_ASYNC16(sb + FV_HI + so, Vhi + go);
    }
    CP_COMMIT();
    if (tid < 64) {
        int r = 200 + (tid >> 3), cc = tid & 7;
        uint32_t so = swz128(r, cc);
        STS128(sb + FK_HI + so, 0u, 0u, 0u, 0u);
        STS128(sb + FV_HI + so, 0u, 0u, 0u, 0u);
    }
    CP_WAIT0();
    __syncthreads();

    float acc[25][4];
#pragma unroll
    for (int f = 0; f < 25; f++)
#pragma unroll
        for (int r = 0; r < 4; r++) acc[f][r] = 0.f;

    const int g  = lane >> 2;
    const int c2 = (lane & 3) * 2;
    const int b_col_in = (lane & 7) + ((lane >> 4) << 3);
    const int b_kh     = (lane >> 3) & 1;

    const int qr0 = qt * 64 + w * 16 + g;
    const int qr1 = qr0 + 8;
    const size_t qo0 = (size_t)min(qr0, S_ - 1) * DK_;
    const size_t qo1 = (size_t)min(qr1, S_ - 1) * DK_;

    for (int kb = 0; kb < 4; kb++) {
        const int col = kb * 16 + c2;
        uint32_t ahi[4], alo[4];
        ahi[0] = *(const uint32_t*)(Qhi + qo0 + col);
        ahi[1] = *(const uint32_t*)(Qhi + qo1 + col);
        ahi[2] = *(const uint32_t*)(Qhi + qo0 + col + 8);
        ahi[3] = *(const uint32_t*)(Qhi + qo1 + col + 8);
        alo[0] = *(const uint32_t*)(Qlo + qo0 + col);
        alo[1] = *(const uint32_t*)(Qlo + qo1 + col);
        alo[2] = *(const uint32_t*)(Qlo + qo0 + col + 8);
        alo[3] = *(const uint32_t*)(Qlo + qo1 + col + 8);
#pragma unroll
        for (int nb = 0; nb < 13; nb++) {
            int row = nb * 16 + b_col_in;
            int ch  = kb * 2 + b_kh;
            uint32_t so = swz128(row, ch);
            uint32_t h0, h1, h2, h3;
            ldsm_x4(h0, h1, h2, h3, sb + FK_HI + so);
            uint32_t bh0[2] = {h0, h1};
            mma_fp16(acc[nb * 2], ahi, bh0);
            mma_fp16(acc[nb * 2], alo, bh0);
            if (nb < 12) {
                uint32_t bh1[2] = {h2, h3};
                mma_fp16(acc[nb * 2 + 1], ahi, bh1);
                mma_fp16(acc[nb * 2 + 1], alo, bh1);
            }
        }
    }

    const int gi0 = qr0;
    const int gi1 = qr1;
    const bool v0ok = (gi0 < S_);
    const bool v1ok = (gi1 < S_);
    const int* mrow0 = mask + (size_t)b * S_ * S_ + (size_t)gi0 * S_;
    const int* mrow1 = mask + (size_t)b * S_ * S_ + (size_t)gi1 * S_;
    const float BC = -0.1f / 200.0f;

    float mx0 = -1e30f, mx1 = -1e30f;
#pragma unroll
    for (int f = 0; f < 25; f++) {
        int gj = f * 8 + c2;
        int2 m0v = v0ok ? *(const int2*)(mrow0 + gj) : make_int2(1, 1);
        int2 m1v = v1ok ? *(const int2*)(mrow1 + gj) : make_int2(1, 1);
        float t00 = BC * fabsf((float)(gi0 - gj));
        float t01 = BC * fabsf((float)(gi0 - gj - 1));
        float t10 = BC * fabsf((float)(gi1 - gj));
        float t11 = BC * fabsf((float)(gi1 - gj - 1));
        acc[f][0] = (m0v.x == 0) ? -1e9f : fmaf(acc[f][0], 0.125f, t00);
        acc[f][1] = (m0v.y == 0) ? -1e9f : fmaf(acc[f][1], 0.125f, t01);
        acc[f][2] = (m1v.x == 0) ? -1e9f : fmaf(acc[f][2], 0.125f, t10);
        acc[f][3] = (m1v.y == 0) ? -1e9f : fmaf(acc[f][3], 0.125f, t11);
        mx0 = fmaxf(mx0, fmaxf(acc[f][0], acc[f][1]));
        mx1 = fmaxf(mx1, fmaxf(acc[f][2], acc[f][3]));
    }
    mx0 = fmaxf(mx0, __shfl_xor_sync(0xffffffffu, mx0, 1));
    mx0 = fmaxf(mx0, __shfl_xor_sync(0xffffffffu, mx0, 2));
    mx1 = fmaxf(mx1, __shfl_xor_sync(0xffffffffu, mx1, 1));
    mx1 = fmaxf(mx1, __shfl_xor_sync(0xffffffffu, mx1, 2));

    float s0 = 0.f, s1 = 0.f;
#pragma unroll
    for (int f = 0; f < 25; f++) {
        acc[f][0] = expf(acc[f][0] - mx0);
        acc[f][1] = expf(acc[f][1] - mx0);
        acc[f][2] = expf(acc[f][2] - mx1);
        acc[f][3] = expf(acc[f][3] - mx1);
        s0 += acc[f][0] + acc[f][1];
        s1 += acc[f][2] + acc[f][3];
    }
    s0 += __shfl_xor_sync(0xffffffffu, s0, 1);
    s0 += __shfl_xor_sync(0xffffffffu, s0, 2);
    s1 += __shfl_xor_sync(0xffffffffu, s1, 1);
    s1 += __shfl_xor_sync(0xffffffffu, s1, 2);
    const float i0 = 1.f / s0;
    const float i1 = 1.f / s1;

    float* arow0 = attn + (size_t)bh * S_ * S_ + (size_t)gi0 * S_;
    float* arow1 = attn + (size_t)bh * S_ * S_ + (size_t)gi1 * S_;
#pragma unroll
    for (int f = 0; f < 25; f++) {
        int gj = f * 8 + c2;
        acc[f][0] *= i0; acc[f][1] *= i0;
        acc[f][2] *= i1; acc[f][3] *= i1;
        if (v0ok) *(float2*)(arow0 + gj) = make_float2(acc[f][0], acc[f][1]);
        if (v1ok) *(float2*)(arow1 + gj) = make_float2(acc[f][2], acc[f][3]);
    }

    float cacc[8][4];
#pragma unroll
    for (int nf = 0; nf < 8; nf++)
#pragma unroll
        for (int r = 0; r < 4; r++) cacc[nf][r] = 0.f;

#pragma unroll
    for (int kf = 0; kf < 13; kf++) {
        uint32_t ahi[4], alo[4];
        split2h(acc[2 * kf][0], acc[2 * kf][1], ahi[0], alo[0]);
        split2h(acc[2 * kf][2], acc[2 * kf][3], ahi[1], alo[1]);
        if (kf < 12) {
            split2h(acc[2 * kf + 1][0], acc[2 * kf + 1][1], ahi[2], alo[2]);
            split2h(acc[2 * kf + 1][2], acc[2 * kf + 1][3], ahi[3], alo[3]);
        } else {
            ahi[2] = alo[2] = ahi[3] = alo[3] = 0u;
        }
#pragma unroll
        for (int nb = 0; nb < 4; nb++) {
            int row = kf * 16 + (lane & 15);
            int ch  = nb * 2 + (lane >> 4);
            uint32_t so = swz128(row, ch);
            uint32_t h0, h1, h2, h3;
            ldsm_x4_t(h0, h1, h2, h3, sb + FV_HI + so);
            uint32_t bh0[2] = {h0, h1};
            uint32_t bh1[2] = {h2, h3};
            mma_fp16(cacc[nb * 2], ahi, bh0);
            mma_fp16(cacc[nb * 2], alo, bh0);
            mma_fp16(cacc[nb * 2 + 1], ahi, bh1);
            mma_fp16(cacc[nb * 2 + 1], alo, bh1);
        }
    }

    const int h = bh & 15;
    __half* chi0 = g_ctxhi + ((size_t)b * S_ + gi0) * DM_ + h * DK_;
    __half* clo0 = g_ctxlo + ((size_t)b * S_ + gi0) * DM_ + h * DK_;
    __half* chi1 = g_ctxhi + ((size_t)b * S_ + gi1) * DM_ + h * DK_;
    __half* clo1 = g_ctxlo + ((size_t)b * S_ + gi1) * DM_ + h * DK_;
#pragma unroll
    for (int nf = 0; nf < 8; nf++) {
        int n = nf * 8 + c2;
        uint32_t hi0, lo0, hi1, lo1;
        split2h(cacc[nf][0], cacc[nf][1], hi0, lo0);
        split2h(cacc[nf][2], cacc[nf][3], hi1, lo1);
        if (v0ok) { *(uint32_t*)(chi0 + n) = hi0; *(uint32_t*)(clo0 + n) = lo0; }
        if (v1ok) { *(uint32_t*)(chi1 + n) = hi1; *(uint32_t*)(clo1 + n) = lo1; }
    }
}

// ---------------------------------------------------------------------------
extern "C" void kernel_launch(void* const* d_in, const int* in_sizes, int n_in,
                              void* d_out, int out_size)
{
    const float* x    = (const float*)d_in[0];
    const int*   mask = (const int*)  d_in[1];
    const float* wq   = (const float*)d_in[2];
    const float* bq   = (const float*)d_in[3];
    const float* wk   = (const float*)d_in[4];
    const float* bk   = (const float*)d_in[5];
    const float* wv   = (const float*)d_in[6];
    const float* bv   = (const float*)d_in[7];
    const float* wo   = (const float*)d_in[8];
    const float* bo   = (const float*)d_in[9];

    void *pAttnFb, *pOutFb;
    cudaGetSymbolAddress(&pAttnFb, g_attn_fb);
    cudaGetSymbolAddress(&pOutFb, g_out_fb);

    float* outp;
    float* attnp;
    size_t osz = (size_t)out_size;
    if (osz >= OUT_N + ATTN_N) {
        outp  = (float*)d_out;
        attnp = (float*)d_out + OUT_N;
    } else if (osz == ATTN_N) {
        attnp = (float*)d_out;
        outp  = (float*)pOutFb;
    } else {
        outp  = (float*)d_out;
        attnp = (float*)pAttnFb;
    }

    cudaFuncSetAttribute(gemm_q,   cudaFuncAttributeMaxDynamicSharedMemorySize, GEMM_SMEM);
    cudaFuncSetAttribute(gemm_kv,  cudaFuncAttributeMaxDynamicSharedMemorySize, GEMM_SMEM);
    cudaFuncSetAttribute(gemm_out, cudaFuncAttributeMaxDynamicSharedMemorySize, GEMM_SMEM);
    cudaFuncSetAttribute(attn_fused, cudaFuncAttributeMaxDynamicSharedMemorySize, FA_SMEM);

    const size_t total = (size_t)XN + 4 * (size_t)WN;   // 17301504
    split_all<<<(unsigned)(total / 2048), 256>>>(x, wq, wk, wv, wo);

    dim3 gQ(DM_ / 128, MROWS / 64);        // (8, 200)
    gemm_q<<<gQ, 128, GEMM_SMEM>>>(bq);
    dim3 gKV(DM_ / 128, MROWS / 64, 2);    // (8, 200, 2)
    gemm_kv<<<gKV, 128, GEMM_SMEM>>>(bk, bv);

    dim3 gFA(4, BH_);
    attn_fused<<<gFA, 128, FA_SMEM>>>(mask, attnp);

    dim3 gOut(DM_ / 128, MROWS / 64);      // (8, 200)
    gemm_out<<<gOut, 128, GEMM_SMEM>>>(bo, outp);
}

// round 14
// speedup vs baseline: 2.0036x; 1.0922x over previous
#include <cuda_runtime.h>
#include <cuda_fp16.h>
#include <math.h>
#include <stdint.h>

// Problem constants
#define B_    64
#define S_    200
#define H_    16
#define DK_   64
#define DM_   1024
#define MROWS (B_ * S_)          // 12800
#define BH_   (B_ * H_)          // 1024
#define OUT_N  ((size_t)MROWS * DM_)       // 13107200
#define ATTN_N ((size_t)BH_ * S_ * S_)     // 40960000
#define XN    (MROWS * DM_)                // 13107200
#define WN    (DM_ * DM_)                  // 1048576

// Scratch (allocation-free rule: __device__ globals)
__device__ __half g_xhi[XN];
__device__ __half g_xlo[XN];
__device__ __half g_whi[4][WN];
__device__ __half g_Qhi[BH_ * S_ * DK_];
__device__ __half g_Qlo[BH_ * S_ * DK_];
__device__ __half g_Khi[BH_ * S_ * DK_];
__device__ __half g_Vhi[BH_ * S_ * DK_];
__device__ __half g_ctxhi[MROWS * DM_];
__device__ float g_attn_fb[BH_ * S_ * S_];
__device__ float g_out_fb[MROWS * DM_];

// ===========================================================================
// Helpers
// ===========================================================================
__device__ __forceinline__ uint32_t smem_to_u32(const void* p) {
    uint32_t a;
    asm("{ .reg .u64 t; cvta.to.shared.u64 t, %1; cvt.u32.u64 %0, t; }"
        : "=r"(a) : "l"(p));
    return a;
}

__device__ __forceinline__ void ldsm_x4(uint32_t& r0, uint32_t& r1,
                                        uint32_t& r2, uint32_t& r3, uint32_t addr) {
    asm volatile("ldmatrix.sync.aligned.m8n8.x4.shared.b16 {%0,%1,%2,%3}, [%4];"
                 : "=r"(r0), "=r"(r1), "=r"(r2), "=r"(r3) : "r"(addr));
}
__device__ __forceinline__ void ldsm_x4_t(uint32_t& r0, uint32_t& r1,
                                          uint32_t& r2, uint32_t& r3, uint32_t addr) {
    asm volatile("ldmatrix.sync.aligned.m8n8.x4.trans.shared.b16 {%0,%1,%2,%3}, [%4];"
                 : "=r"(r0), "=r"(r1), "=r"(r2), "=r"(r3) : "r"(addr));
}

__device__ __forceinline__ void mma_fp16(float* d, const uint32_t* a, const uint32_t* b) {
    asm volatile(
        "mma.sync.aligned.m16n8k16.row.col.f32.f16.f16.f32 "
        "{%0,%1,%2,%3}, {%4,%5,%6,%7}, {%8,%9}, {%0,%1,%2,%3};"
        : "+f"(d[0]), "+f"(d[1]), "+f"(d[2]), "+f"(d[3])
        : "r"(a[0]), "r"(a[1]), "r"(a[2]), "r"(a[3]), "r"(b[0]), "r"(b[1]));
}

#define STS128(addr, r0, r1, r2, r3) \
    asm volatile("st.shared.v4.b32 [%0], {%1,%2,%3,%4};" \
        :: "r"(addr), "r"(r0), "r"(r1), "r"(r2), "r"(r3) : "memory")

#define CP_ASYNC16(sm, gp) \
    asm volatile("{ .reg .u64 g; cvta.to.global.u64 g, %1; " \
                 "cp.async.cg.shared.global [%0], [g], 16; }" \
                 :: "r"(sm), "l"(gp) : "memory")
#define CP_COMMIT() asm volatile("cp.async.commit_group;" ::: "memory")
#define CP_WAIT0()  asm volatile("cp.async.wait_group 0;" ::: "memory")
#define CP_WAIT1()  asm volatile("cp.async.wait_group 1;" ::: "memory")

// hi/lo fp16 split of a float pair, packed as 2x uint32 (half2)
__device__ __forceinline__ void split2h(float x, float y, uint32_t& hi, uint32_t& lo) {
    __half2 h = __floats2half2_rn(x, y);
    float rx = x - __half2float(__low2half(h));
    float ry = y - __half2float(__high2half(h));
    __half2 l = __floats2half2_rn(rx, ry);
    hi = *(uint32_t*)&h;
    lo = *(uint32_t*)&l;
}
__device__ __forceinline__ uint32_t cvt2h(float x, float y) {
    __half2 h = __floats2half2_rn(x, y);
    return *(uint32_t*)&h;
}

// 64B-row swizzle (gemm): 4 chunks of 16B; chunk ^= (row>>1)&3
__device__ __forceinline__ uint32_t swz(int row, int chunk) {
    return (uint32_t)(row * 64 + ((chunk ^ ((row >> 1) & 3)) << 4));
}
// 128B-row swizzle (attention): 8 chunks of 16B; chunk ^= row&7
__device__ __forceinline__ uint32_t swz128(int row, int chunk) {
    return (uint32_t)(row * 128 + ((chunk ^ (row & 7)) << 4));
}

// ===========================================================================
// Combined split kernel: x (hi/lo) + 4 weight matrices (hi only), one launch
// ===========================================================================
__global__ void __launch_bounds__(256) split_all(
    const float* __restrict__ x,
    const float* __restrict__ wq, const float* __restrict__ wk,
    const float* __restrict__ wv, const float* __restrict__ wo)
{
    size_t i = ((size_t)blockIdx.x * 256 + threadIdx.x) * 8;
    if (i < (size_t)XN) {
        float4 v0 = *(const float4*)(x + i);
        float4 v1 = *(const float4*)(x + i + 4);
        uint32_t h[4], l[4];
        split2h(v0.x, v0.y, h[0], l[0]); split2h(v0.z, v0.w, h[1], l[1]);
        split2h(v1.x, v1.y, h[2], l[2]); split2h(v1.z, v1.w, h[3], l[3]);
        *(uint4*)(g_xhi + i) = make_uint4(h[0], h[1], h[2], h[3]);
        *(uint4*)(g_xlo + i) = make_uint4(l[0], l[1], l[2], l[3]);
    } else {
        size_t j = i - XN;
        int wsel = (int)(j >> 20);            // WN = 2^20
        size_t off = j & (WN - 1);
        const float* ws[4] = {wq, wk, wv, wo};
        const float* src = ws[wsel];
        float4 v0 = *(const float4*)(src + off);
        float4 v1 = *(const float4*)(src + off + 4);
        uint4 out;
        out.x = cvt2h(v0.x, v0.y); out.y = cvt2h(v0.z, v0.w);
        out.z = cvt2h(v1.x, v1.y); out.w = cvt2h(v1.z, v1.w);
        *(uint4*)(g_whi[wsel] + off) = out;
    }
}

// ===========================================================================
// GEMM core: CTA 64(M) x 128(N), 128 threads, warp grid 2m x 2n (32x64 tile),
// K-chunk 32, 2-stage cp.async, 32KB smem, 4 CTAs/SM.
// TP=1: acc = (Ahi+Alo)@Whi^T (2-pass). TP=0: acc = Ahi@Whi^T (1-pass).
// ===========================================================================
#define STG_SZ     16384u
#define ST_AHI(s)  ((uint32_t)(s) * STG_SZ + 0u)
#define ST_ALO(s)  ((uint32_t)(s) * STG_SZ + 4096u)
#define ST_BHI(s)  ((uint32_t)(s) * STG_SZ + 8192u)
#define GEMM_SMEM  32768

template <int TP>
struct GemmCore {
    uint32_t sb;
    int tid, lane, wm, wn;
    int m0, n0;
    const __half *Ahi, *Alo, *Whi;
    float acc[2][8][4];

    __device__ __forceinline__ void issue_stage(int st, int kt) {
        const int r = tid >> 1;               // 0..63
        const int cc = (tid & 1) << 1;        // 0 or 2
        const uint32_t s0 = swz(r, cc), s1 = swz(r, cc + 1);
        const uint32_t s2 = swz(r + 64, cc), s3 = swz(r + 64, cc + 1);
        size_t ka = (size_t)kt * 32 + cc * 8;
        const __half* p = Ahi + (size_t)(m0 + r) * DM_ + ka;
        CP_ASYNC16(sb + ST_AHI(st) + s0, p);
        CP_ASYNC16(sb + ST_AHI(st) + s1, p + 8);
        if (TP) {
            p = Alo + (size_t)(m0 + r) * DM_ + ka;
            CP_ASYNC16(sb + ST_ALO(st) + s0, p);
            CP_ASYNC16(sb + ST_ALO(st) + s1, p + 8);
        }
        p = Whi + (size_t)(n0 + r) * DM_ + ka;
        CP_ASYNC16(sb + ST_BHI(st) + s0, p);
        CP_ASYNC16(sb + ST_BHI(st) + s1, p + 8);
        p = Whi + (size_t)(n0 + r + 64) * DM_ + ka;
        CP_ASYNC16(sb + ST_BHI(st) + s2, p);
        CP_ASYNC16(sb + ST_BHI(st) + s3, p + 8);
    }

    __device__ __forceinline__ void run() {
#pragma unroll
        for (int i = 0; i < 2; i++)
#pragma unroll
            for (int j = 0; j < 8; j++)
#pragma unroll
                for (int r = 0; r < 4; r++) acc[i][j][r] = 0.f;

        issue_stage(0, 0);
        CP_COMMIT();

        const int a_row_in = lane & 15;
        const int a_kh     = lane >> 4;
        const int b_col_in = (lane & 7) + ((lane >> 4) << 3);
        const int b_kh     = (lane >> 3) & 1;

        for (int kt = 0; kt < 32; kt++) {
            const int cur = kt & 1;
            if (kt < 31) {
                issue_stage(cur ^ 1, kt + 1);
                CP_COMMIT();
                CP_WAIT1();
            } else {
                CP_WAIT0();
            }
            __syncthreads();

            const uint32_t ahiB = sb + ST_AHI(cur), aloB = sb + ST_ALO(cur);
            const uint32_t bhiB = sb + ST_BHI(cur);

#pragma unroll
            for (int ks = 0; ks < 2; ks++) {
                uint32_t ahi[2][4], alo[2][4];
#pragma unroll
                for (int mf = 0; mf < 2; mf++) {
                    int row = wm * 32 + mf * 16 + a_row_in;
                    int ch  = ks * 2 + a_kh;
                    uint32_t so = swz(row, ch);
                    ldsm_x4(ahi[mf][0], ahi[mf][1], ahi[mf][2], ahi[mf][3], ahiB + so);
                    if (TP)
                        ldsm_x4(alo[mf][0], alo[mf][1], alo[mf][2], alo[mf][3], aloB + so);
                }
                uint32_t bhi[8][2];
#pragma unroll
                for (int bi = 0; bi < 4; bi++) {
                    int col = wn * 64 + bi * 16 + b_col_in;
                    int ch  = ks * 2 + b_kh;
                    uint32_t so = swz(col, ch);
                    uint32_t r0, r1, r2, r3;
                    ldsm_x4(r0, r1, r2, r3, bhiB + so);
                    bhi[bi * 2][0] = r0; bhi[bi * 2][1] = r1;
                    bhi[bi * 2 + 1][0] = r2; bhi[bi * 2 + 1][1] = r3;
                }
#pragma unroll
                for (int mf = 0; mf < 2; mf++)
#pragma unroll
                    for (int nf = 0; nf < 8; nf++) {
                        mma_fp16(acc[mf][nf], ahi[mf], bhi[nf]);
                        if (TP) mma_fp16(acc[mf][nf], alo[mf], bhi[nf]);
                    }
            }
            __syncthreads();
        }
    }
};

// Q GEMM (2-pass): grid (8, 200). Writes Qhi/Qlo split.
__global__ void __launch_bounds__(128, 4) gemm_q(const float* __restrict__ bq)
{
    extern __shared__ char smem[];
    GemmCore<1> gc;
    gc.sb   = smem_to_u32(smem);
    gc.tid  = threadIdx.x;
    gc.lane = gc.tid & 31;
    gc.wm   = (gc.tid >> 5) >> 1;
    gc.wn   = (gc.tid >> 5) & 1;
    gc.m0   = blockIdx.y * 64;
    gc.n0   = blockIdx.x * 128;
    gc.Ahi = g_xhi;  gc.Alo = g_xlo;  gc.Whi = g_whi[0];

    gc.run();

    const int g  = gc.lane >> 2;
    const int c2 = (gc.lane & 3) * 2;
#pragma unroll
    for (int nf = 0; nf < 8; nf++) {
        const int n = gc.n0 + gc.wn * 64 + nf * 8 + c2;
        const float b0 = bq[n], b1 = bq[n + 1];
        const int hh = n >> 6;
        const int dk = n & 63;
#pragma unroll
        for (int mf = 0; mf < 2; mf++) {
            const int m = gc.m0 + gc.wm * 32 + mf * 16 + g;
            float v00 = gc.acc[mf][nf][0] + b0, v01 = gc.acc[mf][nf][1] + b1;
            float v10 = gc.acc[mf][nf][2] + b0, v11 = gc.acc[mf][nf][3] + b1;
            int bb = m / S_;
            int ss = m - bb * S_;
            size_t off0 = (((size_t)bb * H_ + hh) * S_ + ss) * DK_ + dk;
            int m2 = m + 8;
            int bb2 = m2 / S_;
            int ss2 = m2 - bb2 * S_;
            size_t off1 = (((size_t)bb2 * H_ + hh) * S_ + ss2) * DK_ + dk;
            uint32_t hi0, lo0, hi1, lo1;
            split2h(v00, v01, hi0, lo0);
            split2h(v10, v11, hi1, lo1);
            *(uint32_t*)(g_Qhi + off0) = hi0;
            *(uint32_t*)(g_Qlo + off0) = lo0;
            *(uint32_t*)(g_Qhi + off1) = hi1;
            *(uint32_t*)(g_Qlo + off1) = lo1;
        }
    }
}

// K/V GEMM (1-pass): grid (8, 200, 2). z=0: K, z=1: V. Writes hi only.
__global__ void __launch_bounds__(128, 4) gemm_kv(
    const float* __restrict__ bk, const float* __restrict__ bv)
{
    extern __shared__ char smem[];
    GemmCore<0> gc;
    gc.sb   = smem_to_u32(smem);
    gc.tid  = threadIdx.x;
    gc.lane = gc.tid & 31;
    gc.wm   = (gc.tid >> 5) >> 1;
    gc.wn   = (gc.tid >> 5) & 1;
    gc.m0   = blockIdx.y * 64;
    gc.n0   = blockIdx.x * 128;
    const int z = blockIdx.z;
    gc.Ahi = g_xhi;  gc.Alo = nullptr;  gc.Whi = g_whi[1 + z];
    const float* bias = (z == 0) ? bk : bv;
    __half* Chi = (z == 0) ? g_Khi : g_Vhi;

    gc.run();

    const int g  = gc.lane >> 2;
    const int c2 = (gc.lane & 3) * 2;
#pragma unroll
    for (int nf = 0; nf < 8; nf++) {
        const int n = gc.n0 + gc.wn * 64 + nf * 8 + c2;
        const float b0 = bias[n], b1 = bias[n + 1];
        const int hh = n >> 6;
        const int dk = n & 63;
#pragma unroll
        for (int mf = 0; mf < 2; mf++) {
            const int m = gc.m0 + gc.wm * 32 + mf * 16 + g;
            float v00 = gc.acc[mf][nf][0] + b0, v01 = gc.acc[mf][nf][1] + b1;
            float v10 = gc.acc[mf][nf][2] + b0, v11 = gc.acc[mf][nf][3] + b1;
            int bb = m / S_;
            int ss = m - bb * S_;
            size_t off0 = (((size_t)bb * H_ + hh) * S_ + ss) * DK_ + dk;
            int m2 = m + 8;
            int bb2 = m2 / S_;
            int ss2 = m2 - bb2 * S_;
            size_t off1 = (((size_t)bb2 * H_ + hh) * S_ + ss2) * DK_ + dk;
            *(uint32_t*)(Chi + off0) = cvt2h(v00, v01);
            *(uint32_t*)(Chi + off1) = cvt2h(v10, v11);
        }
    }
}

// Output GEMM (1-pass): ctx (fp16) @ wo^T + bo -> fp32 row-major
__global__ void __launch_bounds__(128, 4) gemm_out(
    const float* __restrict__ bias, float* __restrict__ Cf)
{
    extern __shared__ char smem[];
    GemmCore<0> gc;
    gc.sb   = smem_to_u32(smem);
    gc.tid  = threadIdx.x;
    gc.lane = gc.tid & 31;
    gc.wm   = (gc.tid >> 5) >> 1;
    gc.wn   = (gc.tid >> 5) & 1;
    gc.m0   = blockIdx.y * 64;
    gc.n0   = blockIdx.x * 128;
    gc.Ahi = g_ctxhi;  gc.Alo = nullptr;  gc.Whi = g_whi[3];

    gc.run();

    const int g  = gc.lane >> 2;
    const int c2 = (gc.lane & 3) * 2;
#pragma unroll
    for (int nf = 0; nf < 8; nf++) {
        const int n = gc.n0 + gc.wn * 64 + nf * 8 + c2;
        const float b0 = bias[n], b1 = bias[n + 1];
#pragma unroll
        for (int mf = 0; mf < 2; mf++) {
            const int m = gc.m0 + gc.wm * 32 + mf * 16 + g;
            *(float2*)(Cf + (size_t)m * DM_ + n) =
                make_float2(gc.acc[mf][nf][0] + b0, gc.acc[mf][nf][1] + b1);
            *(float2*)(Cf + (size_t)(m + 8) * DM_ + n) =
                make_float2(gc.acc[mf][nf][2] + b0, gc.acc[mf][nf][3] + b1);
        }
    }
}

// ===========================================================================
// Fused attention: CTA = (64 q-rows, bh). 128 threads, 3 CTAs/SM.
// K/V single fp16 in smem; Q hi/lo from gmem (2-pass scores);
// ctx = attn@V 1-pass (attn rounded to fp16 once); ctx stored fp16.
// ===========================================================================
#define FK_HI   0u
#define FV_HI   26624u
#define FA_SMEM 53248

__global__ void __launch_bounds__(128, 3) attn_fused(
    const int* __restrict__ mask, float* __restrict__ attn)
{
    extern __shared__ char smem[];
    const uint32_t sb = smem_to_u32(smem);
    const int tid  = threadIdx.x;
    const int lane = tid & 31;
    const int w    = tid >> 5;
    const int qt   = blockIdx.x;          // 0..3
    const int bh   = blockIdx.y;
    const int b    = bh >> 4;

    const __half* Khi = g_Khi + (size_t)bh * S_ * DK_;
    const __half* Vhi = g_Vhi + (size_t)bh * S_ * DK_;
    const __half* Qhi = g_Qhi + (size_t)bh * S_ * DK_;
    const __half* Qlo = g_Qlo + (size_t)bh * S_ * DK_;

    for (int c = tid; c < 1600; c += 128) {
        int r = c >> 3, cc = c & 7;
        uint32_t so = swz128(r, cc);
        size_t go = (size_t)r * DK_ + cc * 8;
        CP_ASYNC16(sb + FK_HI + so, Khi + go);
        CP_ASYNC16(sb + FV_HI + so, Vhi + go);
    }
    CP_COMMIT();
    if (tid < 64) {
        int r = 200 + (tid >> 3), cc = tid & 7;
        uint32_t so = swz128(r, cc);
        STS128(sb + FK_HI + so, 0u, 0u, 0u, 0u);
        STS128(sb + FV_HI + so, 0u, 0u, 0u, 0u);
    }
    CP_WAIT0();
    __syncthreads();

    float acc[25][4];
#pragma unroll
    for (int f = 0; f < 25; f++)
#pragma unroll
        for (int r = 0; r < 4; r++) acc[f][r] = 0.f;

    const int g  = lane >> 2;
    const int c2 = (lane & 3) * 2;
    const int b_col_in = (lane & 7) + ((lane >> 4) << 3);
    const int b_kh     = (lane >> 3) & 1;

    const int qr0 = qt * 64 + w * 16 + g;
    const int qr1 = qr0 + 8;
    const size_t qo0 = (size_t)min(qr0, S_ - 1) * DK_;
    const size_t qo1 = (size_t)min(qr1, S_ - 1) * DK_;

    for (int kb = 0; kb < 4; kb++) {
        const int col = kb * 16 + c2;
        uint32_t ahi[4], alo[4];
        ahi[0] = *(const uint32_t*)(Qhi + qo0 + col);
        ahi[1] = *(const uint32_t*)(Qhi + qo1 + col);
        ahi[2] = *(const uint32_t*)(Qhi + qo0 + col + 8);
        ahi[3] = *(const uint32_t*)(Qhi + qo1 + col + 8);
        alo[0] = *(const uint32_t*)(Qlo + qo0 + col);
        alo[1] = *(const uint32_t*)(Qlo + qo1 + col);
        alo[2] = *(const uint32_t*)(Qlo + qo0 + col + 8);
        alo[3] = *(const uint32_t*)(Qlo + qo1 + col + 8);
#pragma unroll
        for (int nb = 0; nb < 13; nb++) {
            int row = nb * 16 + b_col_in;
            int ch  = kb * 2 + b_kh;
            uint32_t so = swz128(row, ch);
            uint32_t h0, h1, h2, h3;
            ldsm_x4(h0, h1, h2, h3, sb + FK_HI + so);
            uint32_t bh0[2] = {h0, h1};
            mma_fp16(acc[nb * 2], ahi, bh0);
            mma_fp16(acc[nb * 2], alo, bh0);
            if (nb < 12) {
                uint32_t bh1[2] = {h2, h3};
                mma_fp16(acc[nb * 2 + 1], ahi, bh1);
                mma_fp16(acc[nb * 2 + 1], alo, bh1);
            }
        }
    }

    const int gi0 = qr0;
    const int gi1 = qr1;
    const bool v0ok = (gi0 < S_);
    const bool v1ok = (gi1 < S_);
    const int* mrow0 = mask + (size_t)b * S_ * S_ + (size_t)gi0 * S_;
    const int* mrow1 = mask + (size_t)b * S_ * S_ + (size_t)gi1 * S_;
    const float BC = -0.1f / 200.0f;

    float mx0 = -1e30f, mx1 = -1e30f;
#pragma unroll
    for (int f = 0; f < 25; f++) {
        int gj = f * 8 + c2;
        int2 m0v = v0ok ? *(const int2*)(mrow0 + gj) : make_int2(1, 1);
        int2 m1v = v1ok ? *(const int2*)(mrow1 + gj) : make_int2(1, 1);
        float t00 = BC * fabsf((float)(gi0 - gj));
        float t01 = BC * fabsf((float)(gi0 - gj - 1));
        float t10 = BC * fabsf((float)(gi1 - gj));
        float t11 = BC * fabsf((float)(gi1 - gj - 1));
        acc[f][0] = (m0v.x == 0) ? -1e9f : fmaf(acc[f][0], 0.125f, t00);
        acc[f][1] = (m0v.y == 0) ? -1e9f : fmaf(acc[f][1], 0.125f, t01);
        acc[f][2] = (m1v.x == 0) ? -1e9f : fmaf(acc[f][2], 0.125f, t10);
        acc[f][3] = (m1v.y == 0) ? -1e9f : fmaf(acc[f][3], 0.125f, t11);
        mx0 = fmaxf(mx0, fmaxf(acc[f][0], acc[f][1]));
        mx1 = fmaxf(mx1, fmaxf(acc[f][2], acc[f][3]));
    }
    mx0 = fmaxf(mx0, __shfl_xor_sync(0xffffffffu, mx0, 1));
    mx0 = fmaxf(mx0, __shfl_xor_sync(0xffffffffu, mx0, 2));
    mx1 = fmaxf(mx1, __shfl_xor_sync(0xffffffffu, mx1, 1));
    mx1 = fmaxf(mx1, __shfl_xor_sync(0xffffffffu, mx1, 2));

    float s0 = 0.f, s1 = 0.f;
#pragma unroll
    for (int f = 0; f < 25; f++) {
        acc[f][0] = expf(acc[f][0] - mx0);
        acc[f][1] = expf(acc[f][1] - mx0);
        acc[f][2] = expf(acc[f][2] - mx1);
        acc[f][3] = expf(acc[f][3] - mx1);
        s0 += acc[f][0] + acc[f][1];
        s1 += acc[f][2] + acc[f][3];
    }
    s0 += __shfl_xor_sync(0xffffffffu, s0, 1);
    s0 += __shfl_xor_sync(0xffffffffu, s0, 2);
    s1 += __shfl_xor_sync(0xffffffffu, s1, 1);
    s1 += __shfl_xor_sync(0xffffffffu, s1, 2);
    const float i0 = 1.f / s0;
    const float i1 = 1.f / s1;

    float* arow0 = attn + (size_t)bh * S_ * S_ + (size_t)gi0 * S_;
    float* arow1 = attn + (size_t)bh * S_ * S_ + (size_t)gi1 * S_;
#pragma unroll
    for (int f = 0; f < 25; f++) {
        int gj = f * 8 + c2;
        acc[f][0] *= i0; acc[f][1] *= i0;
        acc[f][2] *= i1; acc[f][3] *= i1;
        if (v0ok) *(float2*)(arow0 + gj) = make_float2(acc[f][0], acc[f][1]);
        if (v1ok) *(float2*)(arow1 + gj) = make_float2(acc[f][2], acc[f][3]);
    }

    // ---- ctx = attn @ V (1-pass; attn rounded to fp16 once) ----
    float cacc[8][4];
#pragma unroll
    for (int nf = 0; nf < 8; nf++)
#pragma unroll
        for (int r = 0; r < 4; r++) cacc[nf][r] = 0.f;

#pragma unroll
    for (int kf = 0; kf < 13; kf++) {
        uint32_t ahi[4];
        ahi[0] = cvt2h(acc[2 * kf][0], acc[2 * kf][1]);
        ahi[1] = cvt2h(acc[2 * kf][2], acc[2 * kf][3]);
        if (kf < 12) {
            ahi[2] = cvt2h(acc[2 * kf + 1][0], acc[2 * kf + 1][1]);
            ahi[3] = cvt2h(acc[2 * kf + 1][2], acc[2 * kf + 1][3]);
        } else {
            ahi[2] = ahi[3] = 0u;
        }
#pragma unroll
        for (int nb = 0; nb < 4; nb++) {
            int row = kf * 16 + (lane & 15);
            int ch  = nb * 2 + (lane >> 4);
            uint32_t so = swz128(row, ch);
            uint32_t h0, h1, h2, h3;
            ldsm_x4_t(h0, h1, h2, h3, sb + FV_HI + so);
            uint32_t bh0[2] = {h0, h1};
            uint32_t bh1[2] = {h2, h3};
            mma_fp16(cacc[nb * 2], ahi, bh0);
            mma_fp16(cacc[nb * 2 + 1], ahi, bh1);
        }
    }

    const int h = bh & 15;
    __half* chi0 = g_ctxhi + ((size_t)b * S_ + gi0) * DM_ + h * DK_;
    __half* chi1 = g_ctxhi + ((size_t)b * S_ + gi1) * DM_ + h * DK_;
#pragma unroll
    for (int nf = 0; nf < 8; nf++) {
        int n = nf * 8 + c2;
        if (v0ok) *(uint32_t*)(chi0 + n) = cvt2h(cacc[nf][0], cacc[nf][1]);
        if (v1ok) *(uint32_t*)(chi1 + n) = cvt2h(cacc[nf][2], cacc[nf][3]);
    }
}

// ---------------------------------------------------------------------------
extern "C" void kernel_launch(void* const* d_in, const int* in_sizes, int n_in,
                              void* d_out, int out_size)
{
    const float* x    = (const float*)d_in[0];
    const int*   mask = (const int*)  d_in[1];
    const float* wq   = (const float*)d_in[2];
    const float* bq   = (const float*)d_in[3];
    const float* wk   = (const float*)d_in[4];
    const float* bk   = (const float*)d_in[5];
    const float* wv   = (const float*)d_in[6];
    const float* bv   = (const float*)d_in[7];
    const float* wo   = (const float*)d_in[8];
    const float* bo   = (const float*)d_in[9];

    void *pAttnFb, *pOutFb;
    cudaGetSymbolAddress(&pAttnFb, g_attn_fb);
    cudaGetSymbolAddress(&pOutFb, g_out_fb);

    float* outp;
    float* attnp;
    size_t osz = (size_t)out_size;
    if (osz >= OUT_N + ATTN_N) {
        outp  = (float*)d_out;
        attnp = (float*)d_out + OUT_N;
    } else if (osz == ATTN_N) {
        attnp = (float*)d_out;
        outp  = (float*)pOutFb;
    } else {
        outp  = (float*)d_out;
        attnp = (float*)pAttnFb;
    }

    cudaFuncSetAttribute(gemm_q,   cudaFuncAttributeMaxDynamicSharedMemorySize, GEMM_SMEM);
    cudaFuncSetAttribute(gemm_kv,  cudaFuncAttributeMaxDynamicSharedMemorySize, GEMM_SMEM);
    cudaFuncSetAttribute(gemm_out, cudaFuncAttributeMaxDynamicSharedMemorySize, GEMM_SMEM);
    cudaFuncSetAttribute(attn_fused, cudaFuncAttributeMaxDynamicSharedMemorySize, FA_SMEM);

    const size_t total = (size_t)XN + 4 * (size_t)WN;   // 17301504
    split_all<<<(unsigned)(total / 2048), 256>>>(x, wq, wk, wv, wo);

    dim3 gQ(DM_ / 128, MROWS / 64);        // (8, 200)
    gemm_q<<<gQ, 128, GEMM_SMEM>>>(bq);
    dim3 gKV(DM_ / 128, MROWS / 64, 2);    // (8, 200, 2)
    gemm_kv<<<gKV, 128, GEMM_SMEM>>>(bk, bv);

    dim3 gFA(4, BH_);
    attn_fused<<<gFA, 128, FA_SMEM>>>(mask, attnp);

    dim3 gOut(DM_ / 128, MROWS / 64);      // (8, 200)
    gemm_out<<<gOut, 128, GEMM_SMEM>>>(bo, outp);
}

// round 15
// speedup vs baseline: 2.2651x; 1.1305x over previous
#include <cuda_runtime.h>
#include <cuda_fp16.h>
#include <math.h>
#include <stdint.h>

// Problem constants
#define B_    64
#define S_    200
#define H_    16
#define DK_   64
#define DM_   1024
#define MROWS (B_ * S_)          // 12800
#define BH_   (B_ * H_)          // 1024
#define OUT_N  ((size_t)MROWS * DM_)       // 13107200
#define ATTN_N ((size_t)BH_ * S_ * S_)     // 40960000
#define XN    (MROWS * DM_)                // 13107200
#define WN    (DM_ * DM_)                  // 1048576

// Scratch (allocation-free rule: __device__ globals)
__device__ __half g_xhi[XN];
__device__ __half g_whi[4][WN];
__device__ __half g_Qhi[BH_ * S_ * DK_];
__device__ __half g_Khi[BH_ * S_ * DK_];
__device__ __half g_Vhi[BH_ * S_ * DK_];
__device__ __half g_ctxhi[MROWS * DM_];
__device__ float g_attn_fb[BH_ * S_ * S_];
__device__ float g_out_fb[MROWS * DM_];

// ===========================================================================
// Helpers
// ===========================================================================
__device__ __forceinline__ uint32_t smem_to_u32(const void* p) {
    uint32_t a;
    asm("{ .reg .u64 t; cvta.to.shared.u64 t, %1; cvt.u32.u64 %0, t; }"
        : "=r"(a) : "l"(p));
    return a;
}

__device__ __forceinline__ void ldsm_x4(uint32_t& r0, uint32_t& r1,
                                        uint32_t& r2, uint32_t& r3, uint32_t addr) {
    asm volatile("ldmatrix.sync.aligned.m8n8.x4.shared.b16 {%0,%1,%2,%3}, [%4];"
                 : "=r"(r0), "=r"(r1), "=r"(r2), "=r"(r3) : "r"(addr));
}
__device__ __forceinline__ void ldsm_x4_t(uint32_t& r0, uint32_t& r1,
                                          uint32_t& r2, uint32_t& r3, uint32_t addr) {
    asm volatile("ldmatrix.sync.aligned.m8n8.x4.trans.shared.b16 {%0,%1,%2,%3}, [%4];"
                 : "=r"(r0), "=r"(r1), "=r"(r2), "=r"(r3) : "r"(addr));
}

__device__ __forceinline__ void mma_fp16(float* d, const uint32_t* a, const uint32_t* b) {
    asm volatile(
        "mma.sync.aligned.m16n8k16.row.col.f32.f16.f16.f32 "
        "{%0,%1,%2,%3}, {%4,%5,%6,%7}, {%8,%9}, {%0,%1,%2,%3};"
        : "+f"(d[0]), "+f"(d[1]), "+f"(d[2]), "+f"(d[3])
        : "r"(a[0]), "r"(a[1]), "r"(a[2]), "r"(a[3]), "r"(b[0]), "r"(b[1]));
}

#define STS128(addr, r0, r1, r2, r3) \
    asm volatile("st.shared.v4.b32 [%0], {%1,%2,%3,%4};" \
        :: "r"(addr), "r"(r0), "r"(r1), "r"(r2), "r"(r3) : "memory")

#define CP_ASYNC16(sm, gp) \
    asm volatile("{ .reg .u64 g; cvta.to.global.u64 g, %1; " \
                 "cp.async.cg.shared.global [%0], [g], 16; }" \
                 :: "r"(sm), "l"(gp) : "memory")
#define CP_COMMIT() asm volatile("cp.async.commit_group;" ::: "memory")
#define CP_WAIT0()  asm volatile("cp.async.wait_group 0;" ::: "memory")
#define CP_WAIT1()  asm volatile("cp.async.wait_group 1;" ::: "memory")

__device__ __forceinline__ uint32_t cvt2h(float x, float y) {
    __half2 h = __floats2half2_rn(x, y);
    return *(uint32_t*)&h;
}

// 64B-row swizzle (gemm): 4 chunks of 16B; chunk ^= (row>>1)&3
__device__ __forceinline__ uint32_t swz(int row, int chunk) {
    return (uint32_t)(row * 64 + ((chunk ^ ((row >> 1) & 3)) << 4));
}
// 128B-row swizzle (attention): 8 chunks of 16B; chunk ^= row&7
__device__ __forceinline__ uint32_t swz128(int row, int chunk) {
    return (uint32_t)(row * 128 + ((chunk ^ (row & 7)) << 4));
}

// ===========================================================================
// Convert kernel: x + 4 weight matrices -> fp16, one launch
// ===========================================================================
__global__ void __launch_bounds__(256) cvt_all(
    const float* __restrict__ x,
    const float* __restrict__ wq, const float* __restrict__ wk,
    const float* __restrict__ wv, const float* __restrict__ wo)
{
    size_t i = ((size_t)blockIdx.x * 256 + threadIdx.x) * 8;
    const float* src;
    __half* dst;
    size_t off;
    if (i < (size_t)XN) {
        src = x; dst = g_xhi; off = i;
    } else {
        size_t j = i - XN;
        int wsel = (int)(j >> 20);            // WN = 2^20
        off = j & (WN - 1);
        const float* ws[4] = {wq, wk, wv, wo};
        src = ws[wsel]; dst = g_whi[wsel];
    }
    float4 v0 = *(const float4*)(src + off);
    float4 v1 = *(const float4*)(src + off + 4);
    uint4 out;
    out.x = cvt2h(v0.x, v0.y); out.y = cvt2h(v0.z, v0.w);
    out.z = cvt2h(v1.x, v1.y); out.w = cvt2h(v1.z, v1.w);
    *(uint4*)(dst + off) = out;
}

// ===========================================================================
// GEMM core: CTA 64(M) x 128(N), 128 threads, warp grid 2m x 2n (32x64 tile),
// K-chunk 32, 2-stage cp.async, 24KB smem, 4 CTAs/SM. 1-pass fp16.
// ===========================================================================
#define STG_SZ     12288u
#define ST_AHI(s)  ((uint32_t)(s) * STG_SZ + 0u)
#define ST_BHI(s)  ((uint32_t)(s) * STG_SZ + 4096u)
#define GEMM_SMEM  24576

struct GemmCore {
    uint32_t sb;
    int tid, lane, wm, wn;
    int m0, n0;
    const __half *Ahi, *Whi;
    float acc[2][8][4];

    __device__ __forceinline__ void issue_stage(int st, int kt) {
        const int r = tid >> 1;               // 0..63
        const int cc = (tid & 1) << 1;        // 0 or 2
        const uint32_t s0 = swz(r, cc), s1 = swz(r, cc + 1);
        const uint32_t s2 = swz(r + 64, cc), s3 = swz(r + 64, cc + 1);
        size_t ka = (size_t)kt * 32 + cc * 8;
        const __half* p = Ahi + (size_t)(m0 + r) * DM_ + ka;
        CP_ASYNC16(sb + ST_AHI(st) + s0, p);
        CP_ASYNC16(sb + ST_AHI(st) + s1, p + 8);
        p = Whi + (size_t)(n0 + r) * DM_ + ka;
        CP_ASYNC16(sb + ST_BHI(st) + s0, p);
        CP_ASYNC16(sb + ST_BHI(st) + s1, p + 8);
        p = Whi + (size_t)(n0 + r + 64) * DM_ + ka;
        CP_ASYNC16(sb + ST_BHI(st) + s2, p);
        CP_ASYNC16(sb + ST_BHI(st) + s3, p + 8);
    }

    __device__ __forceinline__ void run() {
#pragma unroll
        for (int i = 0; i < 2; i++)
#pragma unroll
            for (int j = 0; j < 8; j++)
#pragma unroll
                for (int r = 0; r < 4; r++) acc[i][j][r] = 0.f;

        issue_stage(0, 0);
        CP_COMMIT();

        const int a_row_in = lane & 15;
        const int a_kh     = lane >> 4;
        const int b_col_in = (lane & 7) + ((lane >> 4) << 3);
        const int b_kh     = (lane >> 3) & 1;

        for (int kt = 0; kt < 32; kt++) {
            const int cur = kt & 1;
            if (kt < 31) {
                issue_stage(cur ^ 1, kt + 1);
                CP_COMMIT();
                CP_WAIT1();
            } else {
                CP_WAIT0();
            }
            __syncthreads();

            const uint32_t ahiB = sb + ST_AHI(cur);
            const uint32_t bhiB = sb + ST_BHI(cur);

#pragma unroll
            for (int ks = 0; ks < 2; ks++) {
                uint32_t ahi[2][4];
#pragma unroll
                for (int mf = 0; mf < 2; mf++) {
                    int row = wm * 32 + mf * 16 + a_row_in;
                    int ch  = ks * 2 + a_kh;
                    uint32_t so = swz(row, ch);
                    ldsm_x4(ahi[mf][0], ahi[mf][1], ahi[mf][2], ahi[mf][3], ahiB + so);
                }
                uint32_t bhi[8][2];
#pragma unroll
                for (int bi = 0; bi < 4; bi++) {
                    int col = wn * 64 + bi * 16 + b_col_in;
                    int ch  = ks * 2 + b_kh;
                    uint32_t so = swz(col, ch);
                    uint32_t r0, r1, r2, r3;
                    ldsm_x4(r0, r1, r2, r3, bhiB + so);
                    bhi[bi * 2][0] = r0; bhi[bi * 2][1] = r1;
                    bhi[bi * 2 + 1][0] = r2; bhi[bi * 2 + 1][1] = r3;
                }
#pragma unroll
                for (int mf = 0; mf < 2; mf++)
#pragma unroll
                    for (int nf = 0; nf < 8; nf++)
                        mma_fp16(acc[mf][nf], ahi[mf], bhi[nf]);
            }
            __syncthreads();
        }
    }
};

// QKV GEMM (1-pass): grid (8, 200, 3). z=0: Q, z=1: K, z=2: V. fp16 out.
__global__ void __launch_bounds__(128, 4) gemm_qkv(
    const float* __restrict__ bq, const float* __restrict__ bk,
    const float* __restrict__ bv)
{
    extern __shared__ char smem[];
    GemmCore gc;
    gc.sb   = smem_to_u32(smem);
    gc.tid  = threadIdx.x;
    gc.lane = gc.tid & 31;
    gc.wm   = (gc.tid >> 5) >> 1;
    gc.wn   = (gc.tid >> 5) & 1;
    gc.m0   = blockIdx.y * 64;
    gc.n0   = blockIdx.x * 128;
    const int z = blockIdx.z;
    gc.Ahi = g_xhi;  gc.Whi = g_whi[z];
    const float* bias = (z == 0) ? bq : (z == 1) ? bk : bv;
    __half* Chi = (z == 0) ? g_Qhi : (z == 1) ? g_Khi : g_Vhi;

    gc.run();

    const int g  = gc.lane >> 2;
    const int c2 = (gc.lane & 3) * 2;
#pragma unroll
    for (int nf = 0; nf < 8; nf++) {
        const int n = gc.n0 + gc.wn * 64 + nf * 8 + c2;
        const float b0 = bias[n], b1 = bias[n + 1];
        const int hh = n >> 6;
        const int dk = n & 63;
#pragma unroll
        for (int mf = 0; mf < 2; mf++) {
            const int m = gc.m0 + gc.wm * 32 + mf * 16 + g;
            float v00 = gc.acc[mf][nf][0] + b0, v01 = gc.acc[mf][nf][1] + b1;
            float v10 = gc.acc[mf][nf][2] + b0, v11 = gc.acc[mf][nf][3] + b1;
            int bb = m / S_;
            int ss = m - bb * S_;
            size_t off0 = (((size_t)bb * H_ + hh) * S_ + ss) * DK_ + dk;
            int m2 = m + 8;
            int bb2 = m2 / S_;
            int ss2 = m2 - bb2 * S_;
            size_t off1 = (((size_t)bb2 * H_ + hh) * S_ + ss2) * DK_ + dk;
            *(uint32_t*)(Chi + off0) = cvt2h(v00, v01);
            *(uint32_t*)(Chi + off1) = cvt2h(v10, v11);
        }
    }
}

// Output GEMM (1-pass): ctx (fp16) @ wo^T + bo -> fp32 row-major
__global__ void __launch_bounds__(128, 4) gemm_out(
    const float* __restrict__ bias, float* __restrict__ Cf)
{
    extern __shared__ char smem[];
    GemmCore gc;
    gc.sb   = smem_to_u32(smem);
    gc.tid  = threadIdx.x;
    gc.lane = gc.tid & 31;
    gc.wm   = (gc.tid >> 5) >> 1;
    gc.wn   = (gc.tid >> 5) & 1;
    gc.m0   = blockIdx.y * 64;
    gc.n0   = blockIdx.x * 128;
    gc.Ahi = g_ctxhi;  gc.Whi = g_whi[3];

    gc.run();

    const int g  = gc.lane >> 2;
    const int c2 = (gc.lane & 3) * 2;
#pragma unroll
    for (int nf = 0; nf < 8; nf++) {
        const int n = gc.n0 + gc.wn * 64 + nf * 8 + c2;
        const float b0 = bias[n], b1 = bias[n + 1];
#pragma unroll
        for (int mf = 0; mf < 2; mf++) {
            const int m = gc.m0 + gc.wm * 32 + mf * 16 + g;
            *(float2*)(Cf + (size_t)m * DM_ + n) =
                make_float2(gc.acc[mf][nf][0] + b0, gc.acc[mf][nf][1] + b1);
            *(float2*)(Cf + (size_t)(m + 8) * DM_ + n) =
                make_float2(gc.acc[mf][nf][2] + b0, gc.acc[mf][nf][3] + b1);
        }
    }
}

// ===========================================================================
// Fused attention: CTA = (64 q-rows, bh). 128 threads, 3 CTAs/SM.
// 1-pass fp16 throughout; __expf softmax.
// ===========================================================================
#define FK_HI   0u
#define FV_HI   26624u
#define FA_SMEM 53248

__global__ void __launch_bounds__(128, 3) attn_fused(
    const int* __restrict__ mask, float* __restrict__ attn)
{
    extern __shared__ char smem[];
    const uint32_t sb = smem_to_u32(smem);
    const int tid  = threadIdx.x;
    const int lane = tid & 31;
    const int w    = tid >> 5;
    const int qt   = blockIdx.x;          // 0..3
    const int bh   = blockIdx.y;
    const int b    = bh >> 4;

    const __half* Khi = g_Khi + (size_t)bh * S_ * DK_;
    const __half* Vhi = g_Vhi + (size_t)bh * S_ * DK_;
    const __half* Qhi = g_Qhi + (size_t)bh * S_ * DK_;

    for (int c = tid; c < 1600; c += 128) {
        int r = c >> 3, cc = c & 7;
        uint32_t so = swz128(r, cc);
        size_t go = (size_t)r * DK_ + cc * 8;
        CP_ASYNC16(sb + FK_HI + so, Khi + go);
        CP_ASYNC16(sb + FV_HI + so, Vhi + go);
    }
    CP_COMMIT();
    if (tid < 64) {
        int r = 200 + (tid >> 3), cc = tid & 7;
        uint32_t so = swz128(r, cc);
        STS128(sb + FK_HI + so, 0u, 0u, 0u, 0u);
        STS128(sb + FV_HI + so, 0u, 0u, 0u, 0u);
    }
    CP_WAIT0();
    __syncthreads();

    float acc[25][4];
#pragma unroll
    for (int f = 0; f < 25; f++)
#pragma unroll
        for (int r = 0; r < 4; r++) acc[f][r] = 0.f;

    const int g  = lane >> 2;
    const int c2 = (lane & 3) * 2;
    const int b_col_in = (lane & 7) + ((lane >> 4) << 3);
    const int b_kh     = (lane >> 3) & 1;

    const int qr0 = qt * 64 + w * 16 + g;
    const int qr1 = qr0 + 8;
    const size_t qo0 = (size_t)min(qr0, S_ - 1) * DK_;
    const size_t qo1 = (size_t)min(qr1, S_ - 1) * DK_;

    for (int kb = 0; kb < 4; kb++) {
        const int col = kb * 16 + c2;
        uint32_t ahi[4];
        ahi[0] = *(const uint32_t*)(Qhi + qo0 + col);
        ahi[1] = *(const uint32_t*)(Qhi + qo1 + col);
        ahi[2] = *(const uint32_t*)(Qhi + qo0 + col + 8);
        ahi[3] = *(const uint32_t*)(Qhi + qo1 + col + 8);
#pragma unroll
        for (int nb = 0; nb < 13; nb++) {
            int row = nb * 16 + b_col_in;
            int ch  = kb * 2 + b_kh;
            uint32_t so = swz128(row, ch);
            uint32_t h0, h1, h2, h3;
            ldsm_x4(h0, h1, h2, h3, sb + FK_HI + so);
            uint32_t bh0[2] = {h0, h1};
            mma_fp16(acc[nb * 2], ahi, bh0);
            if (nb < 12) {
                uint32_t bh1[2] = {h2, h3};
                mma_fp16(acc[nb * 2 + 1], ahi, bh1);
            }
        }
    }

    const int gi0 = qr0;
    const int gi1 = qr1;
    const bool v0ok = (gi0 < S_);
    const bool v1ok = (gi1 < S_);
    const int* mrow0 = mask + (size_t)b * S_ * S_ + (size_t)gi0 * S_;
    const int* mrow1 = mask + (size_t)b * S_ * S_ + (size_t)gi1 * S_;
    const float BC = -0.1f / 200.0f;

    float mx0 = -1e30f, mx1 = -1e30f;
#pragma unroll
    for (int f = 0; f < 25; f++) {
        int gj = f * 8 + c2;
        int2 m0v = v0ok ? *(const int2*)(mrow0 + gj) : make_int2(1, 1);
        int2 m1v = v1ok ? *(const int2*)(mrow1 + gj) : make_int2(1, 1);
        float t00 = BC * fabsf((float)(gi0 - gj));
        float t01 = BC * fabsf((float)(gi0 - gj - 1));
        float t10 = BC * fabsf((float)(gi1 - gj));
        float t11 = BC * fabsf((float)(gi1 - gj - 1));
        acc[f][0] = (m0v.x == 0) ? -1e9f : fmaf(acc[f][0], 0.125f, t00);
        acc[f][1] = (m0v.y == 0) ? -1e9f : fmaf(acc[f][1], 0.125f, t01);
        acc[f][2] = (m1v.x == 0) ? -1e9f : fmaf(acc[f][2], 0.125f, t10);
        acc[f][3] = (m1v.y == 0) ? -1e9f : fmaf(acc[f][3], 0.125f, t11);
        mx0 = fmaxf(mx0, fmaxf(acc[f][0], acc[f][1]));
        mx1 = fmaxf(mx1, fmaxf(acc[f][2], acc[f][3]));
    }
    mx0 = fmaxf(mx0, __shfl_xor_sync(0xffffffffu, mx0, 1));
    mx0 = fmaxf(mx0, __shfl_xor_sync(0xffffffffu, mx0, 2));
    mx1 = fmaxf(mx1, __shfl_xor_sync(0xffffffffu, mx1, 1));
    mx1 = fmaxf(mx1, __shfl_xor_sync(0xffffffffu, mx1, 2));

    float s0 = 0.f, s1 = 0.f;
#pragma unroll
    for (int f = 0; f < 25; f++) {
        acc[f][0] = __expf(acc[f][0] - mx0);
        acc[f][1] = __expf(acc[f][1] - mx0);
        acc[f][2] = __expf(acc[f][2] - mx1);
        acc[f][3] = __expf(acc[f][3] - mx1);
        s0 += acc[f][0] + acc[f][1];
        s1 += acc[f][2] + acc[f][3];
    }
    s0 += __shfl_xor_sync(0xffffffffu, s0, 1);
    s0 += __shfl_xor_sync(0xffffffffu, s0, 2);
    s1 += __shfl_xor_sync(0xffffffffu, s1, 1);
    s1 += __shfl_xor_sync(0xffffffffu, s1, 2);
    const float i0 = 1.f / s0;
    const float i1 = 1.f / s1;

    float* arow0 = attn + (size_t)bh * S_ * S_ + (size_t)gi0 * S_;
    float* arow1 = attn + (size_t)bh * S_ * S_ + (size_t)gi1 * S_;
#pragma unroll
    for (int f = 0; f < 25; f++) {
        int gj = f * 8 + c2;
        acc[f][0] *= i0; acc[f][1] *= i0;
        acc[f][2] *= i1; acc[f][3] *= i1;
        if (v0ok) *(float2*)(arow0 + gj) = make_float2(acc[f][0], acc[f][1]);
        if (v1ok) *(float2*)(arow1 + gj) = make_float2(acc[f][2], acc[f][3]);
    }

    // ---- ctx = attn @ V (1-pass) ----
    float cacc[8][4];
#pragma unroll
    for (int nf = 0; nf < 8; nf++)
#pragma unroll
        for (int r = 0; r < 4; r++) cacc[nf][r] = 0.f;

#pragma unroll
    for (int kf = 0; kf < 13; kf++) {
        uint32_t ahi[4];
        ahi[0] = cvt2h(acc[2 * kf][0], acc[2 * kf][1]);
        ahi[1] = cvt2h(acc[2 * kf][2], acc[2 * kf][3]);
        if (kf < 12) {
            ahi[2] = cvt2h(acc[2 * kf + 1][0], acc[2 * kf + 1][1]);
            ahi[3] = cvt2h(acc[2 * kf + 1][2], acc[2 * kf + 1][3]);
        } else {
            ahi[2] = ahi[3] = 0u;
        }
#pragma unroll
        for (int nb = 0; nb < 4; nb++) {
            int row = kf * 16 + (lane & 15);
            int ch  = nb * 2 + (lane >> 4);
            uint32_t so = swz128(row, ch);
            uint32_t h0, h1, h2, h3;
            ldsm_x4_t(h0, h1, h2, h3, sb + FV_HI + so);
            uint32_t bh0[2] = {h0, h1};
            uint32_t bh1[2] = {h2, h3};
            mma_fp16(cacc[nb * 2], ahi, bh0);
            mma_fp16(cacc[nb * 2 + 1], ahi, bh1);
        }
    }

    const int h = bh & 15;
    __half* chi0 = g_ctxhi + ((size_t)b * S_ + gi0) * DM_ + h * DK_;
    __half* chi1 = g_ctxhi + ((size_t)b * S_ + gi1) * DM_ + h * DK_;
#pragma unroll
    for (int nf = 0; nf < 8; nf++) {
        int n = nf * 8 + c2;
        if (v0ok) *(uint32_t*)(chi0 + n) = cvt2h(cacc[nf][0], cacc[nf][1]);
        if (v1ok) *(uint32_t*)(chi1 + n) = cvt2h(cacc[nf][2], cacc[nf][3]);
    }
}

// ---------------------------------------------------------------------------
extern "C" void kernel_launch(void* const* d_in, const int* in_sizes, int n_in,
                              void* d_out, int out_size)
{
    const float* x    = (const float*)d_in[0];
    const int*   mask = (const int*)  d_in[1];
    const float* wq   = (const float*)d_in[2];
    const float* bq   = (const float*)d_in[3];
    const float* wk   = (const float*)d_in[4];
    const float* bk   = (const float*)d_in[5];
    const float* wv   = (const float*)d_in[6];
    const float* bv   = (const float*)d_in[7];
    const float* wo   = (const float*)d_in[8];
    const float* bo   = (const float*)d_in[9];

    void *pAttnFb, *pOutFb;
    cudaGetSymbolAddress(&pAttnFb, g_attn_fb);
    cudaGetSymbolAddress(&pOutFb, g_out_fb);

    float* outp;
    float* attnp;
    size_t osz = (size_t)out_size;
    if (osz >= OUT_N + ATTN_N) {
        outp  = (float*)d_out;
        attnp = (float*)d_out + OUT_N;
    } else if (osz == ATTN_N) {
        attnp = (float*)d_out;
        outp  = (float*)pOutFb;
    } else {
        outp  = (float*)d_out;
        attnp = (float*)pAttnFb;
    }

    cudaFuncSetAttribute(gemm_qkv, cudaFuncAttributeMaxDynamicSharedMemorySize, GEMM_SMEM);
    cudaFuncSetAttribute(gemm_out, cudaFuncAttributeMaxDynamicSharedMemorySize, GEMM_SMEM);
    cudaFuncSetAttribute(attn_fused, cudaFuncAttributeMaxDynamicSharedMemorySize, FA_SMEM);

    const size_t total = (size_t)XN + 4 * (size_t)WN;   // 17301504
    cvt_all<<<(unsigned)(total / 2048), 256>>>(x, wq, wk, wv, wo);

    dim3 gQKV(DM_ / 128, MROWS / 64, 3);   // (8, 200, 3)
    gemm_qkv<<<gQKV, 128, GEMM_SMEM>>>(bq, bk, bv);

    dim3 gFA(4, BH_);
    attn_fused<<<gFA, 128, FA_SMEM>>>(mask, attnp);

    dim3 gOut(DM_ / 128, MROWS / 64);      // (8, 200)
    gemm_out<<<gOut, 128, GEMM_SMEM>>>(bo, outp);
}

// round 16
// speedup vs baseline: 2.3691x; 1.0459x over previous
#include <cuda_runtime.h>
#include <cuda_fp16.h>
#include <math.h>
#include <stdint.h>

// Problem constants
#define B_    64
#define S_    200
#define H_    16
#define DK_   64
#define DM_   1024
#define MROWS (B_ * S_)          // 12800
#define BH_   (B_ * H_)          // 1024
#define OUT_N  ((size_t)MROWS * DM_)       // 13107200
#define ATTN_N ((size_t)BH_ * S_ * S_)     // 40960000
#define XN    (MROWS * DM_)                // 13107200
#define WN    (DM_ * DM_)                  // 1048576

// Scratch (allocation-free rule: __device__ globals)
__device__ __half g_xhi[XN];
__device__ __half g_whi[4][WN];
__device__ __half g_Qhi[BH_ * S_ * DK_];
__device__ __half g_Khi[BH_ * S_ * DK_];
__device__ __half g_Vhi[BH_ * S_ * DK_];
__device__ __half g_ctxhi[MROWS * DM_];
__device__ float g_attn_fb[BH_ * S_ * S_];
__device__ float g_out_fb[MROWS * DM_];

// ===========================================================================
// Helpers
// ===========================================================================
__device__ __forceinline__ uint32_t smem_to_u32(const void* p) {
    uint32_t a;
    asm("{ .reg .u64 t; cvta.to.shared.u64 t, %1; cvt.u32.u64 %0, t; }"
        : "=r"(a) : "l"(p));
    return a;
}

__device__ __forceinline__ void ldsm_x4(uint32_t& r0, uint32_t& r1,
                                        uint32_t& r2, uint32_t& r3, uint32_t addr) {
    asm volatile("ldmatrix.sync.aligned.m8n8.x4.shared.b16 {%0,%1,%2,%3}, [%4];"
                 : "=r"(r0), "=r"(r1), "=r"(r2), "=r"(r3) : "r"(addr));
}
__device__ __forceinline__ void ldsm_x4_t(uint32_t& r0, uint32_t& r1,
                                          uint32_t& r2, uint32_t& r3, uint32_t addr) {
    asm volatile("ldmatrix.sync.aligned.m8n8.x4.trans.shared.b16 {%0,%1,%2,%3}, [%4];"
                 : "=r"(r0), "=r"(r1), "=r"(r2), "=r"(r3) : "r"(addr));
}

__device__ __forceinline__ void mma_fp16(float* d, const uint32_t* a, const uint32_t* b) {
    asm volatile(
        "mma.sync.aligned.m16n8k16.row.col.f32.f16.f16.f32 "
        "{%0,%1,%2,%3}, {%4,%5,%6,%7}, {%8,%9}, {%0,%1,%2,%3};"
        : "+f"(d[0]), "+f"(d[1]), "+f"(d[2]), "+f"(d[3])
        : "r"(a[0]), "r"(a[1]), "r"(a[2]), "r"(a[3]), "r"(b[0]), "r"(b[1]));
}

#define STS128(addr, r0, r1, r2, r3) \
    asm volatile("st.shared.v4.b32 [%0], {%1,%2,%3,%4};" \
        :: "r"(addr), "r"(r0), "r"(r1), "r"(r2), "r"(r3) : "memory")

#define CP_ASYNC16(sm, gp) \
    asm volatile("{ .reg .u64 g; cvta.to.global.u64 g, %1; " \
                 "cp.async.cg.shared.global [%0], [g], 16; }" \
                 :: "r"(sm), "l"(gp) : "memory")
#define CP_COMMIT() asm volatile("cp.async.commit_group;" ::: "memory")
#define CP_WAIT0()  asm volatile("cp.async.wait_group 0;" ::: "memory")
#define CP_WAIT1()  asm volatile("cp.async.wait_group 1;" ::: "memory")

__device__ __forceinline__ uint32_t cvt2h(float x, float y) {
    __half2 h = __floats2half2_rn(x, y);
    return *(uint32_t*)&h;
}

// 64B-row swizzle (gemm): 4 chunks of 16B; chunk ^= (row>>1)&3
__device__ __forceinline__ uint32_t swz(int row, int chunk) {
    return (uint32_t)(row * 64 + ((chunk ^ ((row >> 1) & 3)) << 4));
}
// 128B-row swizzle (attention): 8 chunks of 16B; chunk ^= row&7
__device__ __forceinline__ uint32_t swz128(int row, int chunk) {
    return (uint32_t)(row * 128 + ((chunk ^ (row & 7)) << 4));
}

// ===========================================================================
// Convert kernel: x + 4 weight matrices -> fp16, one launch
// ===========================================================================
__global__ void __launch_bounds__(256) cvt_all(
    const float* __restrict__ x,
    const float* __restrict__ wq, const float* __restrict__ wk,
    const float* __restrict__ wv, const float* __restrict__ wo)
{
    size_t i = ((size_t)blockIdx.x * 256 + threadIdx.x) * 8;
    const float* src;
    __half* dst;
    size_t off;
    if (i < (size_t)XN) {
        src = x; dst = g_xhi; off = i;
    } else {
        size_t j = i - XN;
        int wsel = (int)(j >> 20);            // WN = 2^20
        off = j & (WN - 1);
        const float* ws[4] = {wq, wk, wv, wo};
        src = ws[wsel]; dst = g_whi[wsel];
    }
    float4 v0 = *(const float4*)(src + off);
    float4 v1 = *(const float4*)(src + off + 4);
    uint4 out;
    out.x = cvt2h(v0.x, v0.y); out.y = cvt2h(v0.z, v0.w);
    out.z = cvt2h(v1.x, v1.y); out.w = cvt2h(v1.z, v1.w);
    *(uint4*)(dst + off) = out;
}

// ===========================================================================
// GEMM core: CTA 64(M) x 128(N), 128 threads, warp grid 2m x 2n (32x64 tile),
// K-chunk 32, 3-stage cp.async ring w/ single barrier per iter, 36KB smem,
// 4 CTAs/SM. 1-pass fp16: acc = A@W^T.
// ===========================================================================
#define STG_SZ     12288u
#define ST_AHI(s)  ((uint32_t)(s) * STG_SZ + 0u)
#define ST_BHI(s)  ((uint32_t)(s) * STG_SZ + 4096u)
#define GEMM_SMEM  36864

struct GemmCore {
    uint32_t sb;
    int tid, lane, wm, wn;
    int m0, n0;
    const __half *Ahi, *Whi;
    float acc[2][8][4];

    __device__ __forceinline__ void issue_stage(int st, int kt) {
        const int r = tid >> 1;               // 0..63
        const int cc = (tid & 1) << 1;        // 0 or 2
        const uint32_t s0 = swz(r, cc), s1 = swz(r, cc + 1);
        const uint32_t s2 = swz(r + 64, cc), s3 = swz(r + 64, cc + 1);
        size_t ka = (size_t)kt * 32 + cc * 8;
        const __half* p = Ahi + (size_t)(m0 + r) * DM_ + ka;
        CP_ASYNC16(sb + ST_AHI(st) + s0, p);
        CP_ASYNC16(sb + ST_AHI(st) + s1, p + 8);
        p = Whi + (size_t)(n0 + r) * DM_ + ka;
        CP_ASYNC16(sb + ST_BHI(st) + s0, p);
        CP_ASYNC16(sb + ST_BHI(st) + s1, p + 8);
        p = Whi + (size_t)(n0 + r + 64) * DM_ + ka;
        CP_ASYNC16(sb + ST_BHI(st) + s2, p);
        CP_ASYNC16(sb + ST_BHI(st) + s3, p + 8);
    }

    __device__ __forceinline__ void run() {
#pragma unroll
        for (int i = 0; i < 2; i++)
#pragma unroll
            for (int j = 0; j < 8; j++)
#pragma unroll
                for (int r = 0; r < 4; r++) acc[i][j][r] = 0.f;

        issue_stage(0, 0);
        CP_COMMIT();
        issue_stage(1, 1);
        CP_COMMIT();

        const int a_row_in = lane & 15;
        const int a_kh     = lane >> 4;
        const int b_col_in = (lane & 7) + ((lane >> 4) << 3);
        const int b_kh     = (lane >> 3) & 1;

        int cur = 0;   // stage index = kt % 3, tracked incrementally
        for (int kt = 0; kt < 32; kt++) {
            if (kt <= 30) CP_WAIT1();   // stage kt landed (kt+1 may be in flight)
            else          CP_WAIT0();
            __syncthreads();
            // refill stage (kt+2)%3 = (kt-1)%3: consumed at kt-1, all warps
            // passed the barrier above after computing kt-1 -> safe.
            if (kt < 30) {
                int nxt = cur + 2; if (nxt >= 3) nxt -= 3;
                issue_stage(nxt, kt + 2);
                CP_COMMIT();
            }

            const uint32_t ahiB = sb + ST_AHI(cur);
            const uint32_t bhiB = sb + ST_BHI(cur);

#pragma unroll
            for (int ks = 0; ks < 2; ks++) {
                uint32_t ahi[2][4];
#pragma unroll
                for (int mf = 0; mf < 2; mf++) {
                    int row = wm * 32 + mf * 16 + a_row_in;
                    int ch  = ks * 2 + a_kh;
                    uint32_t so = swz(row, ch);
                    ldsm_x4(ahi[mf][0], ahi[mf][1], ahi[mf][2], ahi[mf][3], ahiB + so);
                }
                uint32_t bhi[8][2];
#pragma unroll
                for (int bi = 0; bi < 4; bi++) {
                    int col = wn * 64 + bi * 16 + b_col_in;
                    int ch  = ks * 2 + b_kh;
                    uint32_t so = swz(col, ch);
                    uint32_t r0, r1, r2, r3;
                    ldsm_x4(r0, r1, r2, r3, bhiB + so);
                    bhi[bi * 2][0] = r0; bhi[bi * 2][1] = r1;
                    bhi[bi * 2 + 1][0] = r2; bhi[bi * 2 + 1][1] = r3;
                }
#pragma unroll
                for (int mf = 0; mf < 2; mf++)
#pragma unroll
                    for (int nf = 0; nf < 8; nf++)
                        mma_fp16(acc[mf][nf], ahi[mf], bhi[nf]);
            }
            cur++; if (cur >= 3) cur = 0;
        }
    }
};

// QKV GEMM (1-pass): grid (8, 200, 3). z=0: Q, z=1: K, z=2: V. fp16 out.
__global__ void __launch_bounds__(128, 4) gemm_qkv(
    const float* __restrict__ bq, const float* __restrict__ bk,
    const float* __restrict__ bv)
{
    extern __shared__ char smem[];
    GemmCore gc;
    gc.sb   = smem_to_u32(smem);
    gc.tid  = threadIdx.x;
    gc.lane = gc.tid & 31;
    gc.wm   = (gc.tid >> 5) >> 1;
    gc.wn   = (gc.tid >> 5) & 1;
    gc.m0   = blockIdx.y * 64;
    gc.n0   = blockIdx.x * 128;
    const int z = blockIdx.z;
    gc.Ahi = g_xhi;  gc.Whi = g_whi[z];
    const float* bias = (z == 0) ? bq : (z == 1) ? bk : bv;
    __half* Chi = (z == 0) ? g_Qhi : (z == 1) ? g_Khi : g_Vhi;

    gc.run();

    const int g  = gc.lane >> 2;
    const int c2 = (gc.lane & 3) * 2;
#pragma unroll
    for (int nf = 0; nf < 8; nf++) {
        const int n = gc.n0 + gc.wn * 64 + nf * 8 + c2;
        const float b0 = bias[n], b1 = bias[n + 1];
        const int hh = n >> 6;
        const int dk = n & 63;
#pragma unroll
        for (int mf = 0; mf < 2; mf++) {
            const int m = gc.m0 + gc.wm * 32 + mf * 16 + g;
            float v00 = gc.acc[mf][nf][0] + b0, v01 = gc.acc[mf][nf][1] + b1;
            float v10 = gc.acc[mf][nf][2] + b0, v11 = gc.acc[mf][nf][3] + b1;
            int bb = m / S_;
            int ss = m - bb * S_;
            size_t off0 = (((size_t)bb * H_ + hh) * S_ + ss) * DK_ + dk;
            int m2 = m + 8;
            int bb2 = m2 / S_;
            int ss2 = m2 - bb2 * S_;
            size_t off1 = (((size_t)bb2 * H_ + hh) * S_ + ss2) * DK_ + dk;
            *(uint32_t*)(Chi + off0) = cvt2h(v00, v01);
            *(uint32_t*)(Chi + off1) = cvt2h(v10, v11);
        }
    }
}

// Output GEMM (1-pass): ctx (fp16) @ wo^T + bo -> fp32 row-major
__global__ void __launch_bounds__(128, 4) gemm_out(
    const float* __restrict__ bias, float* __restrict__ Cf)
{
    extern __shared__ char smem[];
    GemmCore gc;
    gc.sb   = smem_to_u32(smem);
    gc.tid  = threadIdx.x;
    gc.lane = gc.tid & 31;
    gc.wm   = (gc.tid >> 5) >> 1;
    gc.wn   = (gc.tid >> 5) & 1;
    gc.m0   = blockIdx.y * 64;
    gc.n0   = blockIdx.x * 128;
    gc.Ahi = g_ctxhi;  gc.Whi = g_whi[3];

    gc.run();

    const int g  = gc.lane >> 2;
    const int c2 = (gc.lane & 3) * 2;
#pragma unroll
    for (int nf = 0; nf < 8; nf++) {
        const int n = gc.n0 + gc.wn * 64 + nf * 8 + c2;
        const float b0 = bias[n], b1 = bias[n + 1];
#pragma unroll
        for (int mf = 0; mf < 2; mf++) {
            const int m = gc.m0 + gc.wm * 32 + mf * 16 + g;
            *(float2*)(Cf + (size_t)m * DM_ + n) =
                make_float2(gc.acc[mf][nf][0] + b0, gc.acc[mf][nf][1] + b1);
            *(float2*)(Cf + (size_t)(m + 8) * DM_ + n) =
                make_float2(gc.acc[mf][nf][2] + b0, gc.acc[mf][nf][3] + b1);
        }
    }
}

// ===========================================================================
// Fused attention: CTA = (64 q-rows, bh). 128 threads, 3 CTAs/SM.
// 1-pass fp16 throughout; __expf softmax.
// ===========================================================================
#define FK_HI   0u
#define FV_HI   26624u
#define FA_SMEM 53248

__global__ void __launch_bounds__(128, 3) attn_fused(
    const int* __restrict__ mask, float* __restrict__ attn)
{
    extern __shared__ char smem[];
    const uint32_t sb = smem_to_u32(smem);
    const int tid  = threadIdx.x;
    const int lane = tid & 31;
    const int w    = tid >> 5;
    const int qt   = blockIdx.x;          // 0..3
    const int bh   = blockIdx.y;
    const int b    = bh >> 4;

    const __half* Khi = g_Khi + (size_t)bh * S_ * DK_;
    const __half* Vhi = g_Vhi + (size_t)bh * S_ * DK_;
    const __half* Qhi = g_Qhi + (size_t)bh * S_ * DK_;

    for (int c = tid; c < 1600; c += 128) {
        int r = c >> 3, cc = c & 7;
        uint32_t so = swz128(r, cc);
        size_t go = (size_t)r * DK_ + cc * 8;
        CP_ASYNC16(sb + FK_HI + so, Khi + go);
        CP_ASYNC16(sb + FV_HI + so, Vhi + go);
    }
    CP_COMMIT();
    if (tid < 64) {
        int r = 200 + (tid >> 3), cc = tid & 7;
        uint32_t so = swz128(r, cc);
        STS128(sb + FK_HI + so, 0u, 0u, 0u, 0u);
        STS128(sb + FV_HI + so, 0u, 0u, 0u, 0u);
    }
    CP_WAIT0();
    __syncthreads();

    float acc[25][4];
#pragma unroll
    for (int f = 0; f < 25; f++)
#pragma unroll
        for (int r = 0; r < 4; r++) acc[f][r] = 0.f;

    const int g  = lane >> 2;
    const int c2 = (lane & 3) * 2;
    const int b_col_in = (lane & 7) + ((lane >> 4) << 3);
    const int b_kh     = (lane >> 3) & 1;

    const int qr0 = qt * 64 + w * 16 + g;
    const int qr1 = qr0 + 8;
    const size_t qo0 = (size_t)min(qr0, S_ - 1) * DK_;
    const size_t qo1 = (size_t)min(qr1, S_ - 1) * DK_;

    for (int kb = 0; kb < 4; kb++) {
        const int col = kb * 16 + c2;
        uint32_t ahi[4];
        ahi[0] = *(const uint32_t*)(Qhi + qo0 + col);
        ahi[1] = *(const uint32_t*)(Qhi + qo1 + col);
        ahi[2] = *(const uint32_t*)(Qhi + qo0 + col + 8);
        ahi[3] = *(const uint32_t*)(Qhi + qo1 + col + 8);
#pragma unroll
        for (int nb = 0; nb < 13; nb++) {
            int row = nb * 16 + b_col_in;
            int ch  = kb * 2 + b_kh;
            uint32_t so = swz128(row, ch);
            uint32_t h0, h1, h2, h3;
            ldsm_x4(h0, h1, h2, h3, sb + FK_HI + so);
            uint32_t bh0[2] = {h0, h1};
            mma_fp16(acc[nb * 2], ahi, bh0);
            if (nb < 12) {
                uint32_t bh1[2] = {h2, h3};
                mma_fp16(acc[nb * 2 + 1], ahi, bh1);
            }
        }
    }

    const int gi0 = qr0;
    const int gi1 = qr1;
    const bool v0ok = (gi0 < S_);
    const bool v1ok = (gi1 < S_);
    const int* mrow0 = mask + (size_t)b * S_ * S_ + (size_t)gi0 * S_;
    const int* mrow1 = mask + (size_t)b * S_ * S_ + (size_t)gi1 * S_;
    const float BC = -0.1f / 200.0f;

    float mx0 = -1e30f, mx1 = -1e30f;
#pragma unroll
    for (int f = 0; f < 25; f++) {
        int gj = f * 8 + c2;
        int2 m0v = v0ok ? *(const int2*)(mrow0 + gj) : make_int2(1, 1);
        int2 m1v = v1ok ? *(const int2*)(mrow1 + gj) : make_int2(1, 1);
        float t00 = BC * fabsf((float)(gi0 - gj));
        float t01 = BC * fabsf((float)(gi0 - gj - 1));
        float t10 = BC * fabsf((float)(gi1 - gj));
        float t11 = BC * fabsf((float)(gi1 - gj - 1));
        acc[f][0] = (m0v.x == 0) ? -1e9f : fmaf(acc[f][0], 0.125f, t00);
        acc[f][1] = (m0v.y == 0) ? -1e9f : fmaf(acc[f][1], 0.125f, t01);
        acc[f][2] = (m1v.x == 0) ? -1e9f : fmaf(acc[f][2], 0.125f, t10);
        acc[f][3] = (m1v.y == 0) ? -1e9f : fmaf(acc[f][3], 0.125f, t11);
        mx0 = fmaxf(mx0, fmaxf(acc[f][0], acc[f][1]));
        mx1 = fmaxf(mx1, fmaxf(acc[f][2], acc[f][3]));
    }
    mx0 = fmaxf(mx0, __shfl_xor_sync(0xffffffffu, mx0, 1));
    mx0 = fmaxf(mx0, __shfl_xor_sync(0xffffffffu, mx0, 2));
    mx1 = fmaxf(mx1, __shfl_xor_sync(0xffffffffu, mx1, 1));
    mx1 = fmaxf(mx1, __shfl_xor_sync(0xffffffffu, mx1, 2));

    float s0 = 0.f, s1 = 0.f;
#pragma unroll
    for (int f = 0; f < 25; f++) {
        acc[f][0] = __expf(acc[f][0] - mx0);
        acc[f][1] = __expf(acc[f][1] - mx0);
        acc[f][2] = __expf(acc[f][2] - mx1);
        acc[f][3] = __expf(acc[f][3] - mx1);
        s0 += acc[f][0] + acc[f][1];
        s1 += acc[f][2] + acc[f][3];
    }
    s0 += __shfl_xor_sync(0xffffffffu, s0, 1);
    s0 += __shfl_xor_sync(0xffffffffu, s0, 2);
    s1 += __shfl_xor_sync(0xffffffffu, s1, 1);
    s1 += __shfl_xor_sync(0xffffffffu, s1, 2);
    const float i0 = 1.f / s0;
    const float i1 = 1.f / s1;

    float* arow0 = attn + (size_t)bh * S_ * S_ + (size_t)gi0 * S_;
    float* arow1 = attn + (size_t)bh * S_ * S_ + (size_t)gi1 * S_;
#pragma unroll
    for (int f = 0; f < 25; f++) {
        int gj = f * 8 + c2;
        acc[f][0] *= i0; acc[f][1] *= i0;
        acc[f][2] *= i1; acc[f][3] *= i1;
        if (v0ok) *(float2*)(arow0 + gj) = make_float2(acc[f][0], acc[f][1]);
        if (v1ok) *(float2*)(arow1 + gj) = make_float2(acc[f][2], acc[f][3]);
    }

    // ---- ctx = attn @ V (1-pass) ----
    float cacc[8][4];
#pragma unroll
    for (int nf = 0; nf < 8; nf++)
#pragma unroll
        for (int r = 0; r < 4; r++) cacc[nf][r] = 0.f;

#pragma unroll
    for (int kf = 0; kf < 13; kf++) {
        uint32_t ahi[4];
        ahi[0] = cvt2h(acc[2 * kf][0], acc[2 * kf][1]);
        ahi[1] = cvt2h(acc[2 * kf][2], acc[2 * kf][3]);
        if (kf < 12) {
            ahi[2] = cvt2h(acc[2 * kf + 1][0], acc[2 * kf + 1][1]);
            ahi[3] = cvt2h(acc[2 * kf + 1][2], acc[2 * kf + 1][3]);
        } else {
            ahi[2] = ahi[3] = 0u;
        }
#pragma unroll
        for (int nb = 0; nb < 4; nb++) {
            int row = kf * 16 + (lane & 15);
            int ch  = nb * 2 + (lane >> 4);
            uint32_t so = swz128(row, ch);
            uint32_t h0, h1, h2, h3;
            ldsm_x4_t(h0, h1, h2, h3, sb + FV_HI + so);
            uint32_t bh0[2] = {h0, h1};
            uint32_t bh1[2] = {h2, h3};
            mma_fp16(cacc[nb * 2], ahi, bh0);
            mma_fp16(cacc[nb * 2 + 1], ahi, bh1);
        }
    }

    const int h = bh & 15;
    __half* chi0 = g_ctxhi + ((size_t)b * S_ + gi0) * DM_ + h * DK_;
    __half* chi1 = g_ctxhi + ((size_t)b * S_ + gi1) * DM_ + h * DK_;
#pragma unroll
    for (int nf = 0; nf < 8; nf++) {
        int n = nf * 8 + c2;
        if (v0ok) *(uint32_t*)(chi0 + n) = cvt2h(cacc[nf][0], cacc[nf][1]);
        if (v1ok) *(uint32_t*)(chi1 + n) = cvt2h(cacc[nf][2], cacc[nf][3]);
    }
}

// ---------------------------------------------------------------------------
extern "C" void kernel_launch(void* const* d_in, const int* in_sizes, int n_in,
                              void* d_out, int out_size)
{
    const float* x    = (const float*)d_in[0];
    const int*   mask = (const int*)  d_in[1];
    const float* wq   = (const float*)d_in[2];
    const float* bq   = (const float*)d_in[3];
    const float* wk   = (const float*)d_in[4];
    const float* bk   = (const float*)d_in[5];
    const float* wv   = (const float*)d_in[6];
    const float* bv   = (const float*)d_in[7];
    const float* wo   = (const float*)d_in[8];
    const float* bo   = (const float*)d_in[9];

    void *pAttnFb, *pOutFb;
    cudaGetSymbolAddress(&pAttnFb, g_attn_fb);
    cudaGetSymbolAddress(&pOutFb, g_out_fb);

    float* outp;
    float* attnp;
    size_t osz = (size_t)out_size;
    if (osz >= OUT_N + ATTN_N) {
        outp  = (float*)d_out;
        attnp = (float*)d_out + OUT_N;
    } else if (osz == ATTN_N) {
        attnp = (float*)d_out;
        outp  = (float*)pOutFb;
    } else {
        outp  = (float*)d_out;
        attnp = (float*)pAttnFb;
    }

    cudaFuncSetAttribute(gemm_qkv, cudaFuncAttributeMaxDynamicSharedMemorySize, GEMM_SMEM);
    cudaFuncSetAttribute(gemm_out, cudaFuncAttributeMaxDynamicSharedMemorySize, GEMM_SMEM);
    cudaFuncSetAttribute(attn_fused, cudaFuncAttributeMaxDynamicSharedMemorySize, FA_SMEM);

    const size_t total = (size_t)XN + 4 * (size_t)WN;   // 17301504
    cvt_all<<<(unsigned)(total / 2048), 256>>>(x, wq, wk, wv, wo);

    dim3 gQKV(DM_ / 128, MROWS / 64, 3);   // (8, 200, 3)
    gemm_qkv<<<gQKV, 128, GEMM_SMEM>>>(bq, bk, bv);

    dim3 gFA(4, BH_);
    attn_fused<<<gFA, 128, FA_SMEM>>>(mask, attnp);

    dim3 gOut(DM_ / 128, MROWS / 64);      // (8, 200)
    gemm_out<<<gOut, 128, GEMM_SMEM>>>(bo, outp);
}